// round 1
// baseline (speedup 1.0000x reference)
#include <cuda_runtime.h>
#include <math_constants.h>

#define BB 2
#define SS 2048
#define DDIM 1024
#define HH 16
#define HDIM 64
#define MM (BB*SS)          // 4096 rows
#define QKV_LD 3072         // 3*D

// Scratch (device globals: allowed; runtime allocs are not)
__device__ float g_qkv[(size_t)MM * QKV_LD];   // [4096, 3072]
__device__ float g_att[(size_t)MM * DDIM];     // [4096, 1024]

// ---------------------------------------------------------------------------
// SGEMM + bias: C[M,N] = A[M,K] @ B[K,N] + bias[N]
// 128x128 block tile, BK=8, 256 threads, 8x8 micro tile (split 4+4 layout).
// M,N,K all multiples of tile dims for this problem -> no bounds checks.
// ---------------------------------------------------------------------------
__global__ __launch_bounds__(256, 2)
void sgemm_bias_kernel(const float* __restrict__ A,
                       const float* __restrict__ Bw,
                       const float* __restrict__ bias,
                       float* __restrict__ C,
                       int K, int N)
{
    __shared__ float As[8][132];   // padded: conflict-free stores
    __shared__ float Bs[8][128];

    const int tid = threadIdx.x;
    const int m0 = blockIdx.y * 128;
    const int n0 = blockIdx.x * 128;
    const int tm4 = (tid >> 4) * 4;       // 0..60
    const int tn4 = (tid & 15) * 4;       // 0..60

    float acc[8][8];
#pragma unroll
    for (int i = 0; i < 8; i++)
#pragma unroll
        for (int j = 0; j < 8; j++) acc[i][j] = 0.f;

    for (int k0 = 0; k0 < K; k0 += 8) {
#pragma unroll
        for (int i = 0; i < 4; i++) {
            int idx = tid + i * 256;           // 0..1023
            int ma = idx >> 3, ka = idx & 7;   // A tile: 128 x 8
            As[ka][ma] = A[(size_t)(m0 + ma) * K + (k0 + ka)];
            int nb = idx & 127, kb = idx >> 7; // B tile: 8 x 128
            Bs[kb][nb] = Bw[(size_t)(k0 + kb) * N + (n0 + nb)];
        }
        __syncthreads();

#pragma unroll
        for (int kk = 0; kk < 8; kk++) {
            float4 a0 = *(const float4*)&As[kk][tm4];
            float4 a1 = *(const float4*)&As[kk][tm4 + 64];
            float4 b0 = *(const float4*)&Bs[kk][tn4];
            float4 b1 = *(const float4*)&Bs[kk][tn4 + 64];
            float ar[8] = {a0.x, a0.y, a0.z, a0.w, a1.x, a1.y, a1.z, a1.w};
            float br[8] = {b0.x, b0.y, b0.z, b0.w, b1.x, b1.y, b1.z, b1.w};
#pragma unroll
            for (int i = 0; i < 8; i++)
#pragma unroll
                for (int j = 0; j < 8; j++)
                    acc[i][j] = fmaf(ar[i], br[j], acc[i][j]);
        }
        __syncthreads();
    }

    float4 bv0 = *(const float4*)&bias[n0 + tn4];
    float4 bv1 = *(const float4*)&bias[n0 + tn4 + 64];
#pragma unroll
    for (int i = 0; i < 8; i++) {
        int rm = (i < 4) ? (tm4 + i) : (tm4 + 64 + (i - 4));
        size_t rowoff = (size_t)(m0 + rm) * N + n0;
        float4 o0 = make_float4(acc[i][0] + bv0.x, acc[i][1] + bv0.y,
                                acc[i][2] + bv0.z, acc[i][3] + bv0.w);
        float4 o1 = make_float4(acc[i][4] + bv1.x, acc[i][5] + bv1.y,
                                acc[i][6] + bv1.z, acc[i][7] + bv1.w);
        *(float4*)&C[rowoff + tn4]      = o0;
        *(float4*)&C[rowoff + tn4 + 64] = o1;
    }
}

// ---------------------------------------------------------------------------
// Flash attention fp32, causal.
// Grid: (S/128 q-tiles, H, B). Block: 256 threads.
// Each thread: 2 queries (qq, qq+64), key-group g = tid&3 (keys 4*jj+g),
// owns output dims d = g*4 + (dd&3) + (dd>>2)*16.
// Dynamic smem: Qs[128][65] Ks[64][65] Vs[64][65] Ps[128][65] = 99840 B.
// ---------------------------------------------------------------------------
#define FLD 65
#define FLASH_SMEM (((size_t)(128 + 64 + 64 + 128) * FLD) * sizeof(float))

__global__ __launch_bounds__(256, 2)
void flash_kernel(const float* __restrict__ qkv, float* __restrict__ out)
{
    extern __shared__ float sm[];
    float* Qs = sm;                   // 128*65
    float* Ks = Qs + 128 * FLD;       // 64*65
    float* Vs = Ks + 64 * FLD;        // 64*65
    float* Ps = Vs + 64 * FLD;        // 128*65

    const int tid = threadIdx.x;
    const int qt = blockIdx.x, h = blockIdx.y, b = blockIdx.z;
    const int qq = tid >> 2;          // 0..63
    const int g  = tid & 3;

    // Load Q tile (128 rows), scale 1/sqrt(64) folded in
    const float* qbase = qkv + (size_t)(b * SS + qt * 128) * QKV_LD + h * HDIM;
    for (int idx = tid; idx < 128 * 64; idx += 256) {
        int r = idx >> 6, c = idx & 63;
        Qs[r * FLD + c] = qbase[(size_t)r * QKV_LD + c] * 0.125f;
    }

    float acc0[16], acc1[16];
#pragma unroll
    for (int i = 0; i < 16; i++) { acc0[i] = 0.f; acc1[i] = 0.f; }
    float m0 = -CUDART_INF_F, m1 = -CUDART_INF_F;
    float l0 = 0.f, l1 = 0.f;

    const int qg0 = qt * 128 + qq;    // query row for acc0; acc1 is qg0+64
    const int ktmax = 2 * qt + 1;

    for (int kt = 0; kt <= ktmax; kt++) {
        __syncthreads();  // previous AV done before overwriting K/V
        const float* kbase = qkv + (size_t)(b * SS + kt * 64) * QKV_LD + DDIM + h * HDIM;
        const float* vbase = kbase + DDIM;
        for (int idx = tid; idx < 64 * 64; idx += 256) {
            int r = idx >> 6, c = idx & 63;
            Ks[r * FLD + c] = kbase[(size_t)r * QKV_LD + c];
            Vs[r * FLD + c] = vbase[(size_t)r * QKV_LD + c];
        }
        __syncthreads();

        // --- scores: S[q][k] = Q.K ---
        float s0[16], s1[16];
#pragma unroll
        for (int jj = 0; jj < 16; jj++) { s0[jj] = 0.f; s1[jj] = 0.f; }
#pragma unroll 4
        for (int d = 0; d < 64; d++) {
            float q0 = Qs[qq * FLD + d];
            float q1 = Qs[(qq + 64) * FLD + d];
#pragma unroll
            for (int jj = 0; jj < 16; jj++) {
                float kv = Ks[(4 * jj + g) * FLD + d];
                s0[jj] = fmaf(q0, kv, s0[jj]);
                s1[jj] = fmaf(q1, kv, s1[jj]);
            }
        }

        // causal mask (only the 2 diagonal key-tiles)
        if (kt >= 2 * qt) {
#pragma unroll
            for (int jj = 0; jj < 16; jj++) {
                int kg = kt * 64 + 4 * jj + g;
                if (kg > qg0)      s0[jj] = -CUDART_INF_F;
                if (kg > qg0 + 64) s1[jj] = -CUDART_INF_F;
            }
        }

        // --- online softmax (rows reduced across the 4-lane group) ---
        float mt0 = s0[0], mt1 = s1[0];
#pragma unroll
        for (int jj = 1; jj < 16; jj++) {
            mt0 = fmaxf(mt0, s0[jj]); mt1 = fmaxf(mt1, s1[jj]);
        }
        mt0 = fmaxf(mt0, __shfl_xor_sync(0xffffffffu, mt0, 1));
        mt0 = fmaxf(mt0, __shfl_xor_sync(0xffffffffu, mt0, 2));
        mt1 = fmaxf(mt1, __shfl_xor_sync(0xffffffffu, mt1, 1));
        mt1 = fmaxf(mt1, __shfl_xor_sync(0xffffffffu, mt1, 2));

        float mn0 = fmaxf(m0, mt0), mn1 = fmaxf(m1, mt1);
        float fac0 = __expf(m0 - mn0), fac1 = __expf(m1 - mn1);
        float lt0 = 0.f, lt1 = 0.f;
#pragma unroll
        for (int jj = 0; jj < 16; jj++) {
            s0[jj] = __expf(s0[jj] - mn0); lt0 += s0[jj];
            s1[jj] = __expf(s1[jj] - mn1); lt1 += s1[jj];
        }
        lt0 += __shfl_xor_sync(0xffffffffu, lt0, 1);
        lt0 += __shfl_xor_sync(0xffffffffu, lt0, 2);
        lt1 += __shfl_xor_sync(0xffffffffu, lt1, 1);
        lt1 += __shfl_xor_sync(0xffffffffu, lt1, 2);
        l0 = l0 * fac0 + lt0;  m0 = mn0;
        l1 = l1 * fac1 + lt1;  m1 = mn1;
#pragma unroll
        for (int i = 0; i < 16; i++) { acc0[i] *= fac0; acc1[i] *= fac1; }

#pragma unroll
        for (int jj = 0; jj < 16; jj++) {
            Ps[qq * FLD + 4 * jj + g]        = s0[jj];
            Ps[(qq + 64) * FLD + 4 * jj + g] = s1[jj];
        }
        __syncthreads();

        // --- AV accumulate ---
#pragma unroll 4
        for (int k = 0; k < 64; k++) {
            float pv0 = Ps[qq * FLD + k];
            float pv1 = Ps[(qq + 64) * FLD + k];
#pragma unroll
            for (int dd = 0; dd < 16; dd++) {
                int d = g * 4 + (dd & 3) + (dd >> 2) * 16;
                float v = Vs[k * FLD + d];
                acc0[dd] = fmaf(pv0, v, acc0[dd]);
                acc1[dd] = fmaf(pv1, v, acc1[dd]);
            }
        }
    }

    float r0 = 1.f / l0, r1 = 1.f / l1;
    float* o0 = out + (size_t)(b * SS + qt * 128 + qq) * DDIM + h * HDIM;
    float* o1 = o0 + (size_t)64 * DDIM;
#pragma unroll
    for (int dd = 0; dd < 16; dd++) {
        int d = g * 4 + (dd & 3) + (dd >> 2) * 16;
        o0[d] = acc0[dd] * r0;
        o1[d] = acc1[dd] * r1;
    }
}

// ---------------------------------------------------------------------------
extern "C" void kernel_launch(void* const* d_in, const int* in_sizes, int n_in,
                              void* d_out, int out_size)
{
    const float* x      = (const float*)d_in[0];  // [B,S,D]
    const float* w_attn = (const float*)d_in[1];  // [D,3D]
    const float* b_attn = (const float*)d_in[2];  // [3D]
    const float* w_proj = (const float*)d_in[3];  // [D,D]
    const float* b_proj = (const float*)d_in[4];  // [D]
    float* out = (float*)d_out;                   // [B,S,D]

    float *qkv = nullptr, *att = nullptr;
    cudaGetSymbolAddress((void**)&qkv, g_qkv);
    cudaGetSymbolAddress((void**)&att, g_att);

    cudaFuncSetAttribute(flash_kernel,
                         cudaFuncAttributeMaxDynamicSharedMemorySize,
                         (int)FLASH_SMEM);

    // 1) QKV = x @ Wqkv + b : [4096,1024]x[1024,3072]
    sgemm_bias_kernel<<<dim3(QKV_LD / 128, MM / 128), 256>>>(
        x, w_attn, b_attn, qkv, DDIM, QKV_LD);

    // 2) causal attention -> g_att [B,S,D]
    flash_kernel<<<dim3(SS / 128, HH, BB), 256, FLASH_SMEM>>>(qkv, att);

    // 3) out = att @ Wproj + b : [4096,1024]x[1024,1024]
    sgemm_bias_kernel<<<dim3(DDIM / 128, MM / 128), 256>>>(
        att, w_proj, b_proj, out, DDIM, DDIM);
}

// round 3
// speedup vs baseline: 1.2485x; 1.2485x over previous
#include <cuda_runtime.h>
#include <cuda_bf16.h>
#include <math_constants.h>
#include <cstdint>

#define BB 2
#define SS 2048
#define DDIM 1024
#define HH 16
#define HDIM 64
#define MM (BB*SS)          // 4096 rows
#define QKV_LD 3072         // 3*D

// ---------------------------------------------------------------------------
// Scratch (device globals: allowed; runtime allocs are not)
// ---------------------------------------------------------------------------
__device__ float g_qkv[(size_t)MM * QKV_LD];            // fp32 QKV for flash
__device__ __nv_bfloat16 g_xhi[(size_t)MM * DDIM];      // x split
__device__ __nv_bfloat16 g_xlo[(size_t)MM * DDIM];
__device__ __nv_bfloat16 g_w1hi[(size_t)QKV_LD * DDIM]; // w_attn^T [3072,1024]
__device__ __nv_bfloat16 g_w1lo[(size_t)QKV_LD * DDIM];
__device__ __nv_bfloat16 g_w2hi[(size_t)DDIM * DDIM];   // w_proj^T [1024,1024]
__device__ __nv_bfloat16 g_w2lo[(size_t)DDIM * DDIM];
__device__ __nv_bfloat16 g_ahi[(size_t)MM * DDIM];      // attention out split
__device__ __nv_bfloat16 g_alo[(size_t)MM * DDIM];

// ---------------------------------------------------------------------------
// Portable PTX helpers (NO tcgen05 — harness PTX targets plain compute_103)
// ---------------------------------------------------------------------------
__device__ __forceinline__ uint32_t smem_u32(const void* p) {
    uint32_t a;
    asm("{ .reg .u64 t; cvta.to.shared.u64 t, %1; cvt.u32.u64 %0, t; }"
        : "=r"(a) : "l"(p));
    return a;
}

#define CP_ASYNC16(sa, gp) \
    asm volatile("cp.async.cg.shared.global [%0], [%1], 16;" :: "r"(sa), "l"(gp))
#define CP_COMMIT() asm volatile("cp.async.commit_group;" ::: "memory")
#define CP_WAIT1()  asm volatile("cp.async.wait_group 1;" ::: "memory")
#define CP_WAIT0()  asm volatile("cp.async.wait_group 0;" ::: "memory")

#define LDSM_X4(r0, r1, r2, r3, addr) \
    asm volatile("ldmatrix.sync.aligned.m8n8.x4.shared.b16 {%0,%1,%2,%3}, [%4];" \
        : "=r"(r0), "=r"(r1), "=r"(r2), "=r"(r3) : "r"(addr))

#define MMA_BF16(c, a0, a1, a2, a3, b0, b1) \
    asm volatile("mma.sync.aligned.m16n8k16.row.col.f32.bf16.bf16.f32 " \
        "{%0,%1,%2,%3}, {%4,%5,%6,%7}, {%8,%9}, {%0,%1,%2,%3};" \
        : "+f"((c)[0]), "+f"((c)[1]), "+f"((c)[2]), "+f"((c)[3]) \
        : "r"(a0), "r"(a1), "r"(a2), "r"(a3), "r"(b0), "r"(b1))

// ---------------------------------------------------------------------------
// Prep: fp32 -> (bf16 hi, bf16 lo) split (lo = x - hi)
// ---------------------------------------------------------------------------
__global__ void split_plain(const float* __restrict__ s,
                            __nv_bfloat16* __restrict__ hi,
                            __nv_bfloat16* __restrict__ lo, int n4)
{
    for (int i = blockIdx.x * blockDim.x + threadIdx.x; i < n4;
         i += gridDim.x * blockDim.x) {
        float4 v = ((const float4*)s)[i];
        __nv_bfloat16 h0 = __float2bfloat16(v.x), h1 = __float2bfloat16(v.y);
        __nv_bfloat16 h2 = __float2bfloat16(v.z), h3 = __float2bfloat16(v.w);
        __nv_bfloat162* hp = (__nv_bfloat162*)hi;
        __nv_bfloat162* lp = (__nv_bfloat162*)lo;
        hp[2 * i]     = __halves2bfloat162(h0, h1);
        hp[2 * i + 1] = __halves2bfloat162(h2, h3);
        lp[2 * i]     = __halves2bfloat162(
            __float2bfloat16(v.x - __bfloat162float(h0)),
            __float2bfloat16(v.y - __bfloat162float(h1)));
        lp[2 * i + 1] = __halves2bfloat162(
            __float2bfloat16(v.z - __bfloat162float(h2)),
            __float2bfloat16(v.w - __bfloat162float(h3)));
    }
}

// Prep: transpose W[K,N] -> WT[N,K] with bf16 hi/lo split.
__global__ void transpose_split(const float* __restrict__ W,
                                __nv_bfloat16* __restrict__ hi,
                                __nv_bfloat16* __restrict__ lo, int K, int N)
{
    __shared__ float t[32][33];
    int n0 = blockIdx.x * 32, k0 = blockIdx.y * 32;
    int tx = threadIdx.x, ty = threadIdx.y;
#pragma unroll
    for (int i = 0; i < 32; i += 8)
        t[ty + i][tx] = W[(size_t)(k0 + ty + i) * N + n0 + tx];
    __syncthreads();
#pragma unroll
    for (int i = 0; i < 32; i += 8) {
        float v = t[tx][ty + i];
        __nv_bfloat16 h = __float2bfloat16(v);
        size_t o = (size_t)(n0 + ty + i) * K + k0 + tx;
        hi[o] = h;
        lo[o] = __float2bfloat16(v - __bfloat162float(h));
    }
}

// ---------------------------------------------------------------------------
// HMMA split-bf16 GEMM + bias: C[M,N] = (Ahi+Alo)[M,K] @ (Bhi+Blo)^T + bias
// A: [M,K] bf16 row-major; B: [N,K] bf16 row-major (weights pre-transposed).
// 128x128 CTA tile, 8 warps (warp tile 32x64), K-tile 32, cp.async double
// buffer, ldmatrix fragments, 3 MMAs per k16 step (hi*hi + hi*lo + lo*hi).
// ---------------------------------------------------------------------------
#define SAS 40                        // smem row stride (bf16 elems), pad 32->40
#define ARR_ELEMS (128 * SAS)         // 5120 bf16 per array
#define STAGE_ELEMS (4 * ARR_ELEMS)   // Ahi, Alo, Bhi, Blo
#define HMMA_SMEM (2 * STAGE_ELEMS * 2)  // 81920 bytes

__global__ __launch_bounds__(256, 1)
void hmma_gemm(const __nv_bfloat16* __restrict__ Ahi, const __nv_bfloat16* __restrict__ Alo,
               const __nv_bfloat16* __restrict__ Bhi, const __nv_bfloat16* __restrict__ Blo,
               const float* __restrict__ bias, float* __restrict__ C, int K, int N)
{
    extern __shared__ __align__(16) char smraw[];
    const uint32_t sb = smem_u32(smraw);

    const int tid = threadIdx.x;
    const int wid = tid >> 5, lane = tid & 31;
    const int m0 = blockIdx.y * 128, n0 = blockIdx.x * 128;
    const int warp_m = wid & 3;      // 4 warps along M (32 rows each)
    const int warp_n = wid >> 2;     // 2 warps along N (64 cols each)

    const __nv_bfloat16* arrs[4] = {Ahi, Alo, Bhi, Blo};

    float c[2][8][4];
#pragma unroll
    for (int mi = 0; mi < 2; mi++)
#pragma unroll
        for (int nt = 0; nt < 8; nt++)
#pragma unroll
            for (int j = 0; j < 4; j++) c[mi][nt][j] = 0.f;

    const int nkt = K / 32;

    // stage loader: 4 arrays x 128 rows x 4 16B-chunks = 2048 chunks / 256 thr
    auto load_stage = [&](int kt, int buf) {
        const int k0 = kt * 32;
        const uint32_t sbase = sb + (uint32_t)buf * STAGE_ELEMS * 2;
#pragma unroll
        for (int arr = 0; arr < 4; arr++) {
            const __nv_bfloat16* P = arrs[arr];
            const int rowbase = (arr < 2) ? m0 : n0;
#pragma unroll
            for (int i = 0; i < 2; i++) {
                int idx = tid + i * 256;          // 0..511
                int r = idx >> 2, ch = idx & 3;
                const __nv_bfloat16* gp = P + (size_t)(rowbase + r) * K + k0 + ch * 8;
                uint32_t sa = sbase + (uint32_t)(arr * ARR_ELEMS + r * SAS + ch * 8) * 2;
                CP_ASYNC16(sa, gp);
            }
        }
        CP_COMMIT();
    };

    load_stage(0, 0);

    const int lrow = lane & 15;
    const int lkb  = (lane >> 4) * 8;   // k sub-chunk for ldmatrix

    for (int kt = 0; kt < nkt; kt++) {
        const int buf = kt & 1;
        if (kt + 1 < nkt) { load_stage(kt + 1, (kt + 1) & 1); CP_WAIT1(); }
        else              { CP_WAIT0(); }
        __syncthreads();

        const uint32_t sbase = sb + (uint32_t)buf * STAGE_ELEMS * 2;
        const uint32_t aRow = warp_m * 32;
        const uint32_t bRow = warp_n * 64;

#pragma unroll
        for (int ks = 0; ks < 2; ks++) {       // two k16 steps
            const int kcol = ks * 16 + lkb;
            uint32_t ah[2][4], al[2][4], bh[4][4], bl[4][4];
#pragma unroll
            for (int mi = 0; mi < 2; mi++) {
                uint32_t off = (uint32_t)((aRow + mi * 16 + lrow) * SAS + kcol) * 2;
                LDSM_X4(ah[mi][0], ah[mi][1], ah[mi][2], ah[mi][3],
                        sbase + 0 * ARR_ELEMS * 2 + off);
                LDSM_X4(al[mi][0], al[mi][1], al[mi][2], al[mi][3],
                        sbase + 1 * ARR_ELEMS * 2 + off);
            }
#pragma unroll
            for (int np = 0; np < 4; np++) {   // pairs of n8 tiles
                uint32_t off = (uint32_t)((bRow + np * 16 + lrow) * SAS + kcol) * 2;
                LDSM_X4(bh[np][0], bh[np][1], bh[np][2], bh[np][3],
                        sbase + 2 * ARR_ELEMS * 2 + off);
                LDSM_X4(bl[np][0], bl[np][1], bl[np][2], bl[np][3],
                        sbase + 3 * ARR_ELEMS * 2 + off);
            }
#pragma unroll
            for (int mi = 0; mi < 2; mi++) {
#pragma unroll
                for (int nt = 0; nt < 8; nt++) {
                    const int np = nt >> 1, hf = nt & 1;
                    MMA_BF16(c[mi][nt], ah[mi][0], ah[mi][1], ah[mi][2], ah[mi][3],
                             bh[np][hf], bh[np][2 + hf]);
                    MMA_BF16(c[mi][nt], ah[mi][0], ah[mi][1], ah[mi][2], ah[mi][3],
                             bl[np][hf], bl[np][2 + hf]);
                    MMA_BF16(c[mi][nt], al[mi][0], al[mi][1], al[mi][2], al[mi][3],
                             bh[np][hf], bh[np][2 + hf]);
                }
            }
        }
        __syncthreads();   // compute done before next cp.async overwrites buf
    }

    // Epilogue: bias + direct stores (float2 per fragment row)
#pragma unroll
    for (int mi = 0; mi < 2; mi++) {
        int r0 = m0 + warp_m * 32 + mi * 16 + (lane >> 2);
        int r1 = r0 + 8;
#pragma unroll
        for (int nt = 0; nt < 8; nt++) {
            int col = n0 + warp_n * 64 + nt * 8 + (lane & 3) * 2;
            float b0 = bias[col], b1 = bias[col + 1];
            *(float2*)&C[(size_t)r0 * N + col] =
                make_float2(c[mi][nt][0] + b0, c[mi][nt][1] + b1);
            *(float2*)&C[(size_t)r1 * N + col] =
                make_float2(c[mi][nt][2] + b0, c[mi][nt][3] + b1);
        }
    }
}

// ---------------------------------------------------------------------------
// Flash attention fp32, causal (passing R1 version; epilogue writes the
// bf16 hi/lo split of the output for the HMMA proj GEMM).
// ---------------------------------------------------------------------------
#define FLD 65
#define FLASH_SMEM (((size_t)(128 + 64 + 64 + 128) * FLD) * sizeof(float))

__global__ __launch_bounds__(256, 2)
void flash_kernel(const float* __restrict__ qkv,
                  __nv_bfloat16* __restrict__ ohi,
                  __nv_bfloat16* __restrict__ olo)
{
    extern __shared__ float smf[];
    float* Qs = smf;
    float* Ks = Qs + 128 * FLD;
    float* Vs = Ks + 64 * FLD;
    float* Ps = Vs + 64 * FLD;

    const int tid = threadIdx.x;
    const int qt = blockIdx.x, h = blockIdx.y, b = blockIdx.z;
    const int qq = tid >> 2;
    const int g  = tid & 3;

    const float* qbase = qkv + (size_t)(b * SS + qt * 128) * QKV_LD + h * HDIM;
    for (int idx = tid; idx < 128 * 64; idx += 256) {
        int r = idx >> 6, c = idx & 63;
        Qs[r * FLD + c] = qbase[(size_t)r * QKV_LD + c] * 0.125f;
    }

    float acc0[16], acc1[16];
#pragma unroll
    for (int i = 0; i < 16; i++) { acc0[i] = 0.f; acc1[i] = 0.f; }
    float m0 = -CUDART_INF_F, m1 = -CUDART_INF_F;
    float l0 = 0.f, l1 = 0.f;

    const int qg0 = qt * 128 + qq;
    const int ktmax = 2 * qt + 1;

    for (int kt = 0; kt <= ktmax; kt++) {
        __syncthreads();
        const float* kbase = qkv + (size_t)(b * SS + kt * 64) * QKV_LD + DDIM + h * HDIM;
        const float* vbase = kbase + DDIM;
        for (int idx = tid; idx < 64 * 64; idx += 256) {
            int r = idx >> 6, c = idx & 63;
            Ks[r * FLD + c] = kbase[(size_t)r * QKV_LD + c];
            Vs[r * FLD + c] = vbase[(size_t)r * QKV_LD + c];
        }
        __syncthreads();

        float s0[16], s1[16];
#pragma unroll
        for (int jj = 0; jj < 16; jj++) { s0[jj] = 0.f; s1[jj] = 0.f; }
#pragma unroll 4
        for (int d = 0; d < 64; d++) {
            float q0 = Qs[qq * FLD + d];
            float q1 = Qs[(qq + 64) * FLD + d];
#pragma unroll
            for (int jj = 0; jj < 16; jj++) {
                float kv = Ks[(4 * jj + g) * FLD + d];
                s0[jj] = fmaf(q0, kv, s0[jj]);
                s1[jj] = fmaf(q1, kv, s1[jj]);
            }
        }

        if (kt >= 2 * qt) {
#pragma unroll
            for (int jj = 0; jj < 16; jj++) {
                int kg = kt * 64 + 4 * jj + g;
                if (kg > qg0)      s0[jj] = -CUDART_INF_F;
                if (kg > qg0 + 64) s1[jj] = -CUDART_INF_F;
            }
        }

        float mt0 = s0[0], mt1 = s1[0];
#pragma unroll
        for (int jj = 1; jj < 16; jj++) {
            mt0 = fmaxf(mt0, s0[jj]); mt1 = fmaxf(mt1, s1[jj]);
        }
        mt0 = fmaxf(mt0, __shfl_xor_sync(0xffffffffu, mt0, 1));
        mt0 = fmaxf(mt0, __shfl_xor_sync(0xffffffffu, mt0, 2));
        mt1 = fmaxf(mt1, __shfl_xor_sync(0xffffffffu, mt1, 1));
        mt1 = fmaxf(mt1, __shfl_xor_sync(0xffffffffu, mt1, 2));

        float mn0 = fmaxf(m0, mt0), mn1 = fmaxf(m1, mt1);
        float fac0 = __expf(m0 - mn0), fac1 = __expf(m1 - mn1);
        float lt0 = 0.f, lt1 = 0.f;
#pragma unroll
        for (int jj = 0; jj < 16; jj++) {
            s0[jj] = __expf(s0[jj] - mn0); lt0 += s0[jj];
            s1[jj] = __expf(s1[jj] - mn1); lt1 += s1[jj];
        }
        lt0 += __shfl_xor_sync(0xffffffffu, lt0, 1);
        lt0 += __shfl_xor_sync(0xffffffffu, lt0, 2);
        lt1 += __shfl_xor_sync(0xffffffffu, lt1, 1);
        lt1 += __shfl_xor_sync(0xffffffffu, lt1, 2);
        l0 = l0 * fac0 + lt0;  m0 = mn0;
        l1 = l1 * fac1 + lt1;  m1 = mn1;
#pragma unroll
        for (int i = 0; i < 16; i++) { acc0[i] *= fac0; acc1[i] *= fac1; }

#pragma unroll
        for (int jj = 0; jj < 16; jj++) {
            Ps[qq * FLD + 4 * jj + g]        = s0[jj];
            Ps[(qq + 64) * FLD + 4 * jj + g] = s1[jj];
        }
        __syncthreads();

#pragma unroll 4
        for (int k = 0; k < 64; k++) {
            float pv0 = Ps[qq * FLD + k];
            float pv1 = Ps[(qq + 64) * FLD + k];
#pragma unroll
            for (int dd = 0; dd < 16; dd++) {
                int d = g * 4 + (dd & 3) + (dd >> 2) * 16;
                float v = Vs[k * FLD + d];
                acc0[dd] = fmaf(pv0, v, acc0[dd]);
                acc1[dd] = fmaf(pv1, v, acc1[dd]);
            }
        }
    }

    float r0 = 1.f / l0, r1 = 1.f / l1;
    size_t base0 = (size_t)(b * SS + qt * 128 + qq) * DDIM + h * HDIM;
    size_t base1 = base0 + (size_t)64 * DDIM;
#pragma unroll
    for (int dd = 0; dd < 16; dd++) {
        int d = g * 4 + (dd & 3) + (dd >> 2) * 16;
        float v0 = acc0[dd] * r0;
        float v1 = acc1[dd] * r1;
        __nv_bfloat16 h0 = __float2bfloat16(v0);
        __nv_bfloat16 h1 = __float2bfloat16(v1);
        ohi[base0 + d] = h0;
        olo[base0 + d] = __float2bfloat16(v0 - __bfloat162float(h0));
        ohi[base1 + d] = h1;
        olo[base1 + d] = __float2bfloat16(v1 - __bfloat162float(h1));
    }
}

// ---------------------------------------------------------------------------
extern "C" void kernel_launch(void* const* d_in, const int* in_sizes, int n_in,
                              void* d_out, int out_size)
{
    const float* x      = (const float*)d_in[0];  // [B,S,D]
    const float* w_attn = (const float*)d_in[1];  // [D,3D]
    const float* b_attn = (const float*)d_in[2];  // [3D]
    const float* w_proj = (const float*)d_in[3];  // [D,D]
    const float* b_proj = (const float*)d_in[4];  // [D]
    float* out = (float*)d_out;                   // [B,S,D]

    float* qkv = nullptr;
    __nv_bfloat16 *xhi, *xlo, *w1hi, *w1lo, *w2hi, *w2lo, *ahi, *alo;
    cudaGetSymbolAddress((void**)&qkv,  g_qkv);
    cudaGetSymbolAddress((void**)&xhi,  g_xhi);
    cudaGetSymbolAddress((void**)&xlo,  g_xlo);
    cudaGetSymbolAddress((void**)&w1hi, g_w1hi);
    cudaGetSymbolAddress((void**)&w1lo, g_w1lo);
    cudaGetSymbolAddress((void**)&w2hi, g_w2hi);
    cudaGetSymbolAddress((void**)&w2lo, g_w2lo);
    cudaGetSymbolAddress((void**)&ahi,  g_ahi);
    cudaGetSymbolAddress((void**)&alo,  g_alo);

    cudaFuncSetAttribute(flash_kernel,
                         cudaFuncAttributeMaxDynamicSharedMemorySize, (int)FLASH_SMEM);
    cudaFuncSetAttribute(hmma_gemm,
                         cudaFuncAttributeMaxDynamicSharedMemorySize, HMMA_SMEM);

    // Prep: split x, transpose+split weights
    split_plain<<<1024, 256>>>(x, xhi, xlo, MM * DDIM / 4);
    transpose_split<<<dim3(QKV_LD / 32, DDIM / 32), dim3(32, 8)>>>(w_attn, w1hi, w1lo, DDIM, QKV_LD);
    transpose_split<<<dim3(DDIM / 32, DDIM / 32),  dim3(32, 8)>>>(w_proj, w2hi, w2lo, DDIM, DDIM);

    // 1) QKV = x @ Wqkv + b  (HMMA split-bf16)
    hmma_gemm<<<dim3(QKV_LD / 128, MM / 128), 256, HMMA_SMEM>>>(
        xhi, xlo, w1hi, w1lo, b_attn, qkv, DDIM, QKV_LD);

    // 2) causal attention -> bf16 hi/lo split of attn output
    flash_kernel<<<dim3(SS / 128, HH, BB), 256, FLASH_SMEM>>>(qkv, ahi, alo);

    // 3) out = att @ Wproj + b  (HMMA split-bf16)
    hmma_gemm<<<dim3(DDIM / 128, MM / 128), 256, HMMA_SMEM>>>(
        ahi, alo, w2hi, w2lo, b_proj, out, DDIM, DDIM);
}

// round 4
// speedup vs baseline: 2.6820x; 2.1482x over previous
#include <cuda_runtime.h>
#include <cuda_bf16.h>
#include <math_constants.h>
#include <cstdint>

#define BB 2
#define SS 2048
#define DDIM 1024
#define HH 16
#define HDIM 64
#define MM (BB*SS)          // 4096 rows
#define QKV_LD 3072         // 3*D

// ---------------------------------------------------------------------------
// Scratch (device globals: allowed; runtime allocs are not)
// ---------------------------------------------------------------------------
__device__ __nv_bfloat16 g_qkvhi[(size_t)MM * QKV_LD];  // QKV hi (Q pre-scaled)
__device__ __nv_bfloat16 g_qkvlo[(size_t)MM * QKV_LD];  // QKV lo
__device__ __nv_bfloat16 g_xhi[(size_t)MM * DDIM];      // x split
__device__ __nv_bfloat16 g_xlo[(size_t)MM * DDIM];
__device__ __nv_bfloat16 g_w1hi[(size_t)QKV_LD * DDIM]; // w_attn^T [3072,1024]
__device__ __nv_bfloat16 g_w1lo[(size_t)QKV_LD * DDIM];
__device__ __nv_bfloat16 g_w2hi[(size_t)DDIM * DDIM];   // w_proj^T [1024,1024]
__device__ __nv_bfloat16 g_w2lo[(size_t)DDIM * DDIM];
__device__ __nv_bfloat16 g_ahi[(size_t)MM * DDIM];      // attention out split
__device__ __nv_bfloat16 g_alo[(size_t)MM * DDIM];

// ---------------------------------------------------------------------------
// Portable PTX helpers (NO tcgen05 — harness PTX targets plain compute_103)
// ---------------------------------------------------------------------------
__device__ __forceinline__ uint32_t smem_u32(const void* p) {
    uint32_t a;
    asm("{ .reg .u64 t; cvta.to.shared.u64 t, %1; cvt.u32.u64 %0, t; }"
        : "=r"(a) : "l"(p));
    return a;
}

#define CP_ASYNC16(sa, gp) \
    asm volatile("cp.async.cg.shared.global [%0], [%1], 16;" :: "r"(sa), "l"(gp))
#define CP_COMMIT() asm volatile("cp.async.commit_group;" ::: "memory")
#define CP_WAIT1()  asm volatile("cp.async.wait_group 1;" ::: "memory")
#define CP_WAIT0()  asm volatile("cp.async.wait_group 0;" ::: "memory")

#define LDSM_X4(r0, r1, r2, r3, addr) \
    asm volatile("ldmatrix.sync.aligned.m8n8.x4.shared.b16 {%0,%1,%2,%3}, [%4];" \
        : "=r"(r0), "=r"(r1), "=r"(r2), "=r"(r3) : "r"(addr))

#define LDSM_X4_T(r0, r1, r2, r3, addr) \
    asm volatile("ldmatrix.sync.aligned.m8n8.x4.trans.shared.b16 {%0,%1,%2,%3}, [%4];" \
        : "=r"(r0), "=r"(r1), "=r"(r2), "=r"(r3) : "r"(addr))

#define MMA_BF16(c, a0, a1, a2, a3, b0, b1) \
    asm volatile("mma.sync.aligned.m16n8k16.row.col.f32.bf16.bf16.f32 " \
        "{%0,%1,%2,%3}, {%4,%5,%6,%7}, {%8,%9}, {%0,%1,%2,%3};" \
        : "+f"((c)[0]), "+f"((c)[1]), "+f"((c)[2]), "+f"((c)[3]) \
        : "r"(a0), "r"(a1), "r"(a2), "r"(a3), "r"(b0), "r"(b1))

__device__ __forceinline__ uint32_t pack_bf2(float a, float b) {
    __nv_bfloat162 t = __halves2bfloat162(__float2bfloat16(a), __float2bfloat16(b));
    return *(uint32_t*)&t;
}
__device__ __forceinline__ uint32_t pack_lo2(float a, float b, uint32_t hipack) {
    __nv_bfloat162 h = *(__nv_bfloat162*)&hipack;
    return pack_bf2(a - __bfloat162float(h.x), b - __bfloat162float(h.y));
}

// ---------------------------------------------------------------------------
// Prep: fp32 -> (bf16 hi, bf16 lo) split
// ---------------------------------------------------------------------------
__global__ void split_plain(const float* __restrict__ s,
                            __nv_bfloat16* __restrict__ hi,
                            __nv_bfloat16* __restrict__ lo, int n4)
{
    for (int i = blockIdx.x * blockDim.x + threadIdx.x; i < n4;
         i += gridDim.x * blockDim.x) {
        float4 v = ((const float4*)s)[i];
        uint32_t h0 = pack_bf2(v.x, v.y), h1 = pack_bf2(v.z, v.w);
        ((uint32_t*)hi)[2 * i]     = h0;
        ((uint32_t*)hi)[2 * i + 1] = h1;
        ((uint32_t*)lo)[2 * i]     = pack_lo2(v.x, v.y, h0);
        ((uint32_t*)lo)[2 * i + 1] = pack_lo2(v.z, v.w, h1);
    }
}

// Prep: transpose W[K,N] -> WT[N,K] with bf16 hi/lo split.
__global__ void transpose_split(const float* __restrict__ W,
                                __nv_bfloat16* __restrict__ hi,
                                __nv_bfloat16* __restrict__ lo, int K, int N)
{
    __shared__ float t[32][33];
    int n0 = blockIdx.x * 32, k0 = blockIdx.y * 32;
    int tx = threadIdx.x, ty = threadIdx.y;
#pragma unroll
    for (int i = 0; i < 32; i += 8)
        t[ty + i][tx] = W[(size_t)(k0 + ty + i) * N + n0 + tx];
    __syncthreads();
#pragma unroll
    for (int i = 0; i < 32; i += 8) {
        float v = t[tx][ty + i];
        __nv_bfloat16 h = __float2bfloat16(v);
        size_t o = (size_t)(n0 + ty + i) * K + k0 + tx;
        hi[o] = h;
        lo[o] = __float2bfloat16(v - __bfloat162float(h));
    }
}

// ---------------------------------------------------------------------------
// HMMA split-bf16 GEMM + bias.
// MODE 0: fp32 C out.  MODE 1: bf16 hi/lo out, Q columns (col<DDIM) x0.125.
// ---------------------------------------------------------------------------
#define SAS 40
#define ARR_ELEMS (128 * SAS)
#define STAGE_ELEMS (4 * ARR_ELEMS)
#define HMMA_SMEM (2 * STAGE_ELEMS * 2)

template<int MODE>
__global__ __launch_bounds__(256, 1)
void hmma_gemm(const __nv_bfloat16* __restrict__ Ahi, const __nv_bfloat16* __restrict__ Alo,
               const __nv_bfloat16* __restrict__ Bhi, const __nv_bfloat16* __restrict__ Blo,
               const float* __restrict__ bias, float* __restrict__ C,
               __nv_bfloat16* __restrict__ Chi, __nv_bfloat16* __restrict__ Clo,
               int K, int N)
{
    extern __shared__ __align__(16) char smraw[];
    const uint32_t sb = smem_u32(smraw);

    const int tid = threadIdx.x;
    const int wid = tid >> 5, lane = tid & 31;
    const int m0 = blockIdx.y * 128, n0 = blockIdx.x * 128;
    const int warp_m = wid & 3;
    const int warp_n = wid >> 2;

    const __nv_bfloat16* arrs[4] = {Ahi, Alo, Bhi, Blo};

    float c[2][8][4];
#pragma unroll
    for (int mi = 0; mi < 2; mi++)
#pragma unroll
        for (int nt = 0; nt < 8; nt++)
#pragma unroll
            for (int j = 0; j < 4; j++) c[mi][nt][j] = 0.f;

    const int nkt = K / 32;

    auto load_stage = [&](int kt, int buf) {
        const int k0 = kt * 32;
        const uint32_t sbase = sb + (uint32_t)buf * STAGE_ELEMS * 2;
#pragma unroll
        for (int arr = 0; arr < 4; arr++) {
            const __nv_bfloat16* P = arrs[arr];
            const int rowbase = (arr < 2) ? m0 : n0;
#pragma unroll
            for (int i = 0; i < 2; i++) {
                int idx = tid + i * 256;
                int r = idx >> 2, ch = idx & 3;
                const __nv_bfloat16* gp = P + (size_t)(rowbase + r) * K + k0 + ch * 8;
                uint32_t sa = sbase + (uint32_t)(arr * ARR_ELEMS + r * SAS + ch * 8) * 2;
                CP_ASYNC16(sa, gp);
            }
        }
        CP_COMMIT();
    };

    load_stage(0, 0);

    const int lrow = lane & 15;
    const int lkb  = (lane >> 4) * 8;

    for (int kt = 0; kt < nkt; kt++) {
        const int buf = kt & 1;
        if (kt + 1 < nkt) { load_stage(kt + 1, (kt + 1) & 1); CP_WAIT1(); }
        else              { CP_WAIT0(); }
        __syncthreads();

        const uint32_t sbase = sb + (uint32_t)buf * STAGE_ELEMS * 2;
        const uint32_t aRow = warp_m * 32;
        const uint32_t bRow = warp_n * 64;

#pragma unroll
        for (int ks = 0; ks < 2; ks++) {
            const int kcol = ks * 16 + lkb;
            uint32_t ah[2][4], al[2][4], bh[4][4], bl[4][4];
#pragma unroll
            for (int mi = 0; mi < 2; mi++) {
                uint32_t off = (uint32_t)((aRow + mi * 16 + lrow) * SAS + kcol) * 2;
                LDSM_X4(ah[mi][0], ah[mi][1], ah[mi][2], ah[mi][3],
                        sbase + 0 * ARR_ELEMS * 2 + off);
                LDSM_X4(al[mi][0], al[mi][1], al[mi][2], al[mi][3],
                        sbase + 1 * ARR_ELEMS * 2 + off);
            }
#pragma unroll
            for (int np = 0; np < 4; np++) {
                uint32_t off = (uint32_t)((bRow + np * 16 + lrow) * SAS + kcol) * 2;
                LDSM_X4(bh[np][0], bh[np][1], bh[np][2], bh[np][3],
                        sbase + 2 * ARR_ELEMS * 2 + off);
                LDSM_X4(bl[np][0], bl[np][1], bl[np][2], bl[np][3],
                        sbase + 3 * ARR_ELEMS * 2 + off);
            }
#pragma unroll
            for (int mi = 0; mi < 2; mi++) {
#pragma unroll
                for (int nt = 0; nt < 8; nt++) {
                    const int np = nt >> 1, hf = nt & 1;
                    MMA_BF16(c[mi][nt], ah[mi][0], ah[mi][1], ah[mi][2], ah[mi][3],
                             bh[np][hf], bh[np][2 + hf]);
                    MMA_BF16(c[mi][nt], ah[mi][0], ah[mi][1], ah[mi][2], ah[mi][3],
                             bl[np][hf], bl[np][2 + hf]);
                    MMA_BF16(c[mi][nt], al[mi][0], al[mi][1], al[mi][2], al[mi][3],
                             bh[np][hf], bh[np][2 + hf]);
                }
            }
        }
        __syncthreads();
    }

    // Epilogue
#pragma unroll
    for (int mi = 0; mi < 2; mi++) {
        int r0 = m0 + warp_m * 32 + mi * 16 + (lane >> 2);
        int r1 = r0 + 8;
#pragma unroll
        for (int nt = 0; nt < 8; nt++) {
            int col = n0 + warp_n * 64 + nt * 8 + (lane & 3) * 2;
            float b0 = bias[col], b1 = bias[col + 1];
            float v00 = c[mi][nt][0] + b0, v01 = c[mi][nt][1] + b1;
            float v10 = c[mi][nt][2] + b0, v11 = c[mi][nt][3] + b1;
            if (MODE == 0) {
                *(float2*)&C[(size_t)r0 * N + col] = make_float2(v00, v01);
                *(float2*)&C[(size_t)r1 * N + col] = make_float2(v10, v11);
            } else {
                if (col < DDIM) {   // Q columns: fold 1/sqrt(hd) (exact in bf16)
                    v00 *= 0.125f; v01 *= 0.125f; v10 *= 0.125f; v11 *= 0.125f;
                }
                uint32_t h0 = pack_bf2(v00, v01);
                uint32_t h1 = pack_bf2(v10, v11);
                *(uint32_t*)&Chi[(size_t)r0 * N + col] = h0;
                *(uint32_t*)&Clo[(size_t)r0 * N + col] = pack_lo2(v00, v01, h0);
                *(uint32_t*)&Chi[(size_t)r1 * N + col] = h1;
                *(uint32_t*)&Clo[(size_t)r1 * N + col] = pack_lo2(v10, v11, h1);
            }
        }
    }
}

// ---------------------------------------------------------------------------
// HMMA flash attention, causal, split-bf16 (3-term) for QK^T and PV.
// Grid (16, H, B), 256 threads = 8 warps, warp = 16 q-rows.
// P stays in registers (accumulator layout == A-fragment layout).
// ---------------------------------------------------------------------------
#define FSTR 72
#define Q_ELEMS (128 * FSTR)
#define KV_ARR (64 * FSTR)
#define KV_STAGE (4 * KV_ARR)
#define FL_SMEM ((2 * Q_ELEMS + 2 * KV_STAGE) * 2)   // 110592 bytes

__global__ __launch_bounds__(256, 1)
void flash_hmma(const __nv_bfloat16* __restrict__ qkvhi,
                const __nv_bfloat16* __restrict__ qkvlo,
                __nv_bfloat16* __restrict__ ohi,
                __nv_bfloat16* __restrict__ olo)
{
    extern __shared__ __align__(16) char smraw[];
    const uint32_t sb = smem_u32(smraw);
    const int tid = threadIdx.x, wid = tid >> 5, lane = tid & 31;
    const int qt = gridDim.x - 1 - blockIdx.x;   // big tiles first
    const int h = blockIdx.y, b = blockIdx.z;
    const size_t qrowg = (size_t)(b * SS + qt * 128);
    const int hcol = h * HDIM;
    const int lrow = lane & 15, lkb = (lane >> 4) * 8;

    // Q tile hi/lo -> smem (group A)
#pragma unroll
    for (int i = 0; i < 4; i++) {
        int idx = tid + i * 256;
        int r = idx >> 3, ch = idx & 7;
        size_t g = (qrowg + r) * QKV_LD + hcol + ch * 8;
        uint32_t sa = sb + (uint32_t)(r * FSTR + ch * 8) * 2;
        CP_ASYNC16(sa, qkvhi + g);
        CP_ASYNC16(sa + Q_ELEMS * 2, qkvlo + g);
    }
    CP_COMMIT();

    auto load_kv = [&](int kt, int s) {
        size_t krow = (size_t)(b * SS + kt * 64);
        uint32_t sbase = sb + (uint32_t)(2 * Q_ELEMS + s * KV_STAGE) * 2;
#pragma unroll
        for (int i = 0; i < 2; i++) {
            int idx = tid + i * 256;
            int r = idx >> 3, ch = idx & 7;
            size_t g = (krow + r) * QKV_LD + DDIM + hcol + ch * 8;
            uint32_t so = (uint32_t)(r * FSTR + ch * 8) * 2;
            CP_ASYNC16(sbase + so,                  qkvhi + g);
            CP_ASYNC16(sbase + KV_ARR * 2 + so,     qkvlo + g);
            CP_ASYNC16(sbase + 2 * KV_ARR * 2 + so, qkvhi + g + DDIM);
            CP_ASYNC16(sbase + 3 * KV_ARR * 2 + so, qkvlo + g + DDIM);
        }
        CP_COMMIT();
    };

    load_kv(0, 0);
    CP_WAIT1();          // Q group done
    __syncthreads();

    // Hoist Q fragments into registers
    uint32_t qh[4][4], ql[4][4];
#pragma unroll
    for (int ks = 0; ks < 4; ks++) {
        uint32_t off = (uint32_t)((wid * 16 + lrow) * FSTR + ks * 16 + lkb) * 2;
        LDSM_X4(qh[ks][0], qh[ks][1], qh[ks][2], qh[ks][3], sb + off);
        LDSM_X4(ql[ks][0], ql[ks][1], ql[ks][2], ql[ks][3], sb + Q_ELEMS * 2 + off);
    }

    float O[8][4];
#pragma unroll
    for (int ht = 0; ht < 8; ht++)
#pragma unroll
        for (int j = 0; j < 4; j++) O[ht][j] = 0.f;
    float m0 = -CUDART_INF_F, m1 = -CUDART_INF_F, l0 = 0.f, l1 = 0.f;

    const int qr0 = qt * 128 + wid * 16 + (lane >> 2);   // lane's first row
    const int ktmax = 2 * qt + 1;

    for (int kt = 0; kt <= ktmax; kt++) {
        const int s = kt & 1;
        if (kt < ktmax) { load_kv(kt + 1, s ^ 1); CP_WAIT1(); }
        else            { CP_WAIT0(); }
        __syncthreads();
        const uint32_t kvb = sb + (uint32_t)(2 * Q_ELEMS + s * KV_STAGE) * 2;

        // ---- scores: c[nt] = m16n8 tiles over 64 keys ----
        float c[8][4];
#pragma unroll
        for (int nt = 0; nt < 8; nt++)
#pragma unroll
            for (int j = 0; j < 4; j++) c[nt][j] = 0.f;

#pragma unroll
        for (int ks = 0; ks < 4; ks++) {
#pragma unroll
            for (int bp = 0; bp < 4; bp++) {
                uint32_t off = (uint32_t)((bp * 16 + lrow) * FSTR + ks * 16 + lkb) * 2;
                uint32_t k0, k1, k2, k3, e0, e1, e2, e3;
                LDSM_X4(k0, k1, k2, k3, kvb + off);
                LDSM_X4(e0, e1, e2, e3, kvb + KV_ARR * 2 + off);
                MMA_BF16(c[bp * 2], qh[ks][0], qh[ks][1], qh[ks][2], qh[ks][3], k0, k2);
                MMA_BF16(c[bp * 2], qh[ks][0], qh[ks][1], qh[ks][2], qh[ks][3], e0, e2);
                MMA_BF16(c[bp * 2], ql[ks][0], ql[ks][1], ql[ks][2], ql[ks][3], k0, k2);
                MMA_BF16(c[bp * 2 + 1], qh[ks][0], qh[ks][1], qh[ks][2], qh[ks][3], k1, k3);
                MMA_BF16(c[bp * 2 + 1], qh[ks][0], qh[ks][1], qh[ks][2], qh[ks][3], e1, e3);
                MMA_BF16(c[bp * 2 + 1], ql[ks][0], ql[ks][1], ql[ks][2], ql[ks][3], k1, k3);
            }
        }

        // ---- causal mask (only near-diagonal tiles) ----
        if (kt * 64 + 63 > qt * 128 + wid * 16) {
#pragma unroll
            for (int nt = 0; nt < 8; nt++) {
                int kc = kt * 64 + nt * 8 + (lane & 3) * 2;
                if (kc     > qr0)     c[nt][0] = -CUDART_INF_F;
                if (kc + 1 > qr0)     c[nt][1] = -CUDART_INF_F;
                if (kc     > qr0 + 8) c[nt][2] = -CUDART_INF_F;
                if (kc + 1 > qr0 + 8) c[nt][3] = -CUDART_INF_F;
            }
        }

        // ---- online softmax (rows r, r+8; reduce across quad lanes) ----
        float mt0 = -CUDART_INF_F, mt1 = -CUDART_INF_F;
#pragma unroll
        for (int nt = 0; nt < 8; nt++) {
            mt0 = fmaxf(mt0, fmaxf(c[nt][0], c[nt][1]));
            mt1 = fmaxf(mt1, fmaxf(c[nt][2], c[nt][3]));
        }
        mt0 = fmaxf(mt0, __shfl_xor_sync(0xffffffffu, mt0, 1));
        mt0 = fmaxf(mt0, __shfl_xor_sync(0xffffffffu, mt0, 2));
        mt1 = fmaxf(mt1, __shfl_xor_sync(0xffffffffu, mt1, 1));
        mt1 = fmaxf(mt1, __shfl_xor_sync(0xffffffffu, mt1, 2));

        float mn0 = fmaxf(m0, mt0), mn1 = fmaxf(m1, mt1);
        float f0 = __expf(m0 - mn0), f1 = __expf(m1 - mn1);
        float s0 = 0.f, s1 = 0.f;
        uint32_t pa0[8], pa1[8], pb0[8], pb1[8];    // hi/lo packs rows r, r+8
#pragma unroll
        for (int nt = 0; nt < 8; nt++) {
            float p0 = __expf(c[nt][0] - mn0), p1 = __expf(c[nt][1] - mn0);
            float p2 = __expf(c[nt][2] - mn1), p3 = __expf(c[nt][3] - mn1);
            s0 += p0 + p1; s1 += p2 + p3;
            pa0[nt] = pack_bf2(p0, p1); pb0[nt] = pack_lo2(p0, p1, pa0[nt]);
            pa1[nt] = pack_bf2(p2, p3); pb1[nt] = pack_lo2(p2, p3, pa1[nt]);
        }
        s0 += __shfl_xor_sync(0xffffffffu, s0, 1);
        s0 += __shfl_xor_sync(0xffffffffu, s0, 2);
        s1 += __shfl_xor_sync(0xffffffffu, s1, 1);
        s1 += __shfl_xor_sync(0xffffffffu, s1, 2);
        l0 = l0 * f0 + s0;  m0 = mn0;
        l1 = l1 * f1 + s1;  m1 = mn1;
#pragma unroll
        for (int ht = 0; ht < 8; ht++) {
            O[ht][0] *= f0; O[ht][1] *= f0;
            O[ht][2] *= f1; O[ht][3] *= f1;
        }

        // ---- PV: O += (Phi+Plo) @ (Vhi+Vlo), V via ldmatrix.trans ----
#pragma unroll
        for (int ksi = 0; ksi < 4; ksi++) {
            uint32_t a0 = pa0[2 * ksi],     a1 = pa1[2 * ksi];
            uint32_t a2 = pa0[2 * ksi + 1], a3 = pa1[2 * ksi + 1];
            uint32_t g0 = pb0[2 * ksi],     g1 = pb1[2 * ksi];
            uint32_t g2 = pb0[2 * ksi + 1], g3 = pb1[2 * ksi + 1];
#pragma unroll
            for (int bp = 0; bp < 4; bp++) {
                uint32_t off = (uint32_t)((ksi * 16 + lrow) * FSTR + bp * 16 + lkb) * 2;
                uint32_t v0, v1, v2, v3, w0, w1, w2, w3;
                LDSM_X4_T(v0, v1, v2, v3, kvb + 2 * KV_ARR * 2 + off);
                LDSM_X4_T(w0, w1, w2, w3, kvb + 3 * KV_ARR * 2 + off);
                // trans mapping: n-tile bp*2 -> (r0,r1); bp*2+1 -> (r2,r3)
                MMA_BF16(O[bp * 2], a0, a1, a2, a3, v0, v1);
                MMA_BF16(O[bp * 2], a0, a1, a2, a3, w0, w1);
                MMA_BF16(O[bp * 2], g0, g1, g2, g3, v0, v1);
                MMA_BF16(O[bp * 2 + 1], a0, a1, a2, a3, v2, v3);
                MMA_BF16(O[bp * 2 + 1], a0, a1, a2, a3, w2, w3);
                MMA_BF16(O[bp * 2 + 1], g0, g1, g2, g3, v2, v3);
            }
        }
        __syncthreads();   // done with buf before it is refilled
    }

    // ---- epilogue: normalize, split hi/lo, store ----
    float i0 = 1.f / l0, i1 = 1.f / l1;
    size_t r0g = qrowg + wid * 16 + (lane >> 2);
    size_t r1g = r0g + 8;
    int cb = hcol + (lane & 3) * 2;
#pragma unroll
    for (int ht = 0; ht < 8; ht++) {
        int col = cb + ht * 8;
        float v0 = O[ht][0] * i0, v1 = O[ht][1] * i0;
        float v2 = O[ht][2] * i1, v3 = O[ht][3] * i1;
        uint32_t h01 = pack_bf2(v0, v1);
        *(uint32_t*)&ohi[r0g * DDIM + col] = h01;
        *(uint32_t*)&olo[r0g * DDIM + col] = pack_lo2(v0, v1, h01);
        uint32_t h23 = pack_bf2(v2, v3);
        *(uint32_t*)&ohi[r1g * DDIM + col] = h23;
        *(uint32_t*)&olo[r1g * DDIM + col] = pack_lo2(v2, v3, h23);
    }
}

// ---------------------------------------------------------------------------
extern "C" void kernel_launch(void* const* d_in, const int* in_sizes, int n_in,
                              void* d_out, int out_size)
{
    const float* x      = (const float*)d_in[0];
    const float* w_attn = (const float*)d_in[1];
    const float* b_attn = (const float*)d_in[2];
    const float* w_proj = (const float*)d_in[3];
    const float* b_proj = (const float*)d_in[4];
    float* out = (float*)d_out;

    __nv_bfloat16 *qkvhi, *qkvlo, *xhi, *xlo, *w1hi, *w1lo, *w2hi, *w2lo, *ahi, *alo;
    cudaGetSymbolAddress((void**)&qkvhi, g_qkvhi);
    cudaGetSymbolAddress((void**)&qkvlo, g_qkvlo);
    cudaGetSymbolAddress((void**)&xhi,  g_xhi);
    cudaGetSymbolAddress((void**)&xlo,  g_xlo);
    cudaGetSymbolAddress((void**)&w1hi, g_w1hi);
    cudaGetSymbolAddress((void**)&w1lo, g_w1lo);
    cudaGetSymbolAddress((void**)&w2hi, g_w2hi);
    cudaGetSymbolAddress((void**)&w2lo, g_w2lo);
    cudaGetSymbolAddress((void**)&ahi,  g_ahi);
    cudaGetSymbolAddress((void**)&alo,  g_alo);

    cudaFuncSetAttribute(hmma_gemm<0>,
                         cudaFuncAttributeMaxDynamicSharedMemorySize, HMMA_SMEM);
    cudaFuncSetAttribute(hmma_gemm<1>,
                         cudaFuncAttributeMaxDynamicSharedMemorySize, HMMA_SMEM);
    cudaFuncSetAttribute(flash_hmma,
                         cudaFuncAttributeMaxDynamicSharedMemorySize, FL_SMEM);

    // Prep
    split_plain<<<1024, 256>>>(x, xhi, xlo, MM * DDIM / 4);
    transpose_split<<<dim3(QKV_LD / 32, DDIM / 32), dim3(32, 8)>>>(w_attn, w1hi, w1lo, DDIM, QKV_LD);
    transpose_split<<<dim3(DDIM / 32, DDIM / 32),  dim3(32, 8)>>>(w_proj, w2hi, w2lo, DDIM, DDIM);

    // 1) QKV (bf16 hi/lo out, Q pre-scaled)
    hmma_gemm<1><<<dim3(QKV_LD / 128, MM / 128), 256, HMMA_SMEM>>>(
        xhi, xlo, w1hi, w1lo, b_attn, nullptr, qkvhi, qkvlo, DDIM, QKV_LD);

    // 2) HMMA flash attention -> bf16 hi/lo attention output
    flash_hmma<<<dim3(SS / 128, HH, BB), 256, FL_SMEM>>>(qkvhi, qkvlo, ahi, alo);

    // 3) proj (fp32 out)
    hmma_gemm<0><<<dim3(DDIM / 128, MM / 128), 256, HMMA_SMEM>>>(
        ahi, alo, w2hi, w2lo, b_proj, out, nullptr, nullptr, DDIM, DDIM);
}

// round 5
// speedup vs baseline: 2.9005x; 1.0815x over previous
#include <cuda_runtime.h>
#include <cuda_bf16.h>
#include <math_constants.h>
#include <cstdint>

#define BB 2
#define SS 2048
#define DDIM 1024
#define HH 16
#define HDIM 64
#define MM (BB*SS)          // 4096 rows
#define QKV_LD 3072         // 3*D

// ---------------------------------------------------------------------------
// Scratch (device globals: allowed; runtime allocs are not)
// ---------------------------------------------------------------------------
__device__ __nv_bfloat16 g_qkvhi[(size_t)MM * QKV_LD];  // QKV hi (Q pre-scaled)
__device__ __nv_bfloat16 g_qkvlo[(size_t)MM * QKV_LD];  // QKV lo
__device__ __nv_bfloat16 g_xhi[(size_t)MM * DDIM];      // x split
__device__ __nv_bfloat16 g_xlo[(size_t)MM * DDIM];
__device__ __nv_bfloat16 g_w1hi[(size_t)QKV_LD * DDIM]; // w_attn^T [3072,1024]
__device__ __nv_bfloat16 g_w1lo[(size_t)QKV_LD * DDIM];
__device__ __nv_bfloat16 g_w2hi[(size_t)DDIM * DDIM];   // w_proj^T [1024,1024]
__device__ __nv_bfloat16 g_w2lo[(size_t)DDIM * DDIM];
__device__ __nv_bfloat16 g_ahi[(size_t)MM * DDIM];      // attention out split
__device__ __nv_bfloat16 g_alo[(size_t)MM * DDIM];

// ---------------------------------------------------------------------------
// Portable PTX helpers (NO tcgen05 — harness PTX targets plain compute_103)
// ---------------------------------------------------------------------------
__device__ __forceinline__ uint32_t smem_u32(const void* p) {
    uint32_t a;
    asm("{ .reg .u64 t; cvta.to.shared.u64 t, %1; cvt.u32.u64 %0, t; }"
        : "=r"(a) : "l"(p));
    return a;
}

#define CP_ASYNC16(sa, gp) \
    asm volatile("cp.async.cg.shared.global [%0], [%1], 16;" :: "r"(sa), "l"(gp))
#define CP_COMMIT() asm volatile("cp.async.commit_group;" ::: "memory")
#define CP_WAIT1()  asm volatile("cp.async.wait_group 1;" ::: "memory")
#define CP_WAIT0()  asm volatile("cp.async.wait_group 0;" ::: "memory")

#define LDSM_X4(r0, r1, r2, r3, addr) \
    asm volatile("ldmatrix.sync.aligned.m8n8.x4.shared.b16 {%0,%1,%2,%3}, [%4];" \
        : "=r"(r0), "=r"(r1), "=r"(r2), "=r"(r3) : "r"(addr))

#define LDSM_X4_T(r0, r1, r2, r3, addr) \
    asm volatile("ldmatrix.sync.aligned.m8n8.x4.trans.shared.b16 {%0,%1,%2,%3}, [%4];" \
        : "=r"(r0), "=r"(r1), "=r"(r2), "=r"(r3) : "r"(addr))

#define MMA_BF16(c, a0, a1, a2, a3, b0, b1) \
    asm volatile("mma.sync.aligned.m16n8k16.row.col.f32.bf16.bf16.f32 " \
        "{%0,%1,%2,%3}, {%4,%5,%6,%7}, {%8,%9}, {%0,%1,%2,%3};" \
        : "+f"((c)[0]), "+f"((c)[1]), "+f"((c)[2]), "+f"((c)[3]) \
        : "r"(a0), "r"(a1), "r"(a2), "r"(a3), "r"(b0), "r"(b1))

__device__ __forceinline__ uint32_t pack_bf2(float a, float b) {
    __nv_bfloat162 t = __halves2bfloat162(__float2bfloat16(a), __float2bfloat16(b));
    return *(uint32_t*)&t;
}
__device__ __forceinline__ uint32_t pack_lo2(float a, float b, uint32_t hipack) {
    __nv_bfloat162 h = *(__nv_bfloat162*)&hipack;
    return pack_bf2(a - __bfloat162float(h.x), b - __bfloat162float(h.y));
}

// ---------------------------------------------------------------------------
// Prep: fp32 -> (bf16 hi, bf16 lo) split
// ---------------------------------------------------------------------------
__global__ void split_plain(const float* __restrict__ s,
                            __nv_bfloat16* __restrict__ hi,
                            __nv_bfloat16* __restrict__ lo, int n4)
{
    for (int i = blockIdx.x * blockDim.x + threadIdx.x; i < n4;
         i += gridDim.x * blockDim.x) {
        float4 v = ((const float4*)s)[i];
        uint32_t h0 = pack_bf2(v.x, v.y), h1 = pack_bf2(v.z, v.w);
        ((uint32_t*)hi)[2 * i]     = h0;
        ((uint32_t*)hi)[2 * i + 1] = h1;
        ((uint32_t*)lo)[2 * i]     = pack_lo2(v.x, v.y, h0);
        ((uint32_t*)lo)[2 * i + 1] = pack_lo2(v.z, v.w, h1);
    }
}

// Prep: transpose W[K,N] -> WT[N,K] with bf16 hi/lo split.
__global__ void transpose_split(const float* __restrict__ W,
                                __nv_bfloat16* __restrict__ hi,
                                __nv_bfloat16* __restrict__ lo, int K, int N)
{
    __shared__ float t[32][33];
    int n0 = blockIdx.x * 32, k0 = blockIdx.y * 32;
    int tx = threadIdx.x, ty = threadIdx.y;
#pragma unroll
    for (int i = 0; i < 32; i += 8)
        t[ty + i][tx] = W[(size_t)(k0 + ty + i) * N + n0 + tx];
    __syncthreads();
#pragma unroll
    for (int i = 0; i < 32; i += 8) {
        float v = t[tx][ty + i];
        __nv_bfloat16 h = __float2bfloat16(v);
        size_t o = (size_t)(n0 + ty + i) * K + k0 + tx;
        hi[o] = h;
        lo[o] = __float2bfloat16(v - __bfloat162float(h));
    }
}

// ---------------------------------------------------------------------------
// HMMA split-bf16 GEMM + bias.
// MODE 0: fp32 C out.  MODE 1: bf16 hi/lo out, Q columns (col<DDIM) x0.125.
// 2 CTAs/SM: launch_bounds(256,2) caps regs at 128; B fragments loaded
// in-loop to keep live set ~110 regs.
// ---------------------------------------------------------------------------
#define SAS 40
#define ARR_ELEMS (128 * SAS)
#define STAGE_ELEMS (4 * ARR_ELEMS)
#define HMMA_SMEM (2 * STAGE_ELEMS * 2)   // 81920 B -> 2 CTAs/SM (160KB/228KB)

template<int MODE>
__global__ __launch_bounds__(256, 2)
void hmma_gemm(const __nv_bfloat16* __restrict__ Ahi, const __nv_bfloat16* __restrict__ Alo,
               const __nv_bfloat16* __restrict__ Bhi, const __nv_bfloat16* __restrict__ Blo,
               const float* __restrict__ bias, float* __restrict__ C,
               __nv_bfloat16* __restrict__ Chi, __nv_bfloat16* __restrict__ Clo,
               int K, int N)
{
    extern __shared__ __align__(16) char smraw[];
    const uint32_t sb = smem_u32(smraw);

    const int tid = threadIdx.x;
    const int wid = tid >> 5, lane = tid & 31;
    const int m0 = blockIdx.y * 128, n0 = blockIdx.x * 128;
    const int warp_m = wid & 3;
    const int warp_n = wid >> 2;

    const __nv_bfloat16* arrs[4] = {Ahi, Alo, Bhi, Blo};

    float c[2][8][4];
#pragma unroll
    for (int mi = 0; mi < 2; mi++)
#pragma unroll
        for (int nt = 0; nt < 8; nt++)
#pragma unroll
            for (int j = 0; j < 4; j++) c[mi][nt][j] = 0.f;

    const int nkt = K / 32;

    auto load_stage = [&](int kt, int buf) {
        const int k0 = kt * 32;
        const uint32_t sbase = sb + (uint32_t)buf * STAGE_ELEMS * 2;
#pragma unroll
        for (int arr = 0; arr < 4; arr++) {
            const __nv_bfloat16* P = arrs[arr];
            const int rowbase = (arr < 2) ? m0 : n0;
#pragma unroll
            for (int i = 0; i < 2; i++) {
                int idx = tid + i * 256;
                int r = idx >> 2, ch = idx & 3;
                const __nv_bfloat16* gp = P + (size_t)(rowbase + r) * K + k0 + ch * 8;
                uint32_t sa = sbase + (uint32_t)(arr * ARR_ELEMS + r * SAS + ch * 8) * 2;
                CP_ASYNC16(sa, gp);
            }
        }
        CP_COMMIT();
    };

    load_stage(0, 0);

    const int lrow = lane & 15;
    const int lkb  = (lane >> 4) * 8;

    for (int kt = 0; kt < nkt; kt++) {
        const int buf = kt & 1;
        if (kt + 1 < nkt) { load_stage(kt + 1, (kt + 1) & 1); CP_WAIT1(); }
        else              { CP_WAIT0(); }
        __syncthreads();

        const uint32_t sbase = sb + (uint32_t)buf * STAGE_ELEMS * 2;
        const uint32_t aRow = warp_m * 32;
        const uint32_t bRow = warp_n * 64;

#pragma unroll
        for (int ks = 0; ks < 2; ks++) {
            const int kcol = ks * 16 + lkb;
            uint32_t ah[2][4], al[2][4];
#pragma unroll
            for (int mi = 0; mi < 2; mi++) {
                uint32_t off = (uint32_t)((aRow + mi * 16 + lrow) * SAS + kcol) * 2;
                LDSM_X4(ah[mi][0], ah[mi][1], ah[mi][2], ah[mi][3],
                        sbase + 0 * ARR_ELEMS * 2 + off);
                LDSM_X4(al[mi][0], al[mi][1], al[mi][2], al[mi][3],
                        sbase + 1 * ARR_ELEMS * 2 + off);
            }
#pragma unroll
            for (int np = 0; np < 4; np++) {
                uint32_t off = (uint32_t)((bRow + np * 16 + lrow) * SAS + kcol) * 2;
                uint32_t bh[4], bl[4];
                LDSM_X4(bh[0], bh[1], bh[2], bh[3],
                        sbase + 2 * ARR_ELEMS * 2 + off);
                LDSM_X4(bl[0], bl[1], bl[2], bl[3],
                        sbase + 3 * ARR_ELEMS * 2 + off);
#pragma unroll
                for (int mi = 0; mi < 2; mi++) {
#pragma unroll
                    for (int hf = 0; hf < 2; hf++) {
                        const int nt = np * 2 + hf;
                        MMA_BF16(c[mi][nt], ah[mi][0], ah[mi][1], ah[mi][2], ah[mi][3],
                                 bh[hf], bh[2 + hf]);
                        MMA_BF16(c[mi][nt], ah[mi][0], ah[mi][1], ah[mi][2], ah[mi][3],
                                 bl[hf], bl[2 + hf]);
                        MMA_BF16(c[mi][nt], al[mi][0], al[mi][1], al[mi][2], al[mi][3],
                                 bh[hf], bh[2 + hf]);
                    }
                }
            }
        }
        __syncthreads();
    }

    // Epilogue
#pragma unroll
    for (int mi = 0; mi < 2; mi++) {
        int r0 = m0 + warp_m * 32 + mi * 16 + (lane >> 2);
        int r1 = r0 + 8;
#pragma unroll
        for (int nt = 0; nt < 8; nt++) {
            int col = n0 + warp_n * 64 + nt * 8 + (lane & 3) * 2;
            float b0 = bias[col], b1 = bias[col + 1];
            float v00 = c[mi][nt][0] + b0, v01 = c[mi][nt][1] + b1;
            float v10 = c[mi][nt][2] + b0, v11 = c[mi][nt][3] + b1;
            if (MODE == 0) {
                *(float2*)&C[(size_t)r0 * N + col] = make_float2(v00, v01);
                *(float2*)&C[(size_t)r1 * N + col] = make_float2(v10, v11);
            } else {
                if (col < DDIM) {   // Q columns: fold 1/sqrt(hd) (exact in bf16)
                    v00 *= 0.125f; v01 *= 0.125f; v10 *= 0.125f; v11 *= 0.125f;
                }
                uint32_t h0 = pack_bf2(v00, v01);
                uint32_t h1 = pack_bf2(v10, v11);
                *(uint32_t*)&Chi[(size_t)r0 * N + col] = h0;
                *(uint32_t*)&Clo[(size_t)r0 * N + col] = pack_lo2(v00, v01, h0);
                *(uint32_t*)&Chi[(size_t)r1 * N + col] = h1;
                *(uint32_t*)&Clo[(size_t)r1 * N + col] = pack_lo2(v10, v11, h1);
            }
        }
    }
}

// ---------------------------------------------------------------------------
// HMMA flash attention, causal, split-bf16 (3-term) for QK^T and PV.
// Grid (16, H, B), 256 threads = 8 warps, warp = 16 q-rows.
// ---------------------------------------------------------------------------
#define FSTR 72
#define Q_ELEMS (128 * FSTR)
#define KV_ARR (64 * FSTR)
#define KV_STAGE (4 * KV_ARR)
#define FL_SMEM ((2 * Q_ELEMS + 2 * KV_STAGE) * 2)   // 110592 bytes

__global__ __launch_bounds__(256, 1)
void flash_hmma(const __nv_bfloat16* __restrict__ qkvhi,
                const __nv_bfloat16* __restrict__ qkvlo,
                __nv_bfloat16* __restrict__ ohi,
                __nv_bfloat16* __restrict__ olo)
{
    extern __shared__ __align__(16) char smraw[];
    const uint32_t sb = smem_u32(smraw);
    const int tid = threadIdx.x, wid = tid >> 5, lane = tid & 31;
    const int qt = gridDim.x - 1 - blockIdx.x;   // big tiles first
    const int h = blockIdx.y, b = blockIdx.z;
    const size_t qrowg = (size_t)(b * SS + qt * 128);
    const int hcol = h * HDIM;
    const int lrow = lane & 15, lkb = (lane >> 4) * 8;

    // Q tile hi/lo -> smem (group A)
#pragma unroll
    for (int i = 0; i < 4; i++) {
        int idx = tid + i * 256;
        int r = idx >> 3, ch = idx & 7;
        size_t g = (qrowg + r) * QKV_LD + hcol + ch * 8;
        uint32_t sa = sb + (uint32_t)(r * FSTR + ch * 8) * 2;
        CP_ASYNC16(sa, qkvhi + g);
        CP_ASYNC16(sa + Q_ELEMS * 2, qkvlo + g);
    }
    CP_COMMIT();

    auto load_kv = [&](int kt, int s) {
        size_t krow = (size_t)(b * SS + kt * 64);
        uint32_t sbase = sb + (uint32_t)(2 * Q_ELEMS + s * KV_STAGE) * 2;
#pragma unroll
        for (int i = 0; i < 2; i++) {
            int idx = tid + i * 256;
            int r = idx >> 3, ch = idx & 7;
            size_t g = (krow + r) * QKV_LD + DDIM + hcol + ch * 8;
            uint32_t so = (uint32_t)(r * FSTR + ch * 8) * 2;
            CP_ASYNC16(sbase + so,                  qkvhi + g);
            CP_ASYNC16(sbase + KV_ARR * 2 + so,     qkvlo + g);
            CP_ASYNC16(sbase + 2 * KV_ARR * 2 + so, qkvhi + g + DDIM);
            CP_ASYNC16(sbase + 3 * KV_ARR * 2 + so, qkvlo + g + DDIM);
        }
        CP_COMMIT();
    };

    load_kv(0, 0);
    CP_WAIT1();          // Q group done
    __syncthreads();

    // Hoist Q fragments into registers
    uint32_t qh[4][4], ql[4][4];
#pragma unroll
    for (int ks = 0; ks < 4; ks++) {
        uint32_t off = (uint32_t)((wid * 16 + lrow) * FSTR + ks * 16 + lkb) * 2;
        LDSM_X4(qh[ks][0], qh[ks][1], qh[ks][2], qh[ks][3], sb + off);
        LDSM_X4(ql[ks][0], ql[ks][1], ql[ks][2], ql[ks][3], sb + Q_ELEMS * 2 + off);
    }

    float O[8][4];
#pragma unroll
    for (int ht = 0; ht < 8; ht++)
#pragma unroll
        for (int j = 0; j < 4; j++) O[ht][j] = 0.f;
    float m0 = -CUDART_INF_F, m1 = -CUDART_INF_F, l0 = 0.f, l1 = 0.f;

    const int qr0 = qt * 128 + wid * 16 + (lane >> 2);
    const int ktmax = 2 * qt + 1;

    for (int kt = 0; kt <= ktmax; kt++) {
        const int s = kt & 1;
        if (kt < ktmax) { load_kv(kt + 1, s ^ 1); CP_WAIT1(); }
        else            { CP_WAIT0(); }
        __syncthreads();
        const uint32_t kvb = sb + (uint32_t)(2 * Q_ELEMS + s * KV_STAGE) * 2;

        // ---- scores ----
        float c[8][4];
#pragma unroll
        for (int nt = 0; nt < 8; nt++)
#pragma unroll
            for (int j = 0; j < 4; j++) c[nt][j] = 0.f;

#pragma unroll
        for (int ks = 0; ks < 4; ks++) {
#pragma unroll
            for (int bp = 0; bp < 4; bp++) {
                uint32_t off = (uint32_t)((bp * 16 + lrow) * FSTR + ks * 16 + lkb) * 2;
                uint32_t k0, k1, k2, k3, e0, e1, e2, e3;
                LDSM_X4(k0, k1, k2, k3, kvb + off);
                LDSM_X4(e0, e1, e2, e3, kvb + KV_ARR * 2 + off);
                MMA_BF16(c[bp * 2], qh[ks][0], qh[ks][1], qh[ks][2], qh[ks][3], k0, k2);
                MMA_BF16(c[bp * 2], qh[ks][0], qh[ks][1], qh[ks][2], qh[ks][3], e0, e2);
                MMA_BF16(c[bp * 2], ql[ks][0], ql[ks][1], ql[ks][2], ql[ks][3], k0, k2);
                MMA_BF16(c[bp * 2 + 1], qh[ks][0], qh[ks][1], qh[ks][2], qh[ks][3], k1, k3);
                MMA_BF16(c[bp * 2 + 1], qh[ks][0], qh[ks][1], qh[ks][2], qh[ks][3], e1, e3);
                MMA_BF16(c[bp * 2 + 1], ql[ks][0], ql[ks][1], ql[ks][2], ql[ks][3], k1, k3);
            }
        }

        // ---- causal mask ----
        if (kt * 64 + 63 > qt * 128 + wid * 16) {
#pragma unroll
            for (int nt = 0; nt < 8; nt++) {
                int kc = kt * 64 + nt * 8 + (lane & 3) * 2;
                if (kc     > qr0)     c[nt][0] = -CUDART_INF_F;
                if (kc + 1 > qr0)     c[nt][1] = -CUDART_INF_F;
                if (kc     > qr0 + 8) c[nt][2] = -CUDART_INF_F;
                if (kc + 1 > qr0 + 8) c[nt][3] = -CUDART_INF_F;
            }
        }

        // ---- online softmax ----
        float mt0 = -CUDART_INF_F, mt1 = -CUDART_INF_F;
#pragma unroll
        for (int nt = 0; nt < 8; nt++) {
            mt0 = fmaxf(mt0, fmaxf(c[nt][0], c[nt][1]));
            mt1 = fmaxf(mt1, fmaxf(c[nt][2], c[nt][3]));
        }
        mt0 = fmaxf(mt0, __shfl_xor_sync(0xffffffffu, mt0, 1));
        mt0 = fmaxf(mt0, __shfl_xor_sync(0xffffffffu, mt0, 2));
        mt1 = fmaxf(mt1, __shfl_xor_sync(0xffffffffu, mt1, 1));
        mt1 = fmaxf(mt1, __shfl_xor_sync(0xffffffffu, mt1, 2));

        float mn0 = fmaxf(m0, mt0), mn1 = fmaxf(m1, mt1);
        float f0 = __expf(m0 - mn0), f1 = __expf(m1 - mn1);
        float s0 = 0.f, s1 = 0.f;
        uint32_t pa0[8], pa1[8], pb0[8], pb1[8];
#pragma unroll
        for (int nt = 0; nt < 8; nt++) {
            float p0 = __expf(c[nt][0] - mn0), p1 = __expf(c[nt][1] - mn0);
            float p2 = __expf(c[nt][2] - mn1), p3 = __expf(c[nt][3] - mn1);
            s0 += p0 + p1; s1 += p2 + p3;
            pa0[nt] = pack_bf2(p0, p1); pb0[nt] = pack_lo2(p0, p1, pa0[nt]);
            pa1[nt] = pack_bf2(p2, p3); pb1[nt] = pack_lo2(p2, p3, pa1[nt]);
        }
        s0 += __shfl_xor_sync(0xffffffffu, s0, 1);
        s0 += __shfl_xor_sync(0xffffffffu, s0, 2);
        s1 += __shfl_xor_sync(0xffffffffu, s1, 1);
        s1 += __shfl_xor_sync(0xffffffffu, s1, 2);
        l0 = l0 * f0 + s0;  m0 = mn0;
        l1 = l1 * f1 + s1;  m1 = mn1;
#pragma unroll
        for (int ht = 0; ht < 8; ht++) {
            O[ht][0] *= f0; O[ht][1] *= f0;
            O[ht][2] *= f1; O[ht][3] *= f1;
        }

        // ---- PV ----
#pragma unroll
        for (int ksi = 0; ksi < 4; ksi++) {
            uint32_t a0 = pa0[2 * ksi],     a1 = pa1[2 * ksi];
            uint32_t a2 = pa0[2 * ksi + 1], a3 = pa1[2 * ksi + 1];
            uint32_t g0 = pb0[2 * ksi],     g1 = pb1[2 * ksi];
            uint32_t g2 = pb0[2 * ksi + 1], g3 = pb1[2 * ksi + 1];
#pragma unroll
            for (int bp = 0; bp < 4; bp++) {
                uint32_t off = (uint32_t)((ksi * 16 + lrow) * FSTR + bp * 16 + lkb) * 2;
                uint32_t v0, v1, v2, v3, w0, w1, w2, w3;
                LDSM_X4_T(v0, v1, v2, v3, kvb + 2 * KV_ARR * 2 + off);
                LDSM_X4_T(w0, w1, w2, w3, kvb + 3 * KV_ARR * 2 + off);
                MMA_BF16(O[bp * 2], a0, a1, a2, a3, v0, v1);
                MMA_BF16(O[bp * 2], a0, a1, a2, a3, w0, w1);
                MMA_BF16(O[bp * 2], g0, g1, g2, g3, v0, v1);
                MMA_BF16(O[bp * 2 + 1], a0, a1, a2, a3, v2, v3);
                MMA_BF16(O[bp * 2 + 1], a0, a1, a2, a3, w2, w3);
                MMA_BF16(O[bp * 2 + 1], g0, g1, g2, g3, v2, v3);
            }
        }
        __syncthreads();
    }

    // ---- epilogue ----
    float i0 = 1.f / l0, i1 = 1.f / l1;
    size_t r0g = qrowg + wid * 16 + (lane >> 2);
    size_t r1g = r0g + 8;
    int cb = hcol + (lane & 3) * 2;
#pragma unroll
    for (int ht = 0; ht < 8; ht++) {
        int col = cb + ht * 8;
        float v0 = O[ht][0] * i0, v1 = O[ht][1] * i0;
        float v2 = O[ht][2] * i1, v3 = O[ht][3] * i1;
        uint32_t h01 = pack_bf2(v0, v1);
        *(uint32_t*)&ohi[r0g * DDIM + col] = h01;
        *(uint32_t*)&olo[r0g * DDIM + col] = pack_lo2(v0, v1, h01);
        uint32_t h23 = pack_bf2(v2, v3);
        *(uint32_t*)&ohi[r1g * DDIM + col] = h23;
        *(uint32_t*)&olo[r1g * DDIM + col] = pack_lo2(v2, v3, h23);
    }
}

// ---------------------------------------------------------------------------
extern "C" void kernel_launch(void* const* d_in, const int* in_sizes, int n_in,
                              void* d_out, int out_size)
{
    const float* x      = (const float*)d_in[0];
    const float* w_attn = (const float*)d_in[1];
    const float* b_attn = (const float*)d_in[2];
    const float* w_proj = (const float*)d_in[3];
    const float* b_proj = (const float*)d_in[4];
    float* out = (float*)d_out;

    __nv_bfloat16 *qkvhi, *qkvlo, *xhi, *xlo, *w1hi, *w1lo, *w2hi, *w2lo, *ahi, *alo;
    cudaGetSymbolAddress((void**)&qkvhi, g_qkvhi);
    cudaGetSymbolAddress((void**)&qkvlo, g_qkvlo);
    cudaGetSymbolAddress((void**)&xhi,  g_xhi);
    cudaGetSymbolAddress((void**)&xlo,  g_xlo);
    cudaGetSymbolAddress((void**)&w1hi, g_w1hi);
    cudaGetSymbolAddress((void**)&w1lo, g_w1lo);
    cudaGetSymbolAddress((void**)&w2hi, g_w2hi);
    cudaGetSymbolAddress((void**)&w2lo, g_w2lo);
    cudaGetSymbolAddress((void**)&ahi,  g_ahi);
    cudaGetSymbolAddress((void**)&alo,  g_alo);

    cudaFuncSetAttribute(hmma_gemm<0>,
                         cudaFuncAttributeMaxDynamicSharedMemorySize, HMMA_SMEM);
    cudaFuncSetAttribute(hmma_gemm<1>,
                         cudaFuncAttributeMaxDynamicSharedMemorySize, HMMA_SMEM);
    cudaFuncSetAttribute(flash_hmma,
                         cudaFuncAttributeMaxDynamicSharedMemorySize, FL_SMEM);

    // Prep
    split_plain<<<1024, 256>>>(x, xhi, xlo, MM * DDIM / 4);
    transpose_split<<<dim3(QKV_LD / 32, DDIM / 32), dim3(32, 8)>>>(w_attn, w1hi, w1lo, DDIM, QKV_LD);
    transpose_split<<<dim3(DDIM / 32, DDIM / 32),  dim3(32, 8)>>>(w_proj, w2hi, w2lo, DDIM, DDIM);

    // 1) QKV (bf16 hi/lo out, Q pre-scaled)
    hmma_gemm<1><<<dim3(QKV_LD / 128, MM / 128), 256, HMMA_SMEM>>>(
        xhi, xlo, w1hi, w1lo, b_attn, nullptr, qkvhi, qkvlo, DDIM, QKV_LD);

    // 2) HMMA flash attention -> bf16 hi/lo attention output
    flash_hmma<<<dim3(SS / 128, HH, BB), 256, FL_SMEM>>>(qkvhi, qkvlo, ahi, alo);

    // 3) proj (fp32 out)
    hmma_gemm<0><<<dim3(DDIM / 128, MM / 128), 256, HMMA_SMEM>>>(
        ahi, alo, w2hi, w2lo, b_proj, out, nullptr, nullptr, DDIM, DDIM);
}

// round 6
// speedup vs baseline: 3.2632x; 1.1251x over previous
#include <cuda_runtime.h>
#include <cuda_bf16.h>
#include <math_constants.h>
#include <cstdint>

#define BB 2
#define SS 2048
#define DDIM 1024
#define HH 16
#define HDIM 64
#define MM (BB*SS)          // 4096 rows
#define QKV_LD 3072         // 3*D

// ---------------------------------------------------------------------------
// Scratch (device globals: allowed; runtime allocs are not)
// ---------------------------------------------------------------------------
__device__ __nv_bfloat16 g_qkvhi[(size_t)MM * QKV_LD];  // QKV hi (Q pre-scaled)
__device__ __nv_bfloat16 g_qkvlo[(size_t)MM * QKV_LD];  // QKV lo
__device__ __nv_bfloat16 g_xhi[(size_t)MM * DDIM];      // x split
__device__ __nv_bfloat16 g_xlo[(size_t)MM * DDIM];
__device__ __nv_bfloat16 g_w1hi[(size_t)QKV_LD * DDIM]; // w_attn^T [3072,1024]
__device__ __nv_bfloat16 g_w1lo[(size_t)QKV_LD * DDIM];
__device__ __nv_bfloat16 g_w2hi[(size_t)DDIM * DDIM];   // w_proj^T [1024,1024]
__device__ __nv_bfloat16 g_w2lo[(size_t)DDIM * DDIM];
__device__ __nv_bfloat16 g_ahi[(size_t)MM * DDIM];      // attention out split
__device__ __nv_bfloat16 g_alo[(size_t)MM * DDIM];

// ---------------------------------------------------------------------------
// Portable PTX helpers (NO tcgen05 — harness PTX targets plain compute_103)
// ---------------------------------------------------------------------------
__device__ __forceinline__ uint32_t smem_u32(const void* p) {
    uint32_t a;
    asm("{ .reg .u64 t; cvta.to.shared.u64 t, %1; cvt.u32.u64 %0, t; }"
        : "=r"(a) : "l"(p));
    return a;
}

#define CP_ASYNC16(sa, gp) \
    asm volatile("cp.async.cg.shared.global [%0], [%1], 16;" :: "r"(sa), "l"(gp))
#define CP_COMMIT() asm volatile("cp.async.commit_group;" ::: "memory")
#define CP_WAIT1()  asm volatile("cp.async.wait_group 1;" ::: "memory")
#define CP_WAIT0()  asm volatile("cp.async.wait_group 0;" ::: "memory")

#define LDSM_X4(r0, r1, r2, r3, addr) \
    asm volatile("ldmatrix.sync.aligned.m8n8.x4.shared.b16 {%0,%1,%2,%3}, [%4];" \
        : "=r"(r0), "=r"(r1), "=r"(r2), "=r"(r3) : "r"(addr))

#define LDSM_X4_T(r0, r1, r2, r3, addr) \
    asm volatile("ldmatrix.sync.aligned.m8n8.x4.trans.shared.b16 {%0,%1,%2,%3}, [%4];" \
        : "=r"(r0), "=r"(r1), "=r"(r2), "=r"(r3) : "r"(addr))

#define MMA_BF16(c, a0, a1, a2, a3, b0, b1) \
    asm volatile("mma.sync.aligned.m16n8k16.row.col.f32.bf16.bf16.f32 " \
        "{%0,%1,%2,%3}, {%4,%5,%6,%7}, {%8,%9}, {%0,%1,%2,%3};" \
        : "+f"((c)[0]), "+f"((c)[1]), "+f"((c)[2]), "+f"((c)[3]) \
        : "r"(a0), "r"(a1), "r"(a2), "r"(a3), "r"(b0), "r"(b1))

__device__ __forceinline__ uint32_t pack_bf2(float a, float b) {
    __nv_bfloat162 t = __halves2bfloat162(__float2bfloat16(a), __float2bfloat16(b));
    return *(uint32_t*)&t;
}
__device__ __forceinline__ uint32_t pack_lo2(float a, float b, uint32_t hipack) {
    __nv_bfloat162 h = *(__nv_bfloat162*)&hipack;
    return pack_bf2(a - __bfloat162float(h.x), b - __bfloat162float(h.y));
}

// Swizzles: rows of 64B (GEMM, ch in 0..3) and 128B (flash, ch in 0..7).
// Chosen so every 8-lane ldmatrix/cp.async phase hits 8 distinct 16B bank-quads.
__device__ __forceinline__ uint32_t sw64(uint32_t r, uint32_t ch) {
    return r * 64 + ((ch ^ ((r + (r >> 2)) & 3)) << 4);
}
__device__ __forceinline__ uint32_t sw128(uint32_t r, uint32_t ch) {
    return r * 128 + ((ch ^ (r & 7)) << 4);
}

// ---------------------------------------------------------------------------
// Prep: fp32 -> (bf16 hi, bf16 lo) split
// ---------------------------------------------------------------------------
__global__ void split_plain(const float* __restrict__ s,
                            __nv_bfloat16* __restrict__ hi,
                            __nv_bfloat16* __restrict__ lo, int n4)
{
    for (int i = blockIdx.x * blockDim.x + threadIdx.x; i < n4;
         i += gridDim.x * blockDim.x) {
        float4 v = ((const float4*)s)[i];
        uint32_t h0 = pack_bf2(v.x, v.y), h1 = pack_bf2(v.z, v.w);
        ((uint32_t*)hi)[2 * i]     = h0;
        ((uint32_t*)hi)[2 * i + 1] = h1;
        ((uint32_t*)lo)[2 * i]     = pack_lo2(v.x, v.y, h0);
        ((uint32_t*)lo)[2 * i + 1] = pack_lo2(v.z, v.w, h1);
    }
}

// Prep: transpose W[K,N] -> WT[N,K] with bf16 hi/lo split.
__global__ void transpose_split(const float* __restrict__ W,
                                __nv_bfloat16* __restrict__ hi,
                                __nv_bfloat16* __restrict__ lo, int K, int N)
{
    __shared__ float t[32][33];
    int n0 = blockIdx.x * 32, k0 = blockIdx.y * 32;
    int tx = threadIdx.x, ty = threadIdx.y;
#pragma unroll
    for (int i = 0; i < 32; i += 8)
        t[ty + i][tx] = W[(size_t)(k0 + ty + i) * N + n0 + tx];
    __syncthreads();
#pragma unroll
    for (int i = 0; i < 32; i += 8) {
        float v = t[tx][ty + i];
        __nv_bfloat16 h = __float2bfloat16(v);
        size_t o = (size_t)(n0 + ty + i) * K + k0 + tx;
        hi[o] = h;
        lo[o] = __float2bfloat16(v - __bfloat162float(h));
    }
}

// ---------------------------------------------------------------------------
// HMMA split-bf16 GEMM + bias. 3-stage cp.async, 1 barrier/K-tile, XOR-swizzle.
// MODE 0: fp32 C out.  MODE 1: bf16 hi/lo out, Q columns (col<DDIM) x0.125.
// ---------------------------------------------------------------------------
#define GARR 8192                    // bytes per array (128 rows x 64B)
#define GSTAGE (4 * GARR)            // 32768
#define HMMA_SMEM (3 * GSTAGE)       // 98304 -> 2 CTAs/SM (192KB + regs cap)

template<int MODE>
__global__ __launch_bounds__(256, 2)
void hmma_gemm(const __nv_bfloat16* __restrict__ Ahi, const __nv_bfloat16* __restrict__ Alo,
               const __nv_bfloat16* __restrict__ Bhi, const __nv_bfloat16* __restrict__ Blo,
               const float* __restrict__ bias, float* __restrict__ C,
               __nv_bfloat16* __restrict__ Chi, __nv_bfloat16* __restrict__ Clo,
               int K, int N)
{
    extern __shared__ __align__(16) char smraw[];
    const uint32_t sb = smem_u32(smraw);

    const int tid = threadIdx.x;
    const int wid = tid >> 5, lane = tid & 31;
    const int m0 = blockIdx.y * 128, n0 = blockIdx.x * 128;
    const int warp_m = wid & 3;
    const int warp_n = wid >> 2;

    const __nv_bfloat16* arrs[4] = {Ahi, Alo, Bhi, Blo};

    float c[2][8][4];
#pragma unroll
    for (int mi = 0; mi < 2; mi++)
#pragma unroll
        for (int nt = 0; nt < 8; nt++)
#pragma unroll
            for (int j = 0; j < 4; j++) c[mi][nt][j] = 0.f;

    const int nkt = K / 32;

    auto load_stage = [&](int kt, int slot) {
        const int k0 = kt * 32;
        const uint32_t sbase = sb + (uint32_t)slot * GSTAGE;
#pragma unroll
        for (int arr = 0; arr < 4; arr++) {
            const __nv_bfloat16* P = arrs[arr];
            const int rowbase = (arr < 2) ? m0 : n0;
#pragma unroll
            for (int i = 0; i < 2; i++) {
                uint32_t idx = tid + i * 256;
                uint32_t r = idx >> 2, ch = idx & 3;
                const __nv_bfloat16* gp = P + (size_t)(rowbase + r) * K + k0 + ch * 8;
                CP_ASYNC16(sbase + arr * GARR + sw64(r, ch), gp);
            }
        }
        CP_COMMIT();
    };

    load_stage(0, 0);
    load_stage(1, 1);

    const uint32_t lrow = lane & 15;
    const uint32_t lch  = lane >> 4;     // 16B chunk parity within k16

    for (int kt = 0; kt < nkt; kt++) {
        if (kt + 2 < nkt) CP_WAIT1(); else CP_WAIT0();
        __syncthreads();

        const uint32_t sbase = sb + (uint32_t)(kt % 3) * GSTAGE;
        const uint32_t aRow = warp_m * 32;
        const uint32_t bRow = warp_n * 64;

#pragma unroll
        for (int ks = 0; ks < 2; ks++) {
            const uint32_t ch = ks * 2 + lch;
            uint32_t ah[2][4], al[2][4];
#pragma unroll
            for (int mi = 0; mi < 2; mi++) {
                uint32_t row = aRow + mi * 16 + lrow;
                uint32_t off = sw64(row, ch);
                LDSM_X4(ah[mi][0], ah[mi][1], ah[mi][2], ah[mi][3],
                        sbase + 0 * GARR + off);
                LDSM_X4(al[mi][0], al[mi][1], al[mi][2], al[mi][3],
                        sbase + 1 * GARR + off);
            }
#pragma unroll
            for (int np = 0; np < 4; np++) {
                uint32_t row = bRow + np * 16 + lrow;
                uint32_t off = sw64(row, ch);
                uint32_t bh[4], bl[4];
                LDSM_X4(bh[0], bh[1], bh[2], bh[3], sbase + 2 * GARR + off);
                LDSM_X4(bl[0], bl[1], bl[2], bl[3], sbase + 3 * GARR + off);
#pragma unroll
                for (int mi = 0; mi < 2; mi++) {
#pragma unroll
                    for (int hf = 0; hf < 2; hf++) {
                        const int nt = np * 2 + hf;
                        MMA_BF16(c[mi][nt], ah[mi][0], ah[mi][1], ah[mi][2], ah[mi][3],
                                 bh[hf], bh[2 + hf]);
                        MMA_BF16(c[mi][nt], ah[mi][0], ah[mi][1], ah[mi][2], ah[mi][3],
                                 bl[hf], bl[2 + hf]);
                        MMA_BF16(c[mi][nt], al[mi][0], al[mi][1], al[mi][2], al[mi][3],
                                 bh[hf], bh[2 + hf]);
                    }
                }
            }
        }

        if (kt + 2 < nkt) load_stage(kt + 2, (kt + 2) % 3);
    }

    // Epilogue
#pragma unroll
    for (int mi = 0; mi < 2; mi++) {
        int r0 = m0 + warp_m * 32 + mi * 16 + (lane >> 2);
        int r1 = r0 + 8;
#pragma unroll
        for (int nt = 0; nt < 8; nt++) {
            int col = n0 + warp_n * 64 + nt * 8 + (lane & 3) * 2;
            float b0 = bias[col], b1 = bias[col + 1];
            float v00 = c[mi][nt][0] + b0, v01 = c[mi][nt][1] + b1;
            float v10 = c[mi][nt][2] + b0, v11 = c[mi][nt][3] + b1;
            if (MODE == 0) {
                *(float2*)&C[(size_t)r0 * N + col] = make_float2(v00, v01);
                *(float2*)&C[(size_t)r1 * N + col] = make_float2(v10, v11);
            } else {
                if (col < DDIM) {   // Q columns: fold 1/sqrt(hd) (exact in bf16)
                    v00 *= 0.125f; v01 *= 0.125f; v10 *= 0.125f; v11 *= 0.125f;
                }
                uint32_t h0 = pack_bf2(v00, v01);
                uint32_t h1 = pack_bf2(v10, v11);
                *(uint32_t*)&Chi[(size_t)r0 * N + col] = h0;
                *(uint32_t*)&Clo[(size_t)r0 * N + col] = pack_lo2(v00, v01, h0);
                *(uint32_t*)&Chi[(size_t)r1 * N + col] = h1;
                *(uint32_t*)&Clo[(size_t)r1 * N + col] = pack_lo2(v10, v11, h1);
            }
        }
    }
}

// ---------------------------------------------------------------------------
// HMMA flash attention, causal, split-bf16. XOR-swizzle smem (96KB) ->
// 2 CTAs/SM; Q fragments reloaded per ks from smem to fit 128 regs.
// ---------------------------------------------------------------------------
#define FQARR (128 * 128)            // 16384 bytes per Q array
#define FKVARR (64 * 128)            // 8192 bytes per KV array
#define FKVSTAGE (4 * FKVARR)        // 32768
#define FL_SMEM (2 * FQARR + 2 * FKVSTAGE)   // 98304 bytes

__global__ __launch_bounds__(256, 2)
void flash_hmma(const __nv_bfloat16* __restrict__ qkvhi,
                const __nv_bfloat16* __restrict__ qkvlo,
                __nv_bfloat16* __restrict__ ohi,
                __nv_bfloat16* __restrict__ olo)
{
    extern __shared__ __align__(16) char smraw[];
    const uint32_t sb = smem_u32(smraw);
    const int tid = threadIdx.x, wid = tid >> 5, lane = tid & 31;
    const int qt = gridDim.x - 1 - blockIdx.x;   // big tiles first
    const int h = blockIdx.y, b = blockIdx.z;
    const size_t qrowg = (size_t)(b * SS + qt * 128);
    const int hcol = h * HDIM;
    const uint32_t lrow = lane & 15, lch = lane >> 4;

    // Q tile hi/lo -> smem (one commit group)
#pragma unroll
    for (int i = 0; i < 4; i++) {
        uint32_t idx = tid + i * 256;
        uint32_t r = idx >> 3, ch = idx & 7;
        size_t g = (qrowg + r) * QKV_LD + hcol + ch * 8;
        uint32_t sa = sb + sw128(r, ch);
        CP_ASYNC16(sa, qkvhi + g);
        CP_ASYNC16(sa + FQARR, qkvlo + g);
    }
    CP_COMMIT();

    auto load_kv = [&](int kt, int s) {
        size_t krow = (size_t)(b * SS + kt * 64);
        uint32_t sbase = sb + 2 * FQARR + (uint32_t)s * FKVSTAGE;
#pragma unroll
        for (int i = 0; i < 2; i++) {
            uint32_t idx = tid + i * 256;
            uint32_t r = idx >> 3, ch = idx & 7;
            size_t g = (krow + r) * QKV_LD + DDIM + hcol + ch * 8;
            uint32_t so = sw128(r, ch);
            CP_ASYNC16(sbase + so,               qkvhi + g);
            CP_ASYNC16(sbase + FKVARR + so,      qkvlo + g);
            CP_ASYNC16(sbase + 2 * FKVARR + so,  qkvhi + g + DDIM);
            CP_ASYNC16(sbase + 3 * FKVARR + so,  qkvlo + g + DDIM);
        }
        CP_COMMIT();
    };

    load_kv(0, 0);

    float O[8][4];
#pragma unroll
    for (int ht = 0; ht < 8; ht++)
#pragma unroll
        for (int j = 0; j < 4; j++) O[ht][j] = 0.f;
    float m0 = -CUDART_INF_F, m1 = -CUDART_INF_F, l0 = 0.f, l1 = 0.f;

    const int qr0 = qt * 128 + wid * 16 + (lane >> 2);
    const int ktmax = 2 * qt + 1;

    for (int kt = 0; kt <= ktmax; kt++) {
        const int s = kt & 1;
        if (kt < ktmax) { load_kv(kt + 1, s ^ 1); CP_WAIT1(); }
        else            { CP_WAIT0(); }
        __syncthreads();
        const uint32_t kvb = sb + 2 * FQARR + (uint32_t)s * FKVSTAGE;

        // ---- scores (Q frags reloaded per ks — conflict-free swizzled) ----
        float c[8][4];
#pragma unroll
        for (int nt = 0; nt < 8; nt++)
#pragma unroll
            for (int j = 0; j < 4; j++) c[nt][j] = 0.f;

#pragma unroll
        for (int ks = 0; ks < 4; ks++) {
            const uint32_t ch = ks * 2 + lch;
            uint32_t qrow = wid * 16 + lrow;
            uint32_t qoff = sw128(qrow, ch);
            uint32_t q0, q1, q2, q3, u0, u1, u2, u3;
            LDSM_X4(q0, q1, q2, q3, sb + qoff);
            LDSM_X4(u0, u1, u2, u3, sb + FQARR + qoff);
#pragma unroll
            for (int bp = 0; bp < 4; bp++) {
                uint32_t off = sw128(bp * 16 + lrow, ch);
                uint32_t k0, k1, k2, k3, e0, e1, e2, e3;
                LDSM_X4(k0, k1, k2, k3, kvb + off);
                LDSM_X4(e0, e1, e2, e3, kvb + FKVARR + off);
                MMA_BF16(c[bp * 2], q0, q1, q2, q3, k0, k2);
                MMA_BF16(c[bp * 2], q0, q1, q2, q3, e0, e2);
                MMA_BF16(c[bp * 2], u0, u1, u2, u3, k0, k2);
                MMA_BF16(c[bp * 2 + 1], q0, q1, q2, q3, k1, k3);
                MMA_BF16(c[bp * 2 + 1], q0, q1, q2, q3, e1, e3);
                MMA_BF16(c[bp * 2 + 1], u0, u1, u2, u3, k1, k3);
            }
        }

        // ---- causal mask ----
        if (kt * 64 + 63 > qt * 128 + wid * 16) {
#pragma unroll
            for (int nt = 0; nt < 8; nt++) {
                int kc = kt * 64 + nt * 8 + (lane & 3) * 2;
                if (kc     > qr0)     c[nt][0] = -CUDART_INF_F;
                if (kc + 1 > qr0)     c[nt][1] = -CUDART_INF_F;
                if (kc     > qr0 + 8) c[nt][2] = -CUDART_INF_F;
                if (kc + 1 > qr0 + 8) c[nt][3] = -CUDART_INF_F;
            }
        }

        // ---- online softmax ----
        float mt0 = -CUDART_INF_F, mt1 = -CUDART_INF_F;
#pragma unroll
        for (int nt = 0; nt < 8; nt++) {
            mt0 = fmaxf(mt0, fmaxf(c[nt][0], c[nt][1]));
            mt1 = fmaxf(mt1, fmaxf(c[nt][2], c[nt][3]));
        }
        mt0 = fmaxf(mt0, __shfl_xor_sync(0xffffffffu, mt0, 1));
        mt0 = fmaxf(mt0, __shfl_xor_sync(0xffffffffu, mt0, 2));
        mt1 = fmaxf(mt1, __shfl_xor_sync(0xffffffffu, mt1, 1));
        mt1 = fmaxf(mt1, __shfl_xor_sync(0xffffffffu, mt1, 2));

        float mn0 = fmaxf(m0, mt0), mn1 = fmaxf(m1, mt1);
        float f0 = __expf(m0 - mn0), f1 = __expf(m1 - mn1);
        float s0 = 0.f, s1 = 0.f;
        uint32_t pa0[8], pa1[8], pb0[8], pb1[8];
#pragma unroll
        for (int nt = 0; nt < 8; nt++) {
            float p0 = __expf(c[nt][0] - mn0), p1 = __expf(c[nt][1] - mn0);
            float p2 = __expf(c[nt][2] - mn1), p3 = __expf(c[nt][3] - mn1);
            s0 += p0 + p1; s1 += p2 + p3;
            pa0[nt] = pack_bf2(p0, p1); pb0[nt] = pack_lo2(p0, p1, pa0[nt]);
            pa1[nt] = pack_bf2(p2, p3); pb1[nt] = pack_lo2(p2, p3, pa1[nt]);
        }
        s0 += __shfl_xor_sync(0xffffffffu, s0, 1);
        s0 += __shfl_xor_sync(0xffffffffu, s0, 2);
        s1 += __shfl_xor_sync(0xffffffffu, s1, 1);
        s1 += __shfl_xor_sync(0xffffffffu, s1, 2);
        l0 = l0 * f0 + s0;  m0 = mn0;
        l1 = l1 * f1 + s1;  m1 = mn1;
#pragma unroll
        for (int ht = 0; ht < 8; ht++) {
            O[ht][0] *= f0; O[ht][1] *= f0;
            O[ht][2] *= f1; O[ht][3] *= f1;
        }

        // ---- PV ----
#pragma unroll
        for (int ksi = 0; ksi < 4; ksi++) {
            uint32_t a0 = pa0[2 * ksi],     a1 = pa1[2 * ksi];
            uint32_t a2 = pa0[2 * ksi + 1], a3 = pa1[2 * ksi + 1];
            uint32_t g0 = pb0[2 * ksi],     g1 = pb1[2 * ksi];
            uint32_t g2 = pb0[2 * ksi + 1], g3 = pb1[2 * ksi + 1];
#pragma unroll
            for (int bp = 0; bp < 4; bp++) {
                uint32_t off = sw128(ksi * 16 + lrow, bp * 2 + lch);
                uint32_t v0, v1, v2, v3, w0, w1, w2, w3;
                LDSM_X4_T(v0, v1, v2, v3, kvb + 2 * FKVARR + off);
                LDSM_X4_T(w0, w1, w2, w3, kvb + 3 * FKVARR + off);
                MMA_BF16(O[bp * 2], a0, a1, a2, a3, v0, v1);
                MMA_BF16(O[bp * 2], a0, a1, a2, a3, w0, w1);
                MMA_BF16(O[bp * 2], g0, g1, g2, g3, v0, v1);
                MMA_BF16(O[bp * 2 + 1], a0, a1, a2, a3, v2, v3);
                MMA_BF16(O[bp * 2 + 1], a0, a1, a2, a3, w2, w3);
                MMA_BF16(O[bp * 2 + 1], g0, g1, g2, g3, v2, v3);
            }
        }
        __syncthreads();
    }

    // ---- epilogue ----
    float i0 = 1.f / l0, i1 = 1.f / l1;
    size_t r0g = qrowg + wid * 16 + (lane >> 2);
    size_t r1g = r0g + 8;
    int cb = hcol + (lane & 3) * 2;
#pragma unroll
    for (int ht = 0; ht < 8; ht++) {
        int col = cb + ht * 8;
        float v0 = O[ht][0] * i0, v1 = O[ht][1] * i0;
        float v2 = O[ht][2] * i1, v3 = O[ht][3] * i1;
        uint32_t h01 = pack_bf2(v0, v1);
        *(uint32_t*)&ohi[r0g * DDIM + col] = h01;
        *(uint32_t*)&olo[r0g * DDIM + col] = pack_lo2(v0, v1, h01);
        uint32_t h23 = pack_bf2(v2, v3);
        *(uint32_t*)&ohi[r1g * DDIM + col] = h23;
        *(uint32_t*)&olo[r1g * DDIM + col] = pack_lo2(v2, v3, h23);
    }
}

// ---------------------------------------------------------------------------
extern "C" void kernel_launch(void* const* d_in, const int* in_sizes, int n_in,
                              void* d_out, int out_size)
{
    const float* x      = (const float*)d_in[0];
    const float* w_attn = (const float*)d_in[1];
    const float* b_attn = (const float*)d_in[2];
    const float* w_proj = (const float*)d_in[3];
    const float* b_proj = (const float*)d_in[4];
    float* out = (float*)d_out;

    __nv_bfloat16 *qkvhi, *qkvlo, *xhi, *xlo, *w1hi, *w1lo, *w2hi, *w2lo, *ahi, *alo;
    cudaGetSymbolAddress((void**)&qkvhi, g_qkvhi);
    cudaGetSymbolAddress((void**)&qkvlo, g_qkvlo);
    cudaGetSymbolAddress((void**)&xhi,  g_xhi);
    cudaGetSymbolAddress((void**)&xlo,  g_xlo);
    cudaGetSymbolAddress((void**)&w1hi, g_w1hi);
    cudaGetSymbolAddress((void**)&w1lo, g_w1lo);
    cudaGetSymbolAddress((void**)&w2hi, g_w2hi);
    cudaGetSymbolAddress((void**)&w2lo, g_w2lo);
    cudaGetSymbolAddress((void**)&ahi,  g_ahi);
    cudaGetSymbolAddress((void**)&alo,  g_alo);

    cudaFuncSetAttribute(hmma_gemm<0>,
                         cudaFuncAttributeMaxDynamicSharedMemorySize, HMMA_SMEM);
    cudaFuncSetAttribute(hmma_gemm<1>,
                         cudaFuncAttributeMaxDynamicSharedMemorySize, HMMA_SMEM);
    cudaFuncSetAttribute(flash_hmma,
                         cudaFuncAttributeMaxDynamicSharedMemorySize, FL_SMEM);

    // Prep
    split_plain<<<1024, 256>>>(x, xhi, xlo, MM * DDIM / 4);
    transpose_split<<<dim3(QKV_LD / 32, DDIM / 32), dim3(32, 8)>>>(w_attn, w1hi, w1lo, DDIM, QKV_LD);
    transpose_split<<<dim3(DDIM / 32, DDIM / 32),  dim3(32, 8)>>>(w_proj, w2hi, w2lo, DDIM, DDIM);

    // 1) QKV (bf16 hi/lo out, Q pre-scaled)
    hmma_gemm<1><<<dim3(QKV_LD / 128, MM / 128), 256, HMMA_SMEM>>>(
        xhi, xlo, w1hi, w1lo, b_attn, nullptr, qkvhi, qkvlo, DDIM, QKV_LD);

    // 2) HMMA flash attention -> bf16 hi/lo attention output
    flash_hmma<<<dim3(SS / 128, HH, BB), 256, FL_SMEM>>>(qkvhi, qkvlo, ahi, alo);

    // 3) proj (fp32 out)
    hmma_gemm<0><<<dim3(DDIM / 128, MM / 128), 256, HMMA_SMEM>>>(
        ahi, alo, w2hi, w2lo, b_proj, out, nullptr, nullptr, DDIM, DDIM);
}

// round 7
// speedup vs baseline: 4.6060x; 1.4115x over previous
#include <cuda_runtime.h>
#include <cuda_fp16.h>
#include <math_constants.h>
#include <cstdint>

#define BB 2
#define SS 2048
#define DDIM 1024
#define HH 16
#define HDIM 64
#define MM (BB*SS)          // 4096 rows
#define QKV_LD 3072         // 3*D

// ---------------------------------------------------------------------------
// Scratch (device globals: allowed; runtime allocs are not)
// ---------------------------------------------------------------------------
__device__ __half g_qkvhi[(size_t)MM * QKV_LD];  // QKV hi (Q pre-scaled)
__device__ __half g_qkvlo[(size_t)MM * QKV_LD];  // QKV lo (used for K,V)
__device__ __half g_xh[(size_t)MM * DDIM];       // x hi (A-side: hi only)
__device__ __half g_w1h[(size_t)QKV_LD * DDIM];  // w_attn^T hi [3072,1024]
__device__ __half g_w1l[(size_t)QKV_LD * DDIM];  // w_attn^T lo
__device__ __half g_w2h[(size_t)DDIM * DDIM];    // w_proj^T hi [1024,1024]
__device__ __half g_w2l[(size_t)DDIM * DDIM];    // w_proj^T lo
__device__ __half g_ah[(size_t)MM * DDIM];       // attention out hi (A-side)

// ---------------------------------------------------------------------------
// Portable PTX helpers (NO tcgen05 — harness PTX targets plain compute_103)
// ---------------------------------------------------------------------------
__device__ __forceinline__ uint32_t smem_u32(const void* p) {
    uint32_t a;
    asm("{ .reg .u64 t; cvta.to.shared.u64 t, %1; cvt.u32.u64 %0, t; }"
        : "=r"(a) : "l"(p));
    return a;
}

#define CP_ASYNC16(sa, gp) \
    asm volatile("cp.async.cg.shared.global [%0], [%1], 16;" :: "r"(sa), "l"(gp))
#define CP_COMMIT() asm volatile("cp.async.commit_group;" ::: "memory")
#define CP_WAIT1()  asm volatile("cp.async.wait_group 1;" ::: "memory")
#define CP_WAIT0()  asm volatile("cp.async.wait_group 0;" ::: "memory")

#define LDSM_X4(r0, r1, r2, r3, addr) \
    asm volatile("ldmatrix.sync.aligned.m8n8.x4.shared.b16 {%0,%1,%2,%3}, [%4];" \
        : "=r"(r0), "=r"(r1), "=r"(r2), "=r"(r3) : "r"(addr))

#define LDSM_X4_T(r0, r1, r2, r3, addr) \
    asm volatile("ldmatrix.sync.aligned.m8n8.x4.trans.shared.b16 {%0,%1,%2,%3}, [%4];" \
        : "=r"(r0), "=r"(r1), "=r"(r2), "=r"(r3) : "r"(addr))

#define MMA_F16(c, a0, a1, a2, a3, b0, b1) \
    asm volatile("mma.sync.aligned.m16n8k16.row.col.f32.f16.f16.f32 " \
        "{%0,%1,%2,%3}, {%4,%5,%6,%7}, {%8,%9}, {%0,%1,%2,%3};" \
        : "+f"((c)[0]), "+f"((c)[1]), "+f"((c)[2]), "+f"((c)[3]) \
        : "r"(a0), "r"(a1), "r"(a2), "r"(a3), "r"(b0), "r"(b1))

__device__ __forceinline__ uint32_t pack_hf2(float a, float b) {
    __half2 t = __floats2half2_rn(a, b);
    return *(uint32_t*)&t;
}
__device__ __forceinline__ uint32_t pack_hlo2(float a, float b, uint32_t hipack) {
    __half2 h = *(__half2*)&hipack;
    return pack_hf2(a - __low2float(h), b - __high2float(h));
}

// Swizzles: rows of 64B (GEMM, ch in 0..3) and 128B (flash, ch in 0..7).
__device__ __forceinline__ uint32_t sw64(uint32_t r, uint32_t ch) {
    return r * 64 + ((ch ^ ((r + (r >> 2)) & 3)) << 4);
}
__device__ __forceinline__ uint32_t sw128(uint32_t r, uint32_t ch) {
    return r * 128 + ((ch ^ (r & 7)) << 4);
}

// ---------------------------------------------------------------------------
// Prep: x fp32 -> fp16 hi only (A-side term needs no residual)
// ---------------------------------------------------------------------------
__global__ void split_x(const float* __restrict__ s,
                        __half* __restrict__ hi, int n4)
{
    for (int i = blockIdx.x * blockDim.x + threadIdx.x; i < n4;
         i += gridDim.x * blockDim.x) {
        float4 v = ((const float4*)s)[i];
        ((uint32_t*)hi)[2 * i]     = pack_hf2(v.x, v.y);
        ((uint32_t*)hi)[2 * i + 1] = pack_hf2(v.z, v.w);
    }
}

// Prep: transpose W[K,N] -> WT[N,K] with fp16 hi/lo split (B-side).
__global__ void transpose_split(const float* __restrict__ W,
                                __half* __restrict__ hi,
                                __half* __restrict__ lo, int K, int N)
{
    __shared__ float t[32][33];
    int n0 = blockIdx.x * 32, k0 = blockIdx.y * 32;
    int tx = threadIdx.x, ty = threadIdx.y;
#pragma unroll
    for (int i = 0; i < 32; i += 8)
        t[ty + i][tx] = W[(size_t)(k0 + ty + i) * N + n0 + tx];
    __syncthreads();
#pragma unroll
    for (int i = 0; i < 32; i += 8) {
        float v = t[tx][ty + i];
        __half h = __float2half(v);
        size_t o = (size_t)(n0 + ty + i) * K + k0 + tx;
        hi[o] = h;
        lo[o] = __float2half(v - __half2float(h));
    }
}

// ---------------------------------------------------------------------------
// HMMA fp16 asymmetric-split GEMM + bias: C = Ah @ (Bh + Bl)^T + bias
// 3 smem arrays/stage (Ah, Bh, Bl), 3-stage cp.async, XOR swizzle.
// MODE 0: fp32 C.  MODE 1: fp16 hi/lo C (Q cols scaled 0.125).
// ---------------------------------------------------------------------------
#define GARR 8192                    // bytes per array (128 rows x 64B)
#define GSTAGE (3 * GARR)            // 24576
#define HMMA_SMEM (3 * GSTAGE)       // 73728 -> 2 CTAs/SM

template<int MODE>
__global__ __launch_bounds__(256, 2)
void hmma_gemm(const __half* __restrict__ Ah,
               const __half* __restrict__ Bh, const __half* __restrict__ Bl,
               const float* __restrict__ bias, float* __restrict__ C,
               __half* __restrict__ Chi, __half* __restrict__ Clo,
               int K, int N)
{
    extern __shared__ __align__(16) char smraw[];
    const uint32_t sb = smem_u32(smraw);

    const int tid = threadIdx.x;
    const int wid = tid >> 5, lane = tid & 31;
    const int m0 = blockIdx.y * 128, n0 = blockIdx.x * 128;
    const int warp_m = wid & 3;
    const int warp_n = wid >> 2;

    const __half* arrs[3] = {Ah, Bh, Bl};

    float c[2][8][4];
#pragma unroll
    for (int mi = 0; mi < 2; mi++)
#pragma unroll
        for (int nt = 0; nt < 8; nt++)
#pragma unroll
            for (int j = 0; j < 4; j++) c[mi][nt][j] = 0.f;

    const int nkt = K / 32;

    auto load_stage = [&](int kt, int slot) {
        const int k0 = kt * 32;
        const uint32_t sbase = sb + (uint32_t)slot * GSTAGE;
#pragma unroll
        for (int arr = 0; arr < 3; arr++) {
            const __half* P = arrs[arr];
            const int rowbase = (arr == 0) ? m0 : n0;
#pragma unroll
            for (int i = 0; i < 2; i++) {
                uint32_t idx = tid + i * 256;
                uint32_t r = idx >> 2, ch = idx & 3;
                const __half* gp = P + (size_t)(rowbase + r) * K + k0 + ch * 8;
                CP_ASYNC16(sbase + arr * GARR + sw64(r, ch), gp);
            }
        }
        CP_COMMIT();
    };

    load_stage(0, 0);
    load_stage(1, 1);

    const uint32_t lrow = lane & 15;
    const uint32_t lch  = lane >> 4;

    for (int kt = 0; kt < nkt; kt++) {
        if (kt + 2 < nkt) CP_WAIT1(); else CP_WAIT0();
        __syncthreads();

        const uint32_t sbase = sb + (uint32_t)(kt % 3) * GSTAGE;
        const uint32_t aRow = warp_m * 32;
        const uint32_t bRow = warp_n * 64;

#pragma unroll
        for (int ks = 0; ks < 2; ks++) {
            const uint32_t ch = ks * 2 + lch;
            uint32_t ah[2][4];
#pragma unroll
            for (int mi = 0; mi < 2; mi++) {
                uint32_t off = sw64(aRow + mi * 16 + lrow, ch);
                LDSM_X4(ah[mi][0], ah[mi][1], ah[mi][2], ah[mi][3],
                        sbase + off);
            }
#pragma unroll
            for (int np = 0; np < 4; np++) {
                uint32_t off = sw64(bRow + np * 16 + lrow, ch);
                uint32_t bh[4], bl[4];
                LDSM_X4(bh[0], bh[1], bh[2], bh[3], sbase + 1 * GARR + off);
                LDSM_X4(bl[0], bl[1], bl[2], bl[3], sbase + 2 * GARR + off);
#pragma unroll
                for (int mi = 0; mi < 2; mi++) {
#pragma unroll
                    for (int hf = 0; hf < 2; hf++) {
                        const int nt = np * 2 + hf;
                        MMA_F16(c[mi][nt], ah[mi][0], ah[mi][1], ah[mi][2], ah[mi][3],
                                bh[hf], bh[2 + hf]);
                        MMA_F16(c[mi][nt], ah[mi][0], ah[mi][1], ah[mi][2], ah[mi][3],
                                bl[hf], bl[2 + hf]);
                    }
                }
            }
        }

        if (kt + 2 < nkt) load_stage(kt + 2, (kt + 2) % 3);
    }

    // Epilogue
#pragma unroll
    for (int mi = 0; mi < 2; mi++) {
        int r0 = m0 + warp_m * 32 + mi * 16 + (lane >> 2);
        int r1 = r0 + 8;
#pragma unroll
        for (int nt = 0; nt < 8; nt++) {
            int col = n0 + warp_n * 64 + nt * 8 + (lane & 3) * 2;
            float b0 = bias[col], b1 = bias[col + 1];
            float v00 = c[mi][nt][0] + b0, v01 = c[mi][nt][1] + b1;
            float v10 = c[mi][nt][2] + b0, v11 = c[mi][nt][3] + b1;
            if (MODE == 0) {
                *(float2*)&C[(size_t)r0 * N + col] = make_float2(v00, v01);
                *(float2*)&C[(size_t)r1 * N + col] = make_float2(v10, v11);
            } else {
                if (col < DDIM) {   // Q columns: fold 1/sqrt(hd) (exact)
                    v00 *= 0.125f; v01 *= 0.125f; v10 *= 0.125f; v11 *= 0.125f;
                }
                uint32_t h0 = pack_hf2(v00, v01);
                uint32_t h1 = pack_hf2(v10, v11);
                *(uint32_t*)&Chi[(size_t)r0 * N + col] = h0;
                *(uint32_t*)&Clo[(size_t)r0 * N + col] = pack_hlo2(v00, v01, h0);
                *(uint32_t*)&Chi[(size_t)r1 * N + col] = h1;
                *(uint32_t*)&Clo[(size_t)r1 * N + col] = pack_hlo2(v10, v11, h1);
            }
        }
    }
}

// ---------------------------------------------------------------------------
// HMMA flash attention, causal, fp16 asymmetric split:
// S = Qh·(Kh+Kl)^T, O = Ph·(Vh+Vl). Q/P carry no residual (A-side).
// smem: Qh 16KB + 2 KV stages x 32KB = 80KB -> 2 CTAs/SM.
// ---------------------------------------------------------------------------
#define FQARR (128 * 128)            // 16384 bytes (Q hi)
#define FKVARR (64 * 128)            // 8192 bytes per KV array
#define FKVSTAGE (4 * FKVARR)        // Kh, Kl, Vh, Vl = 32768
#define FL_SMEM (FQARR + 2 * FKVSTAGE)   // 81920 bytes

__global__ __launch_bounds__(256, 2)
void flash_hmma(const __half* __restrict__ qkvhi,
                const __half* __restrict__ qkvlo,
                __half* __restrict__ oh)
{
    extern __shared__ __align__(16) char smraw[];
    const uint32_t sb = smem_u32(smraw);
    const int tid = threadIdx.x, wid = tid >> 5, lane = tid & 31;
    const int qt = gridDim.x - 1 - blockIdx.x;   // big tiles first
    const int h = blockIdx.y, b = blockIdx.z;
    const size_t qrowg = (size_t)(b * SS + qt * 128);
    const int hcol = h * HDIM;
    const uint32_t lrow = lane & 15, lch = lane >> 4;

    // Q hi -> smem (one commit group)
#pragma unroll
    for (int i = 0; i < 4; i++) {
        uint32_t idx = tid + i * 256;
        uint32_t r = idx >> 3, ch = idx & 7;
        size_t g = (qrowg + r) * QKV_LD + hcol + ch * 8;
        CP_ASYNC16(sb + sw128(r, ch), qkvhi + g);
    }
    CP_COMMIT();

    auto load_kv = [&](int kt, int s) {
        size_t krow = (size_t)(b * SS + kt * 64);
        uint32_t sbase = sb + FQARR + (uint32_t)s * FKVSTAGE;
#pragma unroll
        for (int i = 0; i < 2; i++) {
            uint32_t idx = tid + i * 256;
            uint32_t r = idx >> 3, ch = idx & 7;
            size_t g = (krow + r) * QKV_LD + DDIM + hcol + ch * 8;
            uint32_t so = sw128(r, ch);
            CP_ASYNC16(sbase + so,               qkvhi + g);
            CP_ASYNC16(sbase + FKVARR + so,      qkvlo + g);
            CP_ASYNC16(sbase + 2 * FKVARR + so,  qkvhi + g + DDIM);
            CP_ASYNC16(sbase + 3 * FKVARR + so,  qkvlo + g + DDIM);
        }
        CP_COMMIT();
    };

    load_kv(0, 0);

    float O[8][4];
#pragma unroll
    for (int ht = 0; ht < 8; ht++)
#pragma unroll
        for (int j = 0; j < 4; j++) O[ht][j] = 0.f;
    float m0 = -CUDART_INF_F, m1 = -CUDART_INF_F, l0 = 0.f, l1 = 0.f;

    const int qr0 = qt * 128 + wid * 16 + (lane >> 2);
    const int ktmax = 2 * qt + 1;

    for (int kt = 0; kt <= ktmax; kt++) {
        const int s = kt & 1;
        if (kt < ktmax) { load_kv(kt + 1, s ^ 1); CP_WAIT1(); }
        else            { CP_WAIT0(); }
        __syncthreads();
        const uint32_t kvb = sb + FQARR + (uint32_t)s * FKVSTAGE;

        // ---- scores: S = Qh·(Kh+Kl)^T ----
        float c[8][4];
#pragma unroll
        for (int nt = 0; nt < 8; nt++)
#pragma unroll
            for (int j = 0; j < 4; j++) c[nt][j] = 0.f;

#pragma unroll
        for (int ks = 0; ks < 4; ks++) {
            const uint32_t ch = ks * 2 + lch;
            uint32_t qoff = sw128(wid * 16 + lrow, ch);
            uint32_t q0, q1, q2, q3;
            LDSM_X4(q0, q1, q2, q3, sb + qoff);
#pragma unroll
            for (int bp = 0; bp < 4; bp++) {
                uint32_t off = sw128(bp * 16 + lrow, ch);
                uint32_t k0, k1, k2, k3, e0, e1, e2, e3;
                LDSM_X4(k0, k1, k2, k3, kvb + off);
                LDSM_X4(e0, e1, e2, e3, kvb + FKVARR + off);
                MMA_F16(c[bp * 2], q0, q1, q2, q3, k0, k2);
                MMA_F16(c[bp * 2], q0, q1, q2, q3, e0, e2);
                MMA_F16(c[bp * 2 + 1], q0, q1, q2, q3, k1, k3);
                MMA_F16(c[bp * 2 + 1], q0, q1, q2, q3, e1, e3);
            }
        }

        // ---- causal mask ----
        if (kt * 64 + 63 > qt * 128 + wid * 16) {
#pragma unroll
            for (int nt = 0; nt < 8; nt++) {
                int kc = kt * 64 + nt * 8 + (lane & 3) * 2;
                if (kc     > qr0)     c[nt][0] = -CUDART_INF_F;
                if (kc + 1 > qr0)     c[nt][1] = -CUDART_INF_F;
                if (kc     > qr0 + 8) c[nt][2] = -CUDART_INF_F;
                if (kc + 1 > qr0 + 8) c[nt][3] = -CUDART_INF_F;
            }
        }

        // ---- online softmax ----
        float mt0 = -CUDART_INF_F, mt1 = -CUDART_INF_F;
#pragma unroll
        for (int nt = 0; nt < 8; nt++) {
            mt0 = fmaxf(mt0, fmaxf(c[nt][0], c[nt][1]));
            mt1 = fmaxf(mt1, fmaxf(c[nt][2], c[nt][3]));
        }
        mt0 = fmaxf(mt0, __shfl_xor_sync(0xffffffffu, mt0, 1));
        mt0 = fmaxf(mt0, __shfl_xor_sync(0xffffffffu, mt0, 2));
        mt1 = fmaxf(mt1, __shfl_xor_sync(0xffffffffu, mt1, 1));
        mt1 = fmaxf(mt1, __shfl_xor_sync(0xffffffffu, mt1, 2));

        float mn0 = fmaxf(m0, mt0), mn1 = fmaxf(m1, mt1);
        float f0 = __expf(m0 - mn0), f1 = __expf(m1 - mn1);
        float s0 = 0.f, s1 = 0.f;
        uint32_t pa0[8], pa1[8];          // P hi packs rows r, r+8
#pragma unroll
        for (int nt = 0; nt < 8; nt++) {
            float p0 = __expf(c[nt][0] - mn0), p1 = __expf(c[nt][1] - mn0);
            float p2 = __expf(c[nt][2] - mn1), p3 = __expf(c[nt][3] - mn1);
            s0 += p0 + p1; s1 += p2 + p3;
            pa0[nt] = pack_hf2(p0, p1);
            pa1[nt] = pack_hf2(p2, p3);
        }
        s0 += __shfl_xor_sync(0xffffffffu, s0, 1);
        s0 += __shfl_xor_sync(0xffffffffu, s0, 2);
        s1 += __shfl_xor_sync(0xffffffffu, s1, 1);
        s1 += __shfl_xor_sync(0xffffffffu, s1, 2);
        l0 = l0 * f0 + s0;  m0 = mn0;
        l1 = l1 * f1 + s1;  m1 = mn1;
#pragma unroll
        for (int ht = 0; ht < 8; ht++) {
            O[ht][0] *= f0; O[ht][1] *= f0;
            O[ht][2] *= f1; O[ht][3] *= f1;
        }

        // ---- PV: O += Ph·(Vh+Vl) ----
#pragma unroll
        for (int ksi = 0; ksi < 4; ksi++) {
            uint32_t a0 = pa0[2 * ksi],     a1 = pa1[2 * ksi];
            uint32_t a2 = pa0[2 * ksi + 1], a3 = pa1[2 * ksi + 1];
#pragma unroll
            for (int bp = 0; bp < 4; bp++) {
                uint32_t off = sw128(ksi * 16 + lrow, bp * 2 + lch);
                uint32_t v0, v1, v2, v3, w0, w1, w2, w3;
                LDSM_X4_T(v0, v1, v2, v3, kvb + 2 * FKVARR + off);
                LDSM_X4_T(w0, w1, w2, w3, kvb + 3 * FKVARR + off);
                MMA_F16(O[bp * 2], a0, a1, a2, a3, v0, v1);
                MMA_F16(O[bp * 2], a0, a1, a2, a3, w0, w1);
                MMA_F16(O[bp * 2 + 1], a0, a1, a2, a3, v2, v3);
                MMA_F16(O[bp * 2 + 1], a0, a1, a2, a3, w2, w3);
            }
        }
        __syncthreads();
    }

    // ---- epilogue: normalize, store fp16 hi only (proj A-side) ----
    float i0 = 1.f / l0, i1 = 1.f / l1;
    size_t r0g = qrowg + wid * 16 + (lane >> 2);
    size_t r1g = r0g + 8;
    int cb = hcol + (lane & 3) * 2;
#pragma unroll
    for (int ht = 0; ht < 8; ht++) {
        int col = cb + ht * 8;
        *(uint32_t*)&oh[r0g * DDIM + col] = pack_hf2(O[ht][0] * i0, O[ht][1] * i0);
        *(uint32_t*)&oh[r1g * DDIM + col] = pack_hf2(O[ht][2] * i1, O[ht][3] * i1);
    }
}

// ---------------------------------------------------------------------------
extern "C" void kernel_launch(void* const* d_in, const int* in_sizes, int n_in,
                              void* d_out, int out_size)
{
    const float* x      = (const float*)d_in[0];
    const float* w_attn = (const float*)d_in[1];
    const float* b_attn = (const float*)d_in[2];
    const float* w_proj = (const float*)d_in[3];
    const float* b_proj = (const float*)d_in[4];
    float* out = (float*)d_out;

    __half *qkvhi, *qkvlo, *xh, *w1h, *w1l, *w2h, *w2l, *ah;
    cudaGetSymbolAddress((void**)&qkvhi, g_qkvhi);
    cudaGetSymbolAddress((void**)&qkvlo, g_qkvlo);
    cudaGetSymbolAddress((void**)&xh,  g_xh);
    cudaGetSymbolAddress((void**)&w1h, g_w1h);
    cudaGetSymbolAddress((void**)&w1l, g_w1l);
    cudaGetSymbolAddress((void**)&w2h, g_w2h);
    cudaGetSymbolAddress((void**)&w2l, g_w2l);
    cudaGetSymbolAddress((void**)&ah,  g_ah);

    cudaFuncSetAttribute(hmma_gemm<0>,
                         cudaFuncAttributeMaxDynamicSharedMemorySize, HMMA_SMEM);
    cudaFuncSetAttribute(hmma_gemm<1>,
                         cudaFuncAttributeMaxDynamicSharedMemorySize, HMMA_SMEM);
    cudaFuncSetAttribute(flash_hmma,
                         cudaFuncAttributeMaxDynamicSharedMemorySize, FL_SMEM);

    // Prep
    split_x<<<1024, 256>>>(x, xh, MM * DDIM / 4);
    transpose_split<<<dim3(QKV_LD / 32, DDIM / 32), dim3(32, 8)>>>(w_attn, w1h, w1l, DDIM, QKV_LD);
    transpose_split<<<dim3(DDIM / 32, DDIM / 32),  dim3(32, 8)>>>(w_proj, w2h, w2l, DDIM, DDIM);

    // 1) QKV (fp16 hi/lo out, Q pre-scaled)
    hmma_gemm<1><<<dim3(QKV_LD / 128, MM / 128), 256, HMMA_SMEM>>>(
        xh, w1h, w1l, b_attn, nullptr, qkvhi, qkvlo, DDIM, QKV_LD);

    // 2) flash attention -> fp16 hi attention output
    flash_hmma<<<dim3(SS / 128, HH, BB), 256, FL_SMEM>>>(qkvhi, qkvlo, ah);

    // 3) proj (fp32 out)
    hmma_gemm<0><<<dim3(DDIM / 128, MM / 128), 256, HMMA_SMEM>>>(
        ah, w2h, w2l, b_proj, out, nullptr, nullptr, DDIM, DDIM);
}

// round 8
// speedup vs baseline: 4.6308x; 1.0054x over previous
#include <cuda_runtime.h>
#include <cuda_fp16.h>
#include <math_constants.h>
#include <cstdint>

#define BB 2
#define SS 2048
#define DDIM 1024
#define HH 16
#define HDIM 64
#define MM (BB*SS)          // 4096 rows
#define QKV_LD 3072         // 3*D

// ---------------------------------------------------------------------------
// Scratch (device globals: allowed; runtime allocs are not)
// ---------------------------------------------------------------------------
__device__ __half g_qkvhi[(size_t)MM * QKV_LD];  // QKV hi (Q pre-scaled)
__device__ __half g_qkvlo[(size_t)MM * QKV_LD];  // QKV lo (used for K,V)
__device__ __half g_xh[(size_t)MM * DDIM];       // x hi (A-side: hi only)
__device__ __half g_w1h[(size_t)QKV_LD * DDIM];  // w_attn^T hi [3072,1024]
__device__ __half g_w1l[(size_t)QKV_LD * DDIM];  // w_attn^T lo
__device__ __half g_w2h[(size_t)DDIM * DDIM];    // w_proj^T hi [1024,1024]
__device__ __half g_w2l[(size_t)DDIM * DDIM];    // w_proj^T lo
__device__ __half g_ah[(size_t)MM * DDIM];       // attention out hi (A-side)

// ---------------------------------------------------------------------------
// Portable PTX helpers
// ---------------------------------------------------------------------------
__device__ __forceinline__ uint32_t smem_u32(const void* p) {
    uint32_t a;
    asm("{ .reg .u64 t; cvta.to.shared.u64 t, %1; cvt.u32.u64 %0, t; }"
        : "=r"(a) : "l"(p));
    return a;
}

#define CP_ASYNC16(sa, gp) \
    asm volatile("cp.async.cg.shared.global [%0], [%1], 16;" :: "r"(sa), "l"(gp))
#define CP_COMMIT() asm volatile("cp.async.commit_group;" ::: "memory")
#define CP_WAIT1()  asm volatile("cp.async.wait_group 1;" ::: "memory")
#define CP_WAIT0()  asm volatile("cp.async.wait_group 0;" ::: "memory")

#define LDSM_X4(r0, r1, r2, r3, addr) \
    asm volatile("ldmatrix.sync.aligned.m8n8.x4.shared.b16 {%0,%1,%2,%3}, [%4];" \
        : "=r"(r0), "=r"(r1), "=r"(r2), "=r"(r3) : "r"(addr))

#define LDSM_X4_T(r0, r1, r2, r3, addr) \
    asm volatile("ldmatrix.sync.aligned.m8n8.x4.trans.shared.b16 {%0,%1,%2,%3}, [%4];" \
        : "=r"(r0), "=r"(r1), "=r"(r2), "=r"(r3) : "r"(addr))

#define MMA_F16(c, a0, a1, a2, a3, b0, b1) \
    asm volatile("mma.sync.aligned.m16n8k16.row.col.f32.f16.f16.f32 " \
        "{%0,%1,%2,%3}, {%4,%5,%6,%7}, {%8,%9}, {%0,%1,%2,%3};" \
        : "+f"((c)[0]), "+f"((c)[1]), "+f"((c)[2]), "+f"((c)[3]) \
        : "r"(a0), "r"(a1), "r"(a2), "r"(a3), "r"(b0), "r"(b1))

__device__ __forceinline__ uint32_t pack_hf2(float a, float b) {
    __half2 t = __floats2half2_rn(a, b);
    return *(uint32_t*)&t;
}
__device__ __forceinline__ uint32_t pack_hlo2(float a, float b, uint32_t hipack) {
    __half2 h = *(__half2*)&hipack;
    return pack_hf2(a - __low2float(h), b - __high2float(h));
}

// Swizzles: rows of 64B (GEMM, ch in 0..3) and 128B (flash, ch in 0..7).
__device__ __forceinline__ uint32_t sw64(uint32_t r, uint32_t ch) {
    return r * 64 + ((ch ^ ((r + (r >> 2)) & 3)) << 4);
}
__device__ __forceinline__ uint32_t sw128(uint32_t r, uint32_t ch) {
    return r * 128 + ((ch ^ (r & 7)) << 4);
}

// ---------------------------------------------------------------------------
// Prep: x fp32 -> fp16 hi only
// ---------------------------------------------------------------------------
__global__ void split_x(const float* __restrict__ s,
                        __half* __restrict__ hi, int n4)
{
    for (int i = blockIdx.x * blockDim.x + threadIdx.x; i < n4;
         i += gridDim.x * blockDim.x) {
        float4 v = ((const float4*)s)[i];
        ((uint32_t*)hi)[2 * i]     = pack_hf2(v.x, v.y);
        ((uint32_t*)hi)[2 * i + 1] = pack_hf2(v.z, v.w);
    }
}

// Prep: transpose W[K,N] -> WT[N,K] with fp16 hi/lo split (B-side).
__global__ void transpose_split(const float* __restrict__ W,
                                __half* __restrict__ hi,
                                __half* __restrict__ lo, int K, int N)
{
    __shared__ float t[32][33];
    int n0 = blockIdx.x * 32, k0 = blockIdx.y * 32;
    int tx = threadIdx.x, ty = threadIdx.y;
#pragma unroll
    for (int i = 0; i < 32; i += 8)
        t[ty + i][tx] = W[(size_t)(k0 + ty + i) * N + n0 + tx];
    __syncthreads();
#pragma unroll
    for (int i = 0; i < 32; i += 8) {
        float v = t[tx][ty + i];
        __half h = __float2half(v);
        size_t o = (size_t)(n0 + ty + i) * K + k0 + tx;
        hi[o] = h;
        lo[o] = __float2half(v - __half2float(h));
    }
}

// ---------------------------------------------------------------------------
// HMMA fp16 asymmetric-split GEMM + bias: C = Ah @ (Bh + Bl)^T + bias
// MMAs reordered: 4 independent-accumulator MMAs between RAW-dependent pairs.
// ---------------------------------------------------------------------------
#define GARR 8192
#define GSTAGE (3 * GARR)            // 24576
#define HMMA_SMEM (3 * GSTAGE)       // 73728 -> 2 CTAs/SM

template<int MODE>
__global__ __launch_bounds__(256, 2)
void hmma_gemm(const __half* __restrict__ Ah,
               const __half* __restrict__ Bh, const __half* __restrict__ Bl,
               const float* __restrict__ bias, float* __restrict__ C,
               __half* __restrict__ Chi, __half* __restrict__ Clo,
               int K, int N)
{
    extern __shared__ __align__(16) char smraw[];
    const uint32_t sb = smem_u32(smraw);

    const int tid = threadIdx.x;
    const int wid = tid >> 5, lane = tid & 31;
    const int m0 = blockIdx.y * 128, n0 = blockIdx.x * 128;
    const int warp_m = wid & 3;
    const int warp_n = wid >> 2;

    const __half* arrs[3] = {Ah, Bh, Bl};

    float c[2][8][4];
#pragma unroll
    for (int mi = 0; mi < 2; mi++)
#pragma unroll
        for (int nt = 0; nt < 8; nt++)
#pragma unroll
            for (int j = 0; j < 4; j++) c[mi][nt][j] = 0.f;

    const int nkt = K / 32;

    auto load_stage = [&](int kt, int slot) {
        const int k0 = kt * 32;
        const uint32_t sbase = sb + (uint32_t)slot * GSTAGE;
#pragma unroll
        for (int arr = 0; arr < 3; arr++) {
            const __half* P = arrs[arr];
            const int rowbase = (arr == 0) ? m0 : n0;
#pragma unroll
            for (int i = 0; i < 2; i++) {
                uint32_t idx = tid + i * 256;
                uint32_t r = idx >> 2, ch = idx & 3;
                const __half* gp = P + (size_t)(rowbase + r) * K + k0 + ch * 8;
                CP_ASYNC16(sbase + arr * GARR + sw64(r, ch), gp);
            }
        }
        CP_COMMIT();
    };

    load_stage(0, 0);
    load_stage(1, 1);

    const uint32_t lrow = lane & 15;
    const uint32_t lch  = lane >> 4;

    for (int kt = 0; kt < nkt; kt++) {
        if (kt + 2 < nkt) CP_WAIT1(); else CP_WAIT0();
        __syncthreads();

        const uint32_t sbase = sb + (uint32_t)(kt % 3) * GSTAGE;
        const uint32_t aRow = warp_m * 32;
        const uint32_t bRow = warp_n * 64;

#pragma unroll
        for (int ks = 0; ks < 2; ks++) {
            const uint32_t ch = ks * 2 + lch;
            uint32_t ah[2][4];
#pragma unroll
            for (int mi = 0; mi < 2; mi++) {
                uint32_t off = sw64(aRow + mi * 16 + lrow, ch);
                LDSM_X4(ah[mi][0], ah[mi][1], ah[mi][2], ah[mi][3],
                        sbase + off);
            }
#pragma unroll
            for (int np = 0; np < 4; np++) {
                uint32_t off = sw64(bRow + np * 16 + lrow, ch);
                uint32_t bh[4], bl[4];
                LDSM_X4(bh[0], bh[1], bh[2], bh[3], sbase + 1 * GARR + off);
                LDSM_X4(bl[0], bl[1], bl[2], bl[3], sbase + 2 * GARR + off);
                const int n0t = np * 2, n1t = np * 2 + 1;
                // 4 hi-MMAs, 4 distinct accumulators
                MMA_F16(c[0][n0t], ah[0][0], ah[0][1], ah[0][2], ah[0][3], bh[0], bh[2]);
                MMA_F16(c[0][n1t], ah[0][0], ah[0][1], ah[0][2], ah[0][3], bh[1], bh[3]);
                MMA_F16(c[1][n0t], ah[1][0], ah[1][1], ah[1][2], ah[1][3], bh[0], bh[2]);
                MMA_F16(c[1][n1t], ah[1][0], ah[1][1], ah[1][2], ah[1][3], bh[1], bh[3]);
                // 4 lo-MMAs — dependent partner is 4 issues back
                MMA_F16(c[0][n0t], ah[0][0], ah[0][1], ah[0][2], ah[0][3], bl[0], bl[2]);
                MMA_F16(c[0][n1t], ah[0][0], ah[0][1], ah[0][2], ah[0][3], bl[1], bl[3]);
                MMA_F16(c[1][n0t], ah[1][0], ah[1][1], ah[1][2], ah[1][3], bl[0], bl[2]);
                MMA_F16(c[1][n1t], ah[1][0], ah[1][1], ah[1][2], ah[1][3], bl[1], bl[3]);
            }
        }

        if (kt + 2 < nkt) load_stage(kt + 2, (kt + 2) % 3);
    }

    // Epilogue
#pragma unroll
    for (int mi = 0; mi < 2; mi++) {
        int r0 = m0 + warp_m * 32 + mi * 16 + (lane >> 2);
        int r1 = r0 + 8;
#pragma unroll
        for (int nt = 0; nt < 8; nt++) {
            int col = n0 + warp_n * 64 + nt * 8 + (lane & 3) * 2;
            float b0 = bias[col], b1 = bias[col + 1];
            float v00 = c[mi][nt][0] + b0, v01 = c[mi][nt][1] + b1;
            float v10 = c[mi][nt][2] + b0, v11 = c[mi][nt][3] + b1;
            if (MODE == 0) {
                *(float2*)&C[(size_t)r0 * N + col] = make_float2(v00, v01);
                *(float2*)&C[(size_t)r1 * N + col] = make_float2(v10, v11);
            } else {
                if (col < DDIM) {
                    v00 *= 0.125f; v01 *= 0.125f; v10 *= 0.125f; v11 *= 0.125f;
                }
                uint32_t h0 = pack_hf2(v00, v01);
                uint32_t h1 = pack_hf2(v10, v11);
                *(uint32_t*)&Chi[(size_t)r0 * N + col] = h0;
                *(uint32_t*)&Clo[(size_t)r0 * N + col] = pack_hlo2(v00, v01, h0);
                *(uint32_t*)&Chi[(size_t)r1 * N + col] = h1;
                *(uint32_t*)&Clo[(size_t)r1 * N + col] = pack_hlo2(v10, v11, h1);
            }
        }
    }
}

// ---------------------------------------------------------------------------
// HMMA flash attention, causal, fp16 asymmetric split.
// QK and PV process key-tiles in pairs: 4 independent MMAs between RAW pairs.
// ---------------------------------------------------------------------------
#define FQARR (128 * 128)
#define FKVARR (64 * 128)
#define FKVSTAGE (4 * FKVARR)
#define FL_SMEM (FQARR + 2 * FKVSTAGE)   // 81920 bytes

__global__ __launch_bounds__(256, 2)
void flash_hmma(const __half* __restrict__ qkvhi,
                const __half* __restrict__ qkvlo,
                __half* __restrict__ oh)
{
    extern __shared__ __align__(16) char smraw[];
    const uint32_t sb = smem_u32(smraw);
    const int tid = threadIdx.x, wid = tid >> 5, lane = tid & 31;
    const int qt = gridDim.x - 1 - blockIdx.x;
    const int h = blockIdx.y, b = blockIdx.z;
    const size_t qrowg = (size_t)(b * SS + qt * 128);
    const int hcol = h * HDIM;
    const uint32_t lrow = lane & 15, lch = lane >> 4;

    // Q hi -> smem
#pragma unroll
    for (int i = 0; i < 4; i++) {
        uint32_t idx = tid + i * 256;
        uint32_t r = idx >> 3, ch = idx & 7;
        size_t g = (qrowg + r) * QKV_LD + hcol + ch * 8;
        CP_ASYNC16(sb + sw128(r, ch), qkvhi + g);
    }
    CP_COMMIT();

    auto load_kv = [&](int kt, int s) {
        size_t krow = (size_t)(b * SS + kt * 64);
        uint32_t sbase = sb + FQARR + (uint32_t)s * FKVSTAGE;
#pragma unroll
        for (int i = 0; i < 2; i++) {
            uint32_t idx = tid + i * 256;
            uint32_t r = idx >> 3, ch = idx & 7;
            size_t g = (krow + r) * QKV_LD + DDIM + hcol + ch * 8;
            uint32_t so = sw128(r, ch);
            CP_ASYNC16(sbase + so,               qkvhi + g);
            CP_ASYNC16(sbase + FKVARR + so,      qkvlo + g);
            CP_ASYNC16(sbase + 2 * FKVARR + so,  qkvhi + g + DDIM);
            CP_ASYNC16(sbase + 3 * FKVARR + so,  qkvlo + g + DDIM);
        }
        CP_COMMIT();
    };

    load_kv(0, 0);

    float O[8][4];
#pragma unroll
    for (int ht = 0; ht < 8; ht++)
#pragma unroll
        for (int j = 0; j < 4; j++) O[ht][j] = 0.f;
    float m0 = -CUDART_INF_F, m1 = -CUDART_INF_F, l0 = 0.f, l1 = 0.f;

    const int qr0 = qt * 128 + wid * 16 + (lane >> 2);
    const int ktmax = 2 * qt + 1;

    for (int kt = 0; kt <= ktmax; kt++) {
        const int s = kt & 1;
        if (kt < ktmax) { load_kv(kt + 1, s ^ 1); CP_WAIT1(); }
        else            { CP_WAIT0(); }
        __syncthreads();
        const uint32_t kvb = sb + FQARR + (uint32_t)s * FKVSTAGE;

        // ---- scores: S = Qh·(Kh+Kl)^T, key-tiles in pairs ----
        float c[8][4];
#pragma unroll
        for (int nt = 0; nt < 8; nt++)
#pragma unroll
            for (int j = 0; j < 4; j++) c[nt][j] = 0.f;

#pragma unroll
        for (int ks = 0; ks < 4; ks++) {
            const uint32_t ch = ks * 2 + lch;
            uint32_t qoff = sw128(wid * 16 + lrow, ch);
            uint32_t q0, q1, q2, q3;
            LDSM_X4(q0, q1, q2, q3, sb + qoff);
#pragma unroll
            for (int bpp = 0; bpp < 2; bpp++) {
                uint32_t offA = sw128((bpp * 2) * 16 + lrow, ch);
                uint32_t offB = sw128((bpp * 2 + 1) * 16 + lrow, ch);
                uint32_t kA[4], eA[4], kB[4], eB[4];
                LDSM_X4(kA[0], kA[1], kA[2], kA[3], kvb + offA);
                LDSM_X4(eA[0], eA[1], eA[2], eA[3], kvb + FKVARR + offA);
                LDSM_X4(kB[0], kB[1], kB[2], kB[3], kvb + offB);
                LDSM_X4(eB[0], eB[1], eB[2], eB[3], kvb + FKVARR + offB);
                float* c0 = c[bpp * 4 + 0]; float* c1 = c[bpp * 4 + 1];
                float* c2 = c[bpp * 4 + 2]; float* c3 = c[bpp * 4 + 3];
                // 4 hi-MMAs (distinct accumulators), then 4 lo-MMAs
                MMA_F16(c0, q0, q1, q2, q3, kA[0], kA[2]);
                MMA_F16(c1, q0, q1, q2, q3, kA[1], kA[3]);
                MMA_F16(c2, q0, q1, q2, q3, kB[0], kB[2]);
                MMA_F16(c3, q0, q1, q2, q3, kB[1], kB[3]);
                MMA_F16(c0, q0, q1, q2, q3, eA[0], eA[2]);
                MMA_F16(c1, q0, q1, q2, q3, eA[1], eA[3]);
                MMA_F16(c2, q0, q1, q2, q3, eB[0], eB[2]);
                MMA_F16(c3, q0, q1, q2, q3, eB[1], eB[3]);
            }
        }

        // ---- causal mask ----
        if (kt * 64 + 63 > qt * 128 + wid * 16) {
#pragma unroll
            for (int nt = 0; nt < 8; nt++) {
                int kc = kt * 64 + nt * 8 + (lane & 3) * 2;
                if (kc     > qr0)     c[nt][0] = -CUDART_INF_F;
                if (kc + 1 > qr0)     c[nt][1] = -CUDART_INF_F;
                if (kc     > qr0 + 8) c[nt][2] = -CUDART_INF_F;
                if (kc + 1 > qr0 + 8) c[nt][3] = -CUDART_INF_F;
            }
        }

        // ---- online softmax ----
        float mt0 = -CUDART_INF_F, mt1 = -CUDART_INF_F;
#pragma unroll
        for (int nt = 0; nt < 8; nt++) {
            mt0 = fmaxf(mt0, fmaxf(c[nt][0], c[nt][1]));
            mt1 = fmaxf(mt1, fmaxf(c[nt][2], c[nt][3]));
        }
        mt0 = fmaxf(mt0, __shfl_xor_sync(0xffffffffu, mt0, 1));
        mt0 = fmaxf(mt0, __shfl_xor_sync(0xffffffffu, mt0, 2));
        mt1 = fmaxf(mt1, __shfl_xor_sync(0xffffffffu, mt1, 1));
        mt1 = fmaxf(mt1, __shfl_xor_sync(0xffffffffu, mt1, 2));

        float mn0 = fmaxf(m0, mt0), mn1 = fmaxf(m1, mt1);
        float f0 = __expf(m0 - mn0), f1 = __expf(m1 - mn1);
        float s0 = 0.f, s1 = 0.f;
        uint32_t pa0[8], pa1[8];
#pragma unroll
        for (int nt = 0; nt < 8; nt++) {
            float p0 = __expf(c[nt][0] - mn0), p1 = __expf(c[nt][1] - mn0);
            float p2 = __expf(c[nt][2] - mn1), p3 = __expf(c[nt][3] - mn1);
            s0 += p0 + p1; s1 += p2 + p3;
            pa0[nt] = pack_hf2(p0, p1);
            pa1[nt] = pack_hf2(p2, p3);
        }
        s0 += __shfl_xor_sync(0xffffffffu, s0, 1);
        s0 += __shfl_xor_sync(0xffffffffu, s0, 2);
        s1 += __shfl_xor_sync(0xffffffffu, s1, 1);
        s1 += __shfl_xor_sync(0xffffffffu, s1, 2);
        l0 = l0 * f0 + s0;  m0 = mn0;
        l1 = l1 * f1 + s1;  m1 = mn1;
#pragma unroll
        for (int ht = 0; ht < 8; ht++) {
            O[ht][0] *= f0; O[ht][1] *= f0;
            O[ht][2] *= f1; O[ht][3] *= f1;
        }

        // ---- PV: O += Ph·(Vh+Vl), head-dim tiles in pairs ----
#pragma unroll
        for (int ksi = 0; ksi < 4; ksi++) {
            uint32_t a0 = pa0[2 * ksi],     a1 = pa1[2 * ksi];
            uint32_t a2 = pa0[2 * ksi + 1], a3 = pa1[2 * ksi + 1];
#pragma unroll
            for (int bpp = 0; bpp < 2; bpp++) {
                uint32_t offA = sw128(ksi * 16 + lrow, (bpp * 2) * 2 + lch);
                uint32_t offB = sw128(ksi * 16 + lrow, (bpp * 2 + 1) * 2 + lch);
                uint32_t vA[4], wA[4], vB[4], wB[4];
                LDSM_X4_T(vA[0], vA[1], vA[2], vA[3], kvb + 2 * FKVARR + offA);
                LDSM_X4_T(wA[0], wA[1], wA[2], wA[3], kvb + 3 * FKVARR + offA);
                LDSM_X4_T(vB[0], vB[1], vB[2], vB[3], kvb + 2 * FKVARR + offB);
                LDSM_X4_T(wB[0], wB[1], wB[2], wB[3], kvb + 3 * FKVARR + offB);
                float* o0 = O[bpp * 4 + 0]; float* o1 = O[bpp * 4 + 1];
                float* o2 = O[bpp * 4 + 2]; float* o3 = O[bpp * 4 + 3];
                MMA_F16(o0, a0, a1, a2, a3, vA[0], vA[1]);
                MMA_F16(o1, a0, a1, a2, a3, vA[2], vA[3]);
                MMA_F16(o2, a0, a1, a2, a3, vB[0], vB[1]);
                MMA_F16(o3, a0, a1, a2, a3, vB[2], vB[3]);
                MMA_F16(o0, a0, a1, a2, a3, wA[0], wA[1]);
                MMA_F16(o1, a0, a1, a2, a3, wA[2], wA[3]);
                MMA_F16(o2, a0, a1, a2, a3, wB[0], wB[1]);
                MMA_F16(o3, a0, a1, a2, a3, wB[2], wB[3]);
            }
        }
        __syncthreads();
    }

    // ---- epilogue ----
    float i0 = 1.f / l0, i1 = 1.f / l1;
    size_t r0g = qrowg + wid * 16 + (lane >> 2);
    size_t r1g = r0g + 8;
    int cb = hcol + (lane & 3) * 2;
#pragma unroll
    for (int ht = 0; ht < 8; ht++) {
        int col = cb + ht * 8;
        *(uint32_t*)&oh[r0g * DDIM + col] = pack_hf2(O[ht][0] * i0, O[ht][1] * i0);
        *(uint32_t*)&oh[r1g * DDIM + col] = pack_hf2(O[ht][2] * i1, O[ht][3] * i1);
    }
}

// ---------------------------------------------------------------------------
extern "C" void kernel_launch(void* const* d_in, const int* in_sizes, int n_in,
                              void* d_out, int out_size)
{
    const float* x      = (const float*)d_in[0];
    const float* w_attn = (const float*)d_in[1];
    const float* b_attn = (const float*)d_in[2];
    const float* w_proj = (const float*)d_in[3];
    const float* b_proj = (const float*)d_in[4];
    float* out = (float*)d_out;

    __half *qkvhi, *qkvlo, *xh, *w1h, *w1l, *w2h, *w2l, *ah;
    cudaGetSymbolAddress((void**)&qkvhi, g_qkvhi);
    cudaGetSymbolAddress((void**)&qkvlo, g_qkvlo);
    cudaGetSymbolAddress((void**)&xh,  g_xh);
    cudaGetSymbolAddress((void**)&w1h, g_w1h);
    cudaGetSymbolAddress((void**)&w1l, g_w1l);
    cudaGetSymbolAddress((void**)&w2h, g_w2h);
    cudaGetSymbolAddress((void**)&w2l, g_w2l);
    cudaGetSymbolAddress((void**)&ah,  g_ah);

    cudaFuncSetAttribute(hmma_gemm<0>,
                         cudaFuncAttributeMaxDynamicSharedMemorySize, HMMA_SMEM);
    cudaFuncSetAttribute(hmma_gemm<1>,
                         cudaFuncAttributeMaxDynamicSharedMemorySize, HMMA_SMEM);
    cudaFuncSetAttribute(flash_hmma,
                         cudaFuncAttributeMaxDynamicSharedMemorySize, FL_SMEM);

    // Prep
    split_x<<<1024, 256>>>(x, xh, MM * DDIM / 4);
    transpose_split<<<dim3(QKV_LD / 32, DDIM / 32), dim3(32, 8)>>>(w_attn, w1h, w1l, DDIM, QKV_LD);
    transpose_split<<<dim3(DDIM / 32, DDIM / 32),  dim3(32, 8)>>>(w_proj, w2h, w2l, DDIM, DDIM);

    // 1) QKV (fp16 hi/lo out, Q pre-scaled)
    hmma_gemm<1><<<dim3(QKV_LD / 128, MM / 128), 256, HMMA_SMEM>>>(
        xh, w1h, w1l, b_attn, nullptr, qkvhi, qkvlo, DDIM, QKV_LD);

    // 2) flash attention -> fp16 hi attention output
    flash_hmma<<<dim3(SS / 128, HH, BB), 256, FL_SMEM>>>(qkvhi, qkvlo, ah);

    // 3) proj (fp32 out)
    hmma_gemm<0><<<dim3(DDIM / 128, MM / 128), 256, HMMA_SMEM>>>(
        ah, w2h, w2l, b_proj, out, nullptr, nullptr, DDIM, DDIM);
}

// round 9
// speedup vs baseline: 7.6913x; 1.6609x over previous
#include <cuda_runtime.h>
#include <cuda_fp16.h>
#include <math_constants.h>
#include <cstdint>

#define BB 2
#define SS 2048
#define DDIM 1024
#define HH 16
#define HDIM 64
#define MM (BB*SS)          // 4096 rows
#define QKV_LD 3072         // 3*D

// ---------------------------------------------------------------------------
// Scratch (device globals: allowed; runtime allocs are not)
// ---------------------------------------------------------------------------
__device__ __half g_qkv[(size_t)MM * QKV_LD];    // QKV fp16 (Q pre-scaled)
__device__ __half g_xh[(size_t)MM * DDIM];       // x fp16
__device__ __half g_w1h[(size_t)QKV_LD * DDIM];  // w_attn^T fp16 [3072,1024]
__device__ __half g_w2h[(size_t)DDIM * DDIM];    // w_proj^T fp16 [1024,1024]
__device__ __half g_ah[(size_t)MM * DDIM];       // attention out fp16

// ---------------------------------------------------------------------------
// Portable PTX helpers
// ---------------------------------------------------------------------------
__device__ __forceinline__ uint32_t smem_u32(const void* p) {
    uint32_t a;
    asm("{ .reg .u64 t; cvta.to.shared.u64 t, %1; cvt.u32.u64 %0, t; }"
        : "=r"(a) : "l"(p));
    return a;
}

#define CP_ASYNC16(sa, gp) \
    asm volatile("cp.async.cg.shared.global [%0], [%1], 16;" :: "r"(sa), "l"(gp))
#define CP_COMMIT() asm volatile("cp.async.commit_group;" ::: "memory")
#define CP_WAIT1()  asm volatile("cp.async.wait_group 1;" ::: "memory")
#define CP_WAIT0()  asm volatile("cp.async.wait_group 0;" ::: "memory")

#define LDSM_X4(r0, r1, r2, r3, addr) \
    asm volatile("ldmatrix.sync.aligned.m8n8.x4.shared.b16 {%0,%1,%2,%3}, [%4];" \
        : "=r"(r0), "=r"(r1), "=r"(r2), "=r"(r3) : "r"(addr))

#define LDSM_X4_T(r0, r1, r2, r3, addr) \
    asm volatile("ldmatrix.sync.aligned.m8n8.x4.trans.shared.b16 {%0,%1,%2,%3}, [%4];" \
        : "=r"(r0), "=r"(r1), "=r"(r2), "=r"(r3) : "r"(addr))

#define MMA_F16(c, a0, a1, a2, a3, b0, b1) \
    asm volatile("mma.sync.aligned.m16n8k16.row.col.f32.f16.f16.f32 " \
        "{%0,%1,%2,%3}, {%4,%5,%6,%7}, {%8,%9}, {%0,%1,%2,%3};" \
        : "+f"((c)[0]), "+f"((c)[1]), "+f"((c)[2]), "+f"((c)[3]) \
        : "r"(a0), "r"(a1), "r"(a2), "r"(a3), "r"(b0), "r"(b1))

__device__ __forceinline__ uint32_t pack_hf2(float a, float b) {
    __half2 t = __floats2half2_rn(a, b);
    return *(uint32_t*)&t;
}

// Swizzles: rows of 64B (GEMM, ch in 0..3) and 128B (flash, ch in 0..7).
__device__ __forceinline__ uint32_t sw64(uint32_t r, uint32_t ch) {
    return r * 64 + ((ch ^ ((r + (r >> 2)) & 3)) << 4);
}
__device__ __forceinline__ uint32_t sw128(uint32_t r, uint32_t ch) {
    return r * 128 + ((ch ^ (r & 7)) << 4);
}

// ---------------------------------------------------------------------------
// Prep: fp32 -> fp16
// ---------------------------------------------------------------------------
__global__ void split_x(const float* __restrict__ s,
                        __half* __restrict__ hi, int n4)
{
    for (int i = blockIdx.x * blockDim.x + threadIdx.x; i < n4;
         i += gridDim.x * blockDim.x) {
        float4 v = ((const float4*)s)[i];
        ((uint32_t*)hi)[2 * i]     = pack_hf2(v.x, v.y);
        ((uint32_t*)hi)[2 * i + 1] = pack_hf2(v.z, v.w);
    }
}

// Prep: transpose W[K,N] -> WT[N,K] fp16.
__global__ void transpose_h(const float* __restrict__ W,
                            __half* __restrict__ hi, int K, int N)
{
    __shared__ float t[32][33];
    int n0 = blockIdx.x * 32, k0 = blockIdx.y * 32;
    int tx = threadIdx.x, ty = threadIdx.y;
#pragma unroll
    for (int i = 0; i < 32; i += 8)
        t[ty + i][tx] = W[(size_t)(k0 + ty + i) * N + n0 + tx];
    __syncthreads();
#pragma unroll
    for (int i = 0; i < 32; i += 8)
        hi[(size_t)(n0 + ty + i) * K + k0 + tx] = __float2half(t[tx][ty + i]);
}

// ---------------------------------------------------------------------------
// HMMA fp16 GEMM + bias (fp32 accumulate): C = Ah @ Bh^T + bias
// 2 smem arrays/stage, 3-stage cp.async, XOR swizzle, 1 barrier/K-tile.
// MODE 0: fp32 C.  MODE 1: fp16 C (Q cols scaled 0.125).
// ---------------------------------------------------------------------------
#define GARR 8192
#define GSTAGE (2 * GARR)            // 16384
#define HMMA_SMEM (3 * GSTAGE)       // 49152 -> 2 CTAs/SM

template<int MODE>
__global__ __launch_bounds__(256, 2)
void hmma_gemm(const __half* __restrict__ Ah, const __half* __restrict__ Bh,
               const float* __restrict__ bias, float* __restrict__ C,
               __half* __restrict__ Chi, int K, int N)
{
    extern __shared__ __align__(16) char smraw[];
    const uint32_t sb = smem_u32(smraw);

    const int tid = threadIdx.x;
    const int wid = tid >> 5, lane = tid & 31;
    const int m0 = blockIdx.y * 128, n0 = blockIdx.x * 128;
    const int warp_m = wid & 3;
    const int warp_n = wid >> 2;

    float c[2][8][4];
#pragma unroll
    for (int mi = 0; mi < 2; mi++)
#pragma unroll
        for (int nt = 0; nt < 8; nt++)
#pragma unroll
            for (int j = 0; j < 4; j++) c[mi][nt][j] = 0.f;

    const int nkt = K / 32;

    auto load_stage = [&](int kt, int slot) {
        const int k0 = kt * 32;
        const uint32_t sbase = sb + (uint32_t)slot * GSTAGE;
#pragma unroll
        for (int arr = 0; arr < 2; arr++) {
            const __half* P = (arr == 0) ? Ah : Bh;
            const int rowbase = (arr == 0) ? m0 : n0;
#pragma unroll
            for (int i = 0; i < 2; i++) {
                uint32_t idx = tid + i * 256;
                uint32_t r = idx >> 2, ch = idx & 3;
                const __half* gp = P + (size_t)(rowbase + r) * K + k0 + ch * 8;
                CP_ASYNC16(sbase + arr * GARR + sw64(r, ch), gp);
            }
        }
        CP_COMMIT();
    };

    load_stage(0, 0);
    load_stage(1, 1);

    const uint32_t lrow = lane & 15;
    const uint32_t lch  = lane >> 4;

    for (int kt = 0; kt < nkt; kt++) {
        if (kt + 2 < nkt) CP_WAIT1(); else CP_WAIT0();
        __syncthreads();

        const uint32_t sbase = sb + (uint32_t)(kt % 3) * GSTAGE;
        const uint32_t aRow = warp_m * 32;
        const uint32_t bRow = warp_n * 64;

#pragma unroll
        for (int ks = 0; ks < 2; ks++) {
            const uint32_t ch = ks * 2 + lch;
            uint32_t ah[2][4];
#pragma unroll
            for (int mi = 0; mi < 2; mi++) {
                uint32_t off = sw64(aRow + mi * 16 + lrow, ch);
                LDSM_X4(ah[mi][0], ah[mi][1], ah[mi][2], ah[mi][3],
                        sbase + off);
            }
#pragma unroll
            for (int np = 0; np < 4; np++) {
                uint32_t off = sw64(bRow + np * 16 + lrow, ch);
                uint32_t bh[4];
                LDSM_X4(bh[0], bh[1], bh[2], bh[3], sbase + GARR + off);
                const int n0t = np * 2, n1t = np * 2 + 1;
                MMA_F16(c[0][n0t], ah[0][0], ah[0][1], ah[0][2], ah[0][3], bh[0], bh[2]);
                MMA_F16(c[0][n1t], ah[0][0], ah[0][1], ah[0][2], ah[0][3], bh[1], bh[3]);
                MMA_F16(c[1][n0t], ah[1][0], ah[1][1], ah[1][2], ah[1][3], bh[0], bh[2]);
                MMA_F16(c[1][n1t], ah[1][0], ah[1][1], ah[1][2], ah[1][3], bh[1], bh[3]);
            }
        }

        if (kt + 2 < nkt) load_stage(kt + 2, (kt + 2) % 3);
    }

    // Epilogue
#pragma unroll
    for (int mi = 0; mi < 2; mi++) {
        int r0 = m0 + warp_m * 32 + mi * 16 + (lane >> 2);
        int r1 = r0 + 8;
#pragma unroll
        for (int nt = 0; nt < 8; nt++) {
            int col = n0 + warp_n * 64 + nt * 8 + (lane & 3) * 2;
            float b0 = bias[col], b1 = bias[col + 1];
            float v00 = c[mi][nt][0] + b0, v01 = c[mi][nt][1] + b1;
            float v10 = c[mi][nt][2] + b0, v11 = c[mi][nt][3] + b1;
            if (MODE == 0) {
                *(float2*)&C[(size_t)r0 * N + col] = make_float2(v00, v01);
                *(float2*)&C[(size_t)r1 * N + col] = make_float2(v10, v11);
            } else {
                if (col < DDIM) {   // Q columns: fold 1/sqrt(hd) (exact)
                    v00 *= 0.125f; v01 *= 0.125f; v10 *= 0.125f; v11 *= 0.125f;
                }
                *(uint32_t*)&Chi[(size_t)r0 * N + col] = pack_hf2(v00, v01);
                *(uint32_t*)&Chi[(size_t)r1 * N + col] = pack_hf2(v10, v11);
            }
        }
    }
}

// ---------------------------------------------------------------------------
// HMMA flash attention, causal, fp16 (fp32 accumulate).
// smem: Q 16KB + 2 KV stages x 16KB = 48KB -> 2 CTAs/SM.
// ---------------------------------------------------------------------------
#define FQARR (128 * 128)
#define FKVARR (64 * 128)
#define FKVSTAGE (2 * FKVARR)            // Kh, Vh = 16384
#define FL_SMEM (FQARR + 2 * FKVSTAGE)   // 49152 bytes

__global__ __launch_bounds__(256, 2)
void flash_hmma(const __half* __restrict__ qkv, __half* __restrict__ oh)
{
    extern __shared__ __align__(16) char smraw[];
    const uint32_t sb = smem_u32(smraw);
    const int tid = threadIdx.x, wid = tid >> 5, lane = tid & 31;
    const int qt = gridDim.x - 1 - blockIdx.x;
    const int h = blockIdx.y, b = blockIdx.z;
    const size_t qrowg = (size_t)(b * SS + qt * 128);
    const int hcol = h * HDIM;
    const uint32_t lrow = lane & 15, lch = lane >> 4;

    // Q -> smem
#pragma unroll
    for (int i = 0; i < 4; i++) {
        uint32_t idx = tid + i * 256;
        uint32_t r = idx >> 3, ch = idx & 7;
        size_t g = (qrowg + r) * QKV_LD + hcol + ch * 8;
        CP_ASYNC16(sb + sw128(r, ch), qkv + g);
    }
    CP_COMMIT();

    auto load_kv = [&](int kt, int s) {
        size_t krow = (size_t)(b * SS + kt * 64);
        uint32_t sbase = sb + FQARR + (uint32_t)s * FKVSTAGE;
#pragma unroll
        for (int i = 0; i < 2; i++) {
            uint32_t idx = tid + i * 256;
            uint32_t r = idx >> 3, ch = idx & 7;
            size_t g = (krow + r) * QKV_LD + DDIM + hcol + ch * 8;
            uint32_t so = sw128(r, ch);
            CP_ASYNC16(sbase + so,          qkv + g);          // K
            CP_ASYNC16(sbase + FKVARR + so, qkv + g + DDIM);   // V
        }
        CP_COMMIT();
    };

    load_kv(0, 0);

    float O[8][4];
#pragma unroll
    for (int ht = 0; ht < 8; ht++)
#pragma unroll
        for (int j = 0; j < 4; j++) O[ht][j] = 0.f;
    float m0 = -CUDART_INF_F, m1 = -CUDART_INF_F, l0 = 0.f, l1 = 0.f;

    const int qr0 = qt * 128 + wid * 16 + (lane >> 2);
    const int ktmax = 2 * qt + 1;

    for (int kt = 0; kt <= ktmax; kt++) {
        const int s = kt & 1;
        if (kt < ktmax) { load_kv(kt + 1, s ^ 1); CP_WAIT1(); }
        else            { CP_WAIT0(); }
        __syncthreads();
        const uint32_t kvb = sb + FQARR + (uint32_t)s * FKVSTAGE;

        // ---- scores: S = Q·K^T ----
        float c[8][4];
#pragma unroll
        for (int nt = 0; nt < 8; nt++)
#pragma unroll
            for (int j = 0; j < 4; j++) c[nt][j] = 0.f;

#pragma unroll
        for (int ks = 0; ks < 4; ks++) {
            const uint32_t ch = ks * 2 + lch;
            uint32_t qoff = sw128(wid * 16 + lrow, ch);
            uint32_t q0, q1, q2, q3;
            LDSM_X4(q0, q1, q2, q3, sb + qoff);
#pragma unroll
            for (int bpp = 0; bpp < 2; bpp++) {
                uint32_t offA = sw128((bpp * 2) * 16 + lrow, ch);
                uint32_t offB = sw128((bpp * 2 + 1) * 16 + lrow, ch);
                uint32_t kA[4], kB[4];
                LDSM_X4(kA[0], kA[1], kA[2], kA[3], kvb + offA);
                LDSM_X4(kB[0], kB[1], kB[2], kB[3], kvb + offB);
                MMA_F16(c[bpp * 4 + 0], q0, q1, q2, q3, kA[0], kA[2]);
                MMA_F16(c[bpp * 4 + 1], q0, q1, q2, q3, kA[1], kA[3]);
                MMA_F16(c[bpp * 4 + 2], q0, q1, q2, q3, kB[0], kB[2]);
                MMA_F16(c[bpp * 4 + 3], q0, q1, q2, q3, kB[1], kB[3]);
            }
        }

        // ---- causal mask ----
        if (kt * 64 + 63 > qt * 128 + wid * 16) {
#pragma unroll
            for (int nt = 0; nt < 8; nt++) {
                int kc = kt * 64 + nt * 8 + (lane & 3) * 2;
                if (kc     > qr0)     c[nt][0] = -CUDART_INF_F;
                if (kc + 1 > qr0)     c[nt][1] = -CUDART_INF_F;
                if (kc     > qr0 + 8) c[nt][2] = -CUDART_INF_F;
                if (kc + 1 > qr0 + 8) c[nt][3] = -CUDART_INF_F;
            }
        }

        // ---- online softmax ----
        float mt0 = -CUDART_INF_F, mt1 = -CUDART_INF_F;
#pragma unroll
        for (int nt = 0; nt < 8; nt++) {
            mt0 = fmaxf(mt0, fmaxf(c[nt][0], c[nt][1]));
            mt1 = fmaxf(mt1, fmaxf(c[nt][2], c[nt][3]));
        }
        mt0 = fmaxf(mt0, __shfl_xor_sync(0xffffffffu, mt0, 1));
        mt0 = fmaxf(mt0, __shfl_xor_sync(0xffffffffu, mt0, 2));
        mt1 = fmaxf(mt1, __shfl_xor_sync(0xffffffffu, mt1, 1));
        mt1 = fmaxf(mt1, __shfl_xor_sync(0xffffffffu, mt1, 2));

        float mn0 = fmaxf(m0, mt0), mn1 = fmaxf(m1, mt1);
        float f0 = __expf(m0 - mn0), f1 = __expf(m1 - mn1);
        float s0 = 0.f, s1 = 0.f;
        uint32_t pa0[8], pa1[8];
#pragma unroll
        for (int nt = 0; nt < 8; nt++) {
            float p0 = __expf(c[nt][0] - mn0), p1 = __expf(c[nt][1] - mn0);
            float p2 = __expf(c[nt][2] - mn1), p3 = __expf(c[nt][3] - mn1);
            s0 += p0 + p1; s1 += p2 + p3;
            pa0[nt] = pack_hf2(p0, p1);
            pa1[nt] = pack_hf2(p2, p3);
        }
        s0 += __shfl_xor_sync(0xffffffffu, s0, 1);
        s0 += __shfl_xor_sync(0xffffffffu, s0, 2);
        s1 += __shfl_xor_sync(0xffffffffu, s1, 1);
        s1 += __shfl_xor_sync(0xffffffffu, s1, 2);
        l0 = l0 * f0 + s0;  m0 = mn0;
        l1 = l1 * f1 + s1;  m1 = mn1;
#pragma unroll
        for (int ht = 0; ht < 8; ht++) {
            O[ht][0] *= f0; O[ht][1] *= f0;
            O[ht][2] *= f1; O[ht][3] *= f1;
        }

        // ---- PV: O += P·V ----
#pragma unroll
        for (int ksi = 0; ksi < 4; ksi++) {
            uint32_t a0 = pa0[2 * ksi],     a1 = pa1[2 * ksi];
            uint32_t a2 = pa0[2 * ksi + 1], a3 = pa1[2 * ksi + 1];
#pragma unroll
            for (int bpp = 0; bpp < 2; bpp++) {
                uint32_t offA = sw128(ksi * 16 + lrow, (bpp * 2) * 2 + lch);
                uint32_t offB = sw128(ksi * 16 + lrow, (bpp * 2 + 1) * 2 + lch);
                uint32_t vA[4], vB[4];
                LDSM_X4_T(vA[0], vA[1], vA[2], vA[3], kvb + FKVARR + offA);
                LDSM_X4_T(vB[0], vB[1], vB[2], vB[3], kvb + FKVARR + offB);
                MMA_F16(O[bpp * 4 + 0], a0, a1, a2, a3, vA[0], vA[1]);
                MMA_F16(O[bpp * 4 + 1], a0, a1, a2, a3, vA[2], vA[3]);
                MMA_F16(O[bpp * 4 + 2], a0, a1, a2, a3, vB[0], vB[1]);
                MMA_F16(O[bpp * 4 + 3], a0, a1, a2, a3, vB[2], vB[3]);
            }
        }
        __syncthreads();
    }

    // ---- epilogue ----
    float i0 = 1.f / l0, i1 = 1.f / l1;
    size_t r0g = qrowg + wid * 16 + (lane >> 2);
    size_t r1g = r0g + 8;
    int cb = hcol + (lane & 3) * 2;
#pragma unroll
    for (int ht = 0; ht < 8; ht++) {
        int col = cb + ht * 8;
        *(uint32_t*)&oh[r0g * DDIM + col] = pack_hf2(O[ht][0] * i0, O[ht][1] * i0);
        *(uint32_t*)&oh[r1g * DDIM + col] = pack_hf2(O[ht][2] * i1, O[ht][3] * i1);
    }
}

// ---------------------------------------------------------------------------
extern "C" void kernel_launch(void* const* d_in, const int* in_sizes, int n_in,
                              void* d_out, int out_size)
{
    const float* x      = (const float*)d_in[0];
    const float* w_attn = (const float*)d_in[1];
    const float* b_attn = (const float*)d_in[2];
    const float* w_proj = (const float*)d_in[3];
    const float* b_proj = (const float*)d_in[4];
    float* out = (float*)d_out;

    __half *qkv, *xh, *w1h, *w2h, *ah;
    cudaGetSymbolAddress((void**)&qkv, g_qkv);
    cudaGetSymbolAddress((void**)&xh,  g_xh);
    cudaGetSymbolAddress((void**)&w1h, g_w1h);
    cudaGetSymbolAddress((void**)&w2h, g_w2h);
    cudaGetSymbolAddress((void**)&ah,  g_ah);

    cudaFuncSetAttribute(hmma_gemm<0>,
                         cudaFuncAttributeMaxDynamicSharedMemorySize, HMMA_SMEM);
    cudaFuncSetAttribute(hmma_gemm<1>,
                         cudaFuncAttributeMaxDynamicSharedMemorySize, HMMA_SMEM);
    cudaFuncSetAttribute(flash_hmma,
                         cudaFuncAttributeMaxDynamicSharedMemorySize, FL_SMEM);

    // Prep
    split_x<<<1024, 256>>>(x, xh, MM * DDIM / 4);
    transpose_h<<<dim3(QKV_LD / 32, DDIM / 32), dim3(32, 8)>>>(w_attn, w1h, DDIM, QKV_LD);
    transpose_h<<<dim3(DDIM / 32, DDIM / 32),  dim3(32, 8)>>>(w_proj, w2h, DDIM, DDIM);

    // 1) QKV (fp16 out, Q pre-scaled)
    hmma_gemm<1><<<dim3(QKV_LD / 128, MM / 128), 256, HMMA_SMEM>>>(
        xh, w1h, b_attn, nullptr, qkv, DDIM, QKV_LD);

    // 2) flash attention -> fp16 attention output
    flash_hmma<<<dim3(SS / 128, HH, BB), 256, FL_SMEM>>>(qkv, ah);

    // 3) proj (fp32 out)
    hmma_gemm<0><<<dim3(DDIM / 128, MM / 128), 256, HMMA_SMEM>>>(
        ah, w2h, b_proj, out, nullptr, DDIM, DDIM);
}

// round 10
// speedup vs baseline: 7.8200x; 1.0167x over previous
#include <cuda_runtime.h>
#include <cuda_fp16.h>
#include <math_constants.h>
#include <cstdint>

#define BB 2
#define SS 2048
#define DDIM 1024
#define HH 16
#define HDIM 64
#define MM (BB*SS)          // 4096 rows
#define QKV_LD 3072         // 3*D

// ---------------------------------------------------------------------------
// Scratch (device globals: allowed; runtime allocs are not)
// ---------------------------------------------------------------------------
__device__ __half g_qkv[(size_t)MM * QKV_LD];    // QKV fp16 (Q pre-scaled)
__device__ __half g_xh[(size_t)MM * DDIM];       // x fp16
__device__ __half g_w1h[(size_t)QKV_LD * DDIM];  // w_attn^T fp16 [3072,1024]
__device__ __half g_w2h[(size_t)DDIM * DDIM];    // w_proj^T fp16 [1024,1024]
__device__ __half g_ah[(size_t)MM * DDIM];       // attention out fp16

// ---------------------------------------------------------------------------
// Portable PTX helpers
// ---------------------------------------------------------------------------
__device__ __forceinline__ uint32_t smem_u32(const void* p) {
    uint32_t a;
    asm("{ .reg .u64 t; cvta.to.shared.u64 t, %1; cvt.u32.u64 %0, t; }"
        : "=r"(a) : "l"(p));
    return a;
}

#define CP_ASYNC16(sa, gp) \
    asm volatile("cp.async.cg.shared.global [%0], [%1], 16;" :: "r"(sa), "l"(gp))
#define CP_COMMIT() asm volatile("cp.async.commit_group;" ::: "memory")
#define CP_WAIT1()  asm volatile("cp.async.wait_group 1;" ::: "memory")
#define CP_WAIT0()  asm volatile("cp.async.wait_group 0;" ::: "memory")

#define LDSM_X4(r0, r1, r2, r3, addr) \
    asm volatile("ldmatrix.sync.aligned.m8n8.x4.shared.b16 {%0,%1,%2,%3}, [%4];" \
        : "=r"(r0), "=r"(r1), "=r"(r2), "=r"(r3) : "r"(addr))

#define LDSM_X4_T(r0, r1, r2, r3, addr) \
    asm volatile("ldmatrix.sync.aligned.m8n8.x4.trans.shared.b16 {%0,%1,%2,%3}, [%4];" \
        : "=r"(r0), "=r"(r1), "=r"(r2), "=r"(r3) : "r"(addr))

#define MMA_F16(c, a0, a1, a2, a3, b0, b1) \
    asm volatile("mma.sync.aligned.m16n8k16.row.col.f32.f16.f16.f32 " \
        "{%0,%1,%2,%3}, {%4,%5,%6,%7}, {%8,%9}, {%0,%1,%2,%3};" \
        : "+f"((c)[0]), "+f"((c)[1]), "+f"((c)[2]), "+f"((c)[3]) \
        : "r"(a0), "r"(a1), "r"(a2), "r"(a3), "r"(b0), "r"(b1))

__device__ __forceinline__ uint32_t pack_hf2(float a, float b) {
    __half2 t = __floats2half2_rn(a, b);
    return *(uint32_t*)&t;
}

// XOR swizzle for 128B rows (ch in 0..7): conflict-free per 8-lane phase.
__device__ __forceinline__ uint32_t sw128(uint32_t r, uint32_t ch) {
    return r * 128 + ((ch ^ (r & 7)) << 4);
}

// ---------------------------------------------------------------------------
// Prep: fp32 -> fp16
// ---------------------------------------------------------------------------
__global__ void split_x(const float* __restrict__ s,
                        __half* __restrict__ hi, int n4)
{
    for (int i = blockIdx.x * blockDim.x + threadIdx.x; i < n4;
         i += gridDim.x * blockDim.x) {
        float4 v = ((const float4*)s)[i];
        ((uint32_t*)hi)[2 * i]     = pack_hf2(v.x, v.y);
        ((uint32_t*)hi)[2 * i + 1] = pack_hf2(v.z, v.w);
    }
}

// Prep: transpose W[K,N] -> WT[N,K] fp16.
__global__ void transpose_h(const float* __restrict__ W,
                            __half* __restrict__ hi, int K, int N)
{
    __shared__ float t[32][33];
    int n0 = blockIdx.x * 32, k0 = blockIdx.y * 32;
    int tx = threadIdx.x, ty = threadIdx.y;
#pragma unroll
    for (int i = 0; i < 32; i += 8)
        t[ty + i][tx] = W[(size_t)(k0 + ty + i) * N + n0 + tx];
    __syncthreads();
#pragma unroll
    for (int i = 0; i < 32; i += 8)
        hi[(size_t)(n0 + ty + i) * K + k0 + tx] = __float2half(t[tx][ty + i]);
}

// ---------------------------------------------------------------------------
// HMMA fp16 GEMM + bias (fp32 accumulate): C = Ah @ Bh^T + bias
// K-tile 64 (128B rows), 3-stage cp.async, 1 barrier / 64-K, sw128 swizzle.
// MODE 0: fp32 C.  MODE 1: fp16 C (Q cols scaled 0.125).
// ---------------------------------------------------------------------------
#define GARR 16384                   // bytes per array (128 rows x 128B)
#define GSTAGE (2 * GARR)            // 32768
#define HMMA_SMEM (3 * GSTAGE)       // 98304 -> 2 CTAs/SM (192KB)

template<int MODE>
__global__ __launch_bounds__(256, 2)
void hmma_gemm(const __half* __restrict__ Ah, const __half* __restrict__ Bh,
               const float* __restrict__ bias, float* __restrict__ C,
               __half* __restrict__ Chi, int K, int N)
{
    extern __shared__ __align__(16) char smraw[];
    const uint32_t sb = smem_u32(smraw);

    const int tid = threadIdx.x;
    const int wid = tid >> 5, lane = tid & 31;
    const int m0 = blockIdx.y * 128, n0 = blockIdx.x * 128;
    const int warp_m = wid & 3;
    const int warp_n = wid >> 2;

    float c[2][8][4];
#pragma unroll
    for (int mi = 0; mi < 2; mi++)
#pragma unroll
        for (int nt = 0; nt < 8; nt++)
#pragma unroll
            for (int j = 0; j < 4; j++) c[mi][nt][j] = 0.f;

    const int nkt = K / 64;

    auto load_stage = [&](int kt, int slot) {
        const int k0 = kt * 64;
        const uint32_t sbase = sb + (uint32_t)slot * GSTAGE;
#pragma unroll
        for (int arr = 0; arr < 2; arr++) {
            const __half* P = (arr == 0) ? Ah : Bh;
            const int rowbase = (arr == 0) ? m0 : n0;
#pragma unroll
            for (int i = 0; i < 4; i++) {
                uint32_t idx = tid + i * 256;          // 0..1023
                uint32_t r = idx >> 3, ch = idx & 7;   // 128 rows x 8 chunks
                const __half* gp = P + (size_t)(rowbase + r) * K + k0 + ch * 8;
                CP_ASYNC16(sbase + arr * GARR + sw128(r, ch), gp);
            }
        }
        CP_COMMIT();
    };

    load_stage(0, 0);
    load_stage(1, 1);

    const uint32_t lrow = lane & 15;
    const uint32_t lch  = lane >> 4;

    for (int kt = 0; kt < nkt; kt++) {
        if (kt + 2 < nkt) CP_WAIT1(); else CP_WAIT0();
        __syncthreads();

        const uint32_t sbase = sb + (uint32_t)(kt % 3) * GSTAGE;
        const uint32_t aRow = warp_m * 32;
        const uint32_t bRow = warp_n * 64;

#pragma unroll
        for (int ks = 0; ks < 4; ks++) {       // 4 k16 steps per K-tile
            const uint32_t ch = ks * 2 + lch;
            uint32_t ah[2][4];
#pragma unroll
            for (int mi = 0; mi < 2; mi++) {
                uint32_t off = sw128(aRow + mi * 16 + lrow, ch);
                LDSM_X4(ah[mi][0], ah[mi][1], ah[mi][2], ah[mi][3],
                        sbase + off);
            }
#pragma unroll
            for (int np = 0; np < 4; np++) {
                uint32_t off = sw128(bRow + np * 16 + lrow, ch);
                uint32_t bh[4];
                LDSM_X4(bh[0], bh[1], bh[2], bh[3], sbase + GARR + off);
                const int n0t = np * 2, n1t = np * 2 + 1;
                MMA_F16(c[0][n0t], ah[0][0], ah[0][1], ah[0][2], ah[0][3], bh[0], bh[2]);
                MMA_F16(c[0][n1t], ah[0][0], ah[0][1], ah[0][2], ah[0][3], bh[1], bh[3]);
                MMA_F16(c[1][n0t], ah[1][0], ah[1][1], ah[1][2], ah[1][3], bh[0], bh[2]);
                MMA_F16(c[1][n1t], ah[1][0], ah[1][1], ah[1][2], ah[1][3], bh[1], bh[3]);
            }
        }

        if (kt + 2 < nkt) load_stage(kt + 2, (kt + 2) % 3);
    }

    // Epilogue
#pragma unroll
    for (int mi = 0; mi < 2; mi++) {
        int r0 = m0 + warp_m * 32 + mi * 16 + (lane >> 2);
        int r1 = r0 + 8;
#pragma unroll
        for (int nt = 0; nt < 8; nt++) {
            int col = n0 + warp_n * 64 + nt * 8 + (lane & 3) * 2;
            float b0 = bias[col], b1 = bias[col + 1];
            float v00 = c[mi][nt][0] + b0, v01 = c[mi][nt][1] + b1;
            float v10 = c[mi][nt][2] + b0, v11 = c[mi][nt][3] + b1;
            if (MODE == 0) {
                *(float2*)&C[(size_t)r0 * N + col] = make_float2(v00, v01);
                *(float2*)&C[(size_t)r1 * N + col] = make_float2(v10, v11);
            } else {
                if (col < DDIM) {   // Q columns: fold 1/sqrt(hd) (exact)
                    v00 *= 0.125f; v01 *= 0.125f; v10 *= 0.125f; v11 *= 0.125f;
                }
                *(uint32_t*)&Chi[(size_t)r0 * N + col] = pack_hf2(v00, v01);
                *(uint32_t*)&Chi[(size_t)r1 * N + col] = pack_hf2(v10, v11);
            }
        }
    }
}

// ---------------------------------------------------------------------------
// HMMA flash attention, causal, fp16 (fp32 accumulate).
// 3-stage KV pipeline (prefetch distance 2): Q 16KB + 3 x 16KB = 64KB
// -> 2 CTAs/SM.
// ---------------------------------------------------------------------------
#define FQARR (128 * 128)
#define FKVARR (64 * 128)
#define FKVSTAGE (2 * FKVARR)            // Kh, Vh = 16384
#define FL_SMEM (FQARR + 3 * FKVSTAGE)   // 65536 bytes

__global__ __launch_bounds__(256, 2)
void flash_hmma(const __half* __restrict__ qkv, __half* __restrict__ oh)
{
    extern __shared__ __align__(16) char smraw[];
    const uint32_t sb = smem_u32(smraw);
    const int tid = threadIdx.x, wid = tid >> 5, lane = tid & 31;
    const int qt = gridDim.x - 1 - blockIdx.x;
    const int h = blockIdx.y, b = blockIdx.z;
    const size_t qrowg = (size_t)(b * SS + qt * 128);
    const int hcol = h * HDIM;
    const uint32_t lrow = lane & 15, lch = lane >> 4;

    // Q -> smem (group 0)
#pragma unroll
    for (int i = 0; i < 4; i++) {
        uint32_t idx = tid + i * 256;
        uint32_t r = idx >> 3, ch = idx & 7;
        size_t g = (qrowg + r) * QKV_LD + hcol + ch * 8;
        CP_ASYNC16(sb + sw128(r, ch), qkv + g);
    }
    CP_COMMIT();

    auto load_kv = [&](int kt, int s) {
        size_t krow = (size_t)(b * SS + kt * 64);
        uint32_t sbase = sb + FQARR + (uint32_t)s * FKVSTAGE;
#pragma unroll
        for (int i = 0; i < 2; i++) {
            uint32_t idx = tid + i * 256;
            uint32_t r = idx >> 3, ch = idx & 7;
            size_t g = (krow + r) * QKV_LD + DDIM + hcol + ch * 8;
            uint32_t so = sw128(r, ch);
            CP_ASYNC16(sbase + so,          qkv + g);          // K
            CP_ASYNC16(sbase + FKVARR + so, qkv + g + DDIM);   // V
        }
        CP_COMMIT();
    };

    const int ktmax = 2 * qt + 1;      // >= 1 always
    load_kv(0, 0);
    load_kv(1, 1);

    float O[8][4];
#pragma unroll
    for (int ht = 0; ht < 8; ht++)
#pragma unroll
        for (int j = 0; j < 4; j++) O[ht][j] = 0.f;
    float m0 = -CUDART_INF_F, m1 = -CUDART_INF_F, l0 = 0.f, l1 = 0.f;

    const int qr0 = qt * 128 + wid * 16 + (lane >> 2);

    for (int kt = 0; kt <= ktmax; kt++) {
        if (kt + 2 <= ktmax) CP_WAIT1(); else CP_WAIT0();
        __syncthreads();
        const uint32_t kvb = sb + FQARR + (uint32_t)(kt % 3) * FKVSTAGE;

        // ---- scores: S = Q·K^T ----
        float c[8][4];
#pragma unroll
        for (int nt = 0; nt < 8; nt++)
#pragma unroll
            for (int j = 0; j < 4; j++) c[nt][j] = 0.f;

#pragma unroll
        for (int ks = 0; ks < 4; ks++) {
            const uint32_t ch = ks * 2 + lch;
            uint32_t qoff = sw128(wid * 16 + lrow, ch);
            uint32_t q0, q1, q2, q3;
            LDSM_X4(q0, q1, q2, q3, sb + qoff);
#pragma unroll
            for (int bpp = 0; bpp < 2; bpp++) {
                uint32_t offA = sw128((bpp * 2) * 16 + lrow, ch);
                uint32_t offB = sw128((bpp * 2 + 1) * 16 + lrow, ch);
                uint32_t kA[4], kB[4];
                LDSM_X4(kA[0], kA[1], kA[2], kA[3], kvb + offA);
                LDSM_X4(kB[0], kB[1], kB[2], kB[3], kvb + offB);
                MMA_F16(c[bpp * 4 + 0], q0, q1, q2, q3, kA[0], kA[2]);
                MMA_F16(c[bpp * 4 + 1], q0, q1, q2, q3, kA[1], kA[3]);
                MMA_F16(c[bpp * 4 + 2], q0, q1, q2, q3, kB[0], kB[2]);
                MMA_F16(c[bpp * 4 + 3], q0, q1, q2, q3, kB[1], kB[3]);
            }
        }

        // ---- causal mask ----
        if (kt * 64 + 63 > qt * 128 + wid * 16) {
#pragma unroll
            for (int nt = 0; nt < 8; nt++) {
                int kc = kt * 64 + nt * 8 + (lane & 3) * 2;
                if (kc     > qr0)     c[nt][0] = -CUDART_INF_F;
                if (kc + 1 > qr0)     c[nt][1] = -CUDART_INF_F;
                if (kc     > qr0 + 8) c[nt][2] = -CUDART_INF_F;
                if (kc + 1 > qr0 + 8) c[nt][3] = -CUDART_INF_F;
            }
        }

        // ---- online softmax ----
        float mt0 = -CUDART_INF_F, mt1 = -CUDART_INF_F;
#pragma unroll
        for (int nt = 0; nt < 8; nt++) {
            mt0 = fmaxf(mt0, fmaxf(c[nt][0], c[nt][1]));
            mt1 = fmaxf(mt1, fmaxf(c[nt][2], c[nt][3]));
        }
        mt0 = fmaxf(mt0, __shfl_xor_sync(0xffffffffu, mt0, 1));
        mt0 = fmaxf(mt0, __shfl_xor_sync(0xffffffffu, mt0, 2));
        mt1 = fmaxf(mt1, __shfl_xor_sync(0xffffffffu, mt1, 1));
        mt1 = fmaxf(mt1, __shfl_xor_sync(0xffffffffu, mt1, 2));

        float mn0 = fmaxf(m0, mt0), mn1 = fmaxf(m1, mt1);
        float f0 = __expf(m0 - mn0), f1 = __expf(m1 - mn1);
        float s0 = 0.f, s1 = 0.f;
        uint32_t pa0[8], pa1[8];
#pragma unroll
        for (int nt = 0; nt < 8; nt++) {
            float p0 = __expf(c[nt][0] - mn0), p1 = __expf(c[nt][1] - mn0);
            float p2 = __expf(c[nt][2] - mn1), p3 = __expf(c[nt][3] - mn1);
            s0 += p0 + p1; s1 += p2 + p3;
            pa0[nt] = pack_hf2(p0, p1);
            pa1[nt] = pack_hf2(p2, p3);
        }
        s0 += __shfl_xor_sync(0xffffffffu, s0, 1);
        s0 += __shfl_xor_sync(0xffffffffu, s0, 2);
        s1 += __shfl_xor_sync(0xffffffffu, s1, 1);
        s1 += __shfl_xor_sync(0xffffffffu, s1, 2);
        l0 = l0 * f0 + s0;  m0 = mn0;
        l1 = l1 * f1 + s1;  m1 = mn1;
#pragma unroll
        for (int ht = 0; ht < 8; ht++) {
            O[ht][0] *= f0; O[ht][1] *= f0;
            O[ht][2] *= f1; O[ht][3] *= f1;
        }

        // ---- PV: O += P·V ----
#pragma unroll
        for (int ksi = 0; ksi < 4; ksi++) {
            uint32_t a0 = pa0[2 * ksi],     a1 = pa1[2 * ksi];
            uint32_t a2 = pa0[2 * ksi + 1], a3 = pa1[2 * ksi + 1];
#pragma unroll
            for (int bpp = 0; bpp < 2; bpp++) {
                uint32_t offA = sw128(ksi * 16 + lrow, (bpp * 2) * 2 + lch);
                uint32_t offB = sw128(ksi * 16 + lrow, (bpp * 2 + 1) * 2 + lch);
                uint32_t vA[4], vB[4];
                LDSM_X4_T(vA[0], vA[1], vA[2], vA[3], kvb + FKVARR + offA);
                LDSM_X4_T(vB[0], vB[1], vB[2], vB[3], kvb + FKVARR + offB);
                MMA_F16(O[bpp * 4 + 0], a0, a1, a2, a3, vA[0], vA[1]);
                MMA_F16(O[bpp * 4 + 1], a0, a1, a2, a3, vA[2], vA[3]);
                MMA_F16(O[bpp * 4 + 2], a0, a1, a2, a3, vB[0], vB[1]);
                MMA_F16(O[bpp * 4 + 3], a0, a1, a2, a3, vB[2], vB[3]);
            }
        }

        if (kt + 2 <= ktmax) load_kv(kt + 2, (kt + 2) % 3);
    }

    // ---- epilogue ----
    float i0 = 1.f / l0, i1 = 1.f / l1;
    size_t r0g = qrowg + wid * 16 + (lane >> 2);
    size_t r1g = r0g + 8;
    int cb = hcol + (lane & 3) * 2;
#pragma unroll
    for (int ht = 0; ht < 8; ht++) {
        int col = cb + ht * 8;
        *(uint32_t*)&oh[r0g * DDIM + col] = pack_hf2(O[ht][0] * i0, O[ht][1] * i0);
        *(uint32_t*)&oh[r1g * DDIM + col] = pack_hf2(O[ht][2] * i1, O[ht][3] * i1);
    }
}

// ---------------------------------------------------------------------------
extern "C" void kernel_launch(void* const* d_in, const int* in_sizes, int n_in,
                              void* d_out, int out_size)
{
    const float* x      = (const float*)d_in[0];
    const float* w_attn = (const float*)d_in[1];
    const float* b_attn = (const float*)d_in[2];
    const float* w_proj = (const float*)d_in[3];
    const float* b_proj = (const float*)d_in[4];
    float* out = (float*)d_out;

    __half *qkv, *xh, *w1h, *w2h, *ah;
    cudaGetSymbolAddress((void**)&qkv, g_qkv);
    cudaGetSymbolAddress((void**)&xh,  g_xh);
    cudaGetSymbolAddress((void**)&w1h, g_w1h);
    cudaGetSymbolAddress((void**)&w2h, g_w2h);
    cudaGetSymbolAddress((void**)&ah,  g_ah);

    cudaFuncSetAttribute(hmma_gemm<0>,
                         cudaFuncAttributeMaxDynamicSharedMemorySize, HMMA_SMEM);
    cudaFuncSetAttribute(hmma_gemm<1>,
                         cudaFuncAttributeMaxDynamicSharedMemorySize, HMMA_SMEM);
    cudaFuncSetAttribute(flash_hmma,
                         cudaFuncAttributeMaxDynamicSharedMemorySize, FL_SMEM);

    // Prep
    split_x<<<1024, 256>>>(x, xh, MM * DDIM / 4);
    transpose_h<<<dim3(QKV_LD / 32, DDIM / 32), dim3(32, 8)>>>(w_attn, w1h, DDIM, QKV_LD);
    transpose_h<<<dim3(DDIM / 32, DDIM / 32),  dim3(32, 8)>>>(w_proj, w2h, DDIM, DDIM);

    // 1) QKV (fp16 out, Q pre-scaled)
    hmma_gemm<1><<<dim3(QKV_LD / 128, MM / 128), 256, HMMA_SMEM>>>(
        xh, w1h, b_attn, nullptr, qkv, DDIM, QKV_LD);

    // 2) flash attention -> fp16 attention output
    flash_hmma<<<dim3(SS / 128, HH, BB), 256, FL_SMEM>>>(qkv, ah);

    // 3) proj (fp32 out)
    hmma_gemm<0><<<dim3(DDIM / 128, MM / 128), 256, HMMA_SMEM>>>(
        ah, w2h, b_proj, out, nullptr, DDIM, DDIM);
}